// round 4
// baseline (speedup 1.0000x reference)
#include <cuda_runtime.h>
#include <cuda_bf16.h>
#include <cstdint>
#include <cmath>

#define LPN 4096
#define LHN 4096
#define DN  300
#define HN  512

// ---------------- scratch (static device globals) ---------------------------
__device__ float g_pemb[LPN * DN];
__device__ float g_hemb[LHN * DN];
__device__ float g_t   [LPN * HN];
__device__ float g_fp  [LPN * HN];
__device__ float g_fh  [LHN * HN];
__device__ float g_x   [LPN * 2 * DN];
__device__ float g_u   [LPN * HN];
__device__ float g_eik [LPN];
__device__ float g_ekj [LHN];
__device__ float g_part[32 * 4096];
__device__ float g_split[2 * LPN * DN];

// ---------------- PTX helpers ------------------------------------------------
__device__ __forceinline__ uint32_t smem_u32(const void* p) {
    uint32_t a;
    asm("{ .reg .u64 t; cvta.to.shared.u64 t, %1; cvt.u32.u64 %0, t; }" : "=r"(a) : "l"(p));
    return a;
}
__device__ __forceinline__ void ldsm4(uint32_t& r0, uint32_t& r1, uint32_t& r2,
                                      uint32_t& r3, uint32_t addr) {
    asm volatile("ldmatrix.sync.aligned.m8n8.x4.shared.b16 {%0,%1,%2,%3}, [%4];"
                 : "=r"(r0), "=r"(r1), "=r"(r2), "=r"(r3) : "r"(addr));
}
__device__ __forceinline__ void mma16816(float* c, const uint32_t* a,
                                         const uint32_t b0, const uint32_t b1) {
    asm volatile(
        "mma.sync.aligned.m16n8k16.row.col.f32.bf16.bf16.f32 "
        "{%0,%1,%2,%3}, {%4,%5,%6,%7}, {%8,%9}, {%0,%1,%2,%3};"
        : "+f"(c[0]), "+f"(c[1]), "+f"(c[2]), "+f"(c[3])
        : "r"(a[0]), "r"(a[1]), "r"(a[2]), "r"(a[3]), "r"(b0), "r"(b1));
}
__device__ __forceinline__ void cvt_split(float x, __nv_bfloat16& hi, __nv_bfloat16& lo) {
    hi = __float2bfloat16(x);
    lo = __float2bfloat16(x - __bfloat162float(hi));
}

// ---------------- mma.sync bf16x3 SGEMM, 128x128 block, k-chunk 32 ----------
// C[m,n] = epi( sum_k A(m,k) * B(n,k) )
// AKC: A row-major [M,K] k-contiguous (stride sA per m); else A[k*sA + m] (m-contig).
// BKC: B row-major [N,K] k-contiguous (stride sB per n); else B[k*sB + n] (n-contig).
// M must be a multiple of 128. blockIdx.z = split-K slice.
template <bool AKC, bool BKC>
__global__ __launch_bounds__(256, 2)
void mgemm(const float* __restrict__ A, long sA,
           const float* __restrict__ B, long sB,
           const float* __restrict__ bias, const float* __restrict__ rowdiv,
           float* __restrict__ C, long ldc, long sliceStride,
           int M, int N, int K, int kPerSlice, int relu) {
    __shared__ __align__(16) __nv_bfloat16 Ah[128][40];
    __shared__ __align__(16) __nv_bfloat16 Al[128][40];
    __shared__ __align__(16) __nv_bfloat16 Bh[128][40];
    __shared__ __align__(16) __nv_bfloat16 Bl[128][40];

    const int tid = threadIdx.x, lane = tid & 31, wid = tid >> 5;
    const int wm = wid >> 1, wn = wid & 1;          // 4 x 2 warp grid
    const int m0 = blockIdx.y * 128, n0 = blockIdx.x * 128;
    const int kbeg = blockIdx.z * kPerSlice;
    const int kend = min(K, kbeg + kPerSlice);
    C += (long)blockIdx.z * sliceStride;

    float acc[2][8][4];
    #pragma unroll
    for (int i = 0; i < 2; i++)
        #pragma unroll
        for (int j = 0; j < 8; j++)
            #pragma unroll
            for (int e = 0; e < 4; e++) acc[i][j][e] = 0.f;

    const uint32_t aAh = smem_u32(&Ah[0][0]), aAl = smem_u32(&Al[0][0]);
    const uint32_t aBh = smem_u32(&Bh[0][0]), aBl = smem_u32(&Bl[0][0]);
    // ldmatrix lane -> (row-in-frag16, 16B col) mapping
    const int lrow = (((lane >> 3) & 1) << 3) + (lane & 7);
    const int lcol = (lane >> 4) << 4;   // bytes

    for (int k0 = kbeg; k0 < kend; k0 += 32) {
        __syncthreads();
        // ---- load + split A tile: 128(m) x 32(k) ----
        if (AKC) {
            #pragma unroll
            for (int i = 0; i < 4; i++) {
                int idx = tid + i * 256;
                int r = idx >> 3, kq = (idx & 7) << 2;
                int k = k0 + kq;
                const float* src = A + (long)(m0 + r) * sA + k;
                float4 v = make_float4(0.f, 0.f, 0.f, 0.f);
                if (k + 3 < kend) v = *(const float4*)src;
                else {
                    if (k + 0 < kend) v.x = src[0];
                    if (k + 1 < kend) v.y = src[1];
                    if (k + 2 < kend) v.z = src[2];
                    if (k + 3 < kend) v.w = src[3];
                }
                cvt_split(v.x, Ah[r][kq + 0], Al[r][kq + 0]);
                cvt_split(v.y, Ah[r][kq + 1], Al[r][kq + 1]);
                cvt_split(v.z, Ah[r][kq + 2], Al[r][kq + 2]);
                cvt_split(v.w, Ah[r][kq + 3], Al[r][kq + 3]);
            }
        } else {
            #pragma unroll
            for (int i = 0; i < 4; i++) {
                int idx = tid + i * 256;
                int kq = idx >> 5, mq = (idx & 31) << 2;
                int k = k0 + kq;
                float4 v = make_float4(0.f, 0.f, 0.f, 0.f);
                if (k < kend) v = *(const float4*)(A + (long)k * sA + m0 + mq);
                cvt_split(v.x, Ah[mq + 0][kq], Al[mq + 0][kq]);
                cvt_split(v.y, Ah[mq + 1][kq], Al[mq + 1][kq]);
                cvt_split(v.z, Ah[mq + 2][kq], Al[mq + 2][kq]);
                cvt_split(v.w, Ah[mq + 3][kq], Al[mq + 3][kq]);
            }
        }
        // ---- load + split B tile: 128(n) x 32(k) ----
        if (BKC) {
            #pragma unroll
            for (int i = 0; i < 4; i++) {
                int idx = tid + i * 256;
                int r = idx >> 3, kq = (idx & 7) << 2;
                int k = k0 + kq;
                float4 v = make_float4(0.f, 0.f, 0.f, 0.f);
                if (n0 + r < N) {
                    const float* src = B + (long)(n0 + r) * sB + k;
                    if (k + 3 < kend) v = *(const float4*)src;
                    else {
                        if (k + 0 < kend) v.x = src[0];
                        if (k + 1 < kend) v.y = src[1];
                        if (k + 2 < kend) v.z = src[2];
                        if (k + 3 < kend) v.w = src[3];
                    }
                }
                cvt_split(v.x, Bh[r][kq + 0], Bl[r][kq + 0]);
                cvt_split(v.y, Bh[r][kq + 1], Bl[r][kq + 1]);
                cvt_split(v.z, Bh[r][kq + 2], Bl[r][kq + 2]);
                cvt_split(v.w, Bh[r][kq + 3], Bl[r][kq + 3]);
            }
        } else {
            #pragma unroll
            for (int i = 0; i < 4; i++) {
                int idx = tid + i * 256;
                int kq = idx >> 5, nq = (idx & 31) << 2;
                int k = k0 + kq;
                float4 v = make_float4(0.f, 0.f, 0.f, 0.f);
                if (k < kend) {
                    const float* src = B + (long)k * sB + n0 + nq;
                    if (n0 + nq + 3 < N) v = *(const float4*)src;
                    else {
                        if (n0 + nq + 0 < N) v.x = src[0];
                        if (n0 + nq + 1 < N) v.y = src[1];
                        if (n0 + nq + 2 < N) v.z = src[2];
                        if (n0 + nq + 3 < N) v.w = src[3];
                    }
                }
                cvt_split(v.x, Bh[nq + 0][kq], Bl[nq + 0][kq]);
                cvt_split(v.y, Bh[nq + 1][kq], Bl[nq + 1][kq]);
                cvt_split(v.z, Bh[nq + 2][kq], Bl[nq + 2][kq]);
                cvt_split(v.w, Bh[nq + 3][kq], Bl[nq + 3][kq]);
            }
        }
        __syncthreads();

        // ---- two k16 MMA steps ----
        #pragma unroll
        for (int s = 0; s < 2; s++) {
            const int sb = s * 32;   // byte offset of k-half within row
            uint32_t ah[2][4], al[2][4];
            #pragma unroll
            for (int mf = 0; mf < 2; mf++) {
                int row = wm * 32 + mf * 16 + lrow;
                ldsm4(ah[mf][0], ah[mf][1], ah[mf][2], ah[mf][3],
                      aAh + row * 80 + lcol + sb);
                ldsm4(al[mf][0], al[mf][1], al[mf][2], al[mf][3],
                      aAl + row * 80 + lcol + sb);
            }
            #pragma unroll
            for (int nf = 0; nf < 4; nf++) {
                int row = wn * 64 + nf * 16 + lrow;
                uint32_t bh[4], bl[4];
                ldsm4(bh[0], bh[1], bh[2], bh[3], aBh + row * 80 + lcol + sb);
                ldsm4(bl[0], bl[1], bl[2], bl[3], aBl + row * 80 + lcol + sb);
                #pragma unroll
                for (int j = 0; j < 2; j++) {
                    #pragma unroll
                    for (int mf = 0; mf < 2; mf++) {
                        float* c = acc[mf][nf * 2 + j];
                        mma16816(c, ah[mf], bh[j], bh[j + 2]);   // hi*hi
                        mma16816(c, al[mf], bh[j], bh[j + 2]);   // lo*hi
                        mma16816(c, ah[mf], bl[j], bl[j + 2]);   // hi*lo
                    }
                }
            }
        }
    }

    // ---- epilogue ----
    const int tg = lane >> 2;           // 0..7
    const int tn = (lane & 3) << 1;     // 0,2,4,6
    #pragma unroll
    for (int mf = 0; mf < 2; mf++) {
        #pragma unroll
        for (int h2 = 0; h2 < 2; h2++) {
            int m = m0 + wm * 32 + mf * 16 + h2 * 8 + tg;
            float rd = rowdiv ? rowdiv[m] : 1.f;
            #pragma unroll
            for (int nfj = 0; nfj < 8; nfj++) {
                int n = n0 + wn * 64 + nfj * 8 + tn;
                if (n >= N) continue;
                float2 v;
                v.x = acc[mf][nfj][h2 * 2 + 0];
                v.y = acc[mf][nfj][h2 * 2 + 1];
                if (bias) { v.x += bias[n]; v.y += bias[n + 1]; }
                if (relu) { v.x = fmaxf(v.x, 0.f); v.y = fmaxf(v.y, 0.f); }
                if (rowdiv) { v.x /= rd; v.y /= rd; }
                *(float2*)(C + (long)m * ldc + n) = v;
            }
        }
    }
}

// ---------------- gather -----------------------------------------------------
__global__ void gather_kernel(const float* __restrict__ emb,
                              const int* __restrict__ idx,
                              float* __restrict__ out, int d) {
    int r = blockIdx.x;
    long src = idx[r];
    const float* s = emb + src * (long)d;
    float* o = out + (long)r * d;
    for (int c = threadIdx.x; c < d; c += blockDim.x) o[c] = s[c];
}

// ---------------- split-K reduce with per-row divide --------------------------
__global__ void splitk_reduce_kernel(const float* __restrict__ part,
                                     const float* __restrict__ rowdiv,
                                     float* __restrict__ C, long ldc,
                                     int M, int N, int S) {
    long i = (long)blockIdx.x * blockDim.x + threadIdx.x;
    long total = (long)M * N;
    if (i >= total) return;
    int m = (int)(i / N), n = (int)(i % N);
    float s = 0.f;
    for (int p = 0; p < S; p++) s += part[(long)p * total + i];
    C[(long)m * ldc + n] = s / rowdiv[m];
}

// ---------------- row sums ----------------------------------------------------
__global__ void rowsum_kernel(const float* __restrict__ A,
                              float* __restrict__ out, int cols) {
    __shared__ float sm[256];
    int r = blockIdx.x;
    const float* a = A + (long)r * cols;
    float s = 0.f;
    for (int c = threadIdx.x; c < cols; c += 256) s += a[c];
    sm[threadIdx.x] = s;
    __syncthreads();
    for (int o = 128; o > 0; o >>= 1) {
        if (threadIdx.x < o) sm[threadIdx.x] += sm[threadIdx.x + o];
        __syncthreads();
    }
    if (threadIdx.x == 0) out[r] = sm[0];
}

// ---------------- column sums (two-stage, deterministic) ----------------------
__global__ void colsum_part_kernel(const float* __restrict__ A,
                                   float* __restrict__ part,
                                   int R, int C, int rows_per) {
    int c = blockIdx.x * blockDim.x + threadIdx.x;
    if (c >= C) return;
    int r0 = blockIdx.y * rows_per;
    int r1 = min(r0 + rows_per, R);
    float s = 0.f;
    for (int r = r0; r < r1; r++) s += A[(long)r * C + c];
    part[(long)blockIdx.y * C + c] = s;
}

__global__ void colsum_reduce_kernel(const float* __restrict__ part,
                                     float* __restrict__ out, int C, int P) {
    int c = blockIdx.x * blockDim.x + threadIdx.x;
    if (c >= C) return;
    float s = 0.f;
    for (int p = 0; p < P; p++) s += part[(long)p * C + c];
    out[c] = s;
}

// ---------------- concat ------------------------------------------------------
__global__ void concat_kernel(const float* __restrict__ a,
                              const float* __restrict__ b,
                              float* __restrict__ out,
                              int n, int da, int db) {
    int dt = da + db;
    long total = (long)n * dt;
    long i = (long)blockIdx.x * blockDim.x + threadIdx.x;
    if (i >= total) return;
    int r = (int)(i / dt), c = (int)(i % dt);
    out[i] = (c < da) ? a[(long)r * da + c] : b[(long)r * db + (c - da)];
}

// ---------------- final MLP head + softmax -------------------------------------
__global__ void head_kernel(const float* __restrict__ v,
                            const float* __restrict__ Wg1, const float* __restrict__ bg1,
                            const float* __restrict__ Wg2, const float* __restrict__ bg2,
                            const float* __restrict__ Wg3, const float* __restrict__ bg3,
                            float* __restrict__ y) {
    __shared__ float sv[2 * HN];
    __shared__ float y1[HN];
    __shared__ float y2[HN];
    __shared__ float logit[3];
    int t = threadIdx.x;
    sv[t] = v[t];
    sv[t + HN] = v[t + HN];
    __syncthreads();
    {
        float acc = bg1[t];
        const float* w = Wg1 + (long)t * (2 * HN);
        for (int k = 0; k < 2 * HN; k++) acc += sv[k] * w[k];
        y1[t] = fmaxf(acc, 0.f);
    }
    __syncthreads();
    {
        float acc = bg2[t];
        const float* w = Wg2 + (long)t * HN;
        for (int k = 0; k < HN; k++) acc += y1[k] * w[k];
        y2[t] = fmaxf(acc, 0.f);
    }
    __syncthreads();
    if (t < 3) {
        float a = bg3[t];
        const float* w = Wg3 + (long)t * HN;
        for (int k = 0; k < HN; k++) a += y2[k] * w[k];
        logit[t] = a;
    }
    __syncthreads();
    if (t == 0) {
        float m = fmaxf(logit[0], fmaxf(logit[1], logit[2]));
        float e0 = expf(logit[0] - m), e1 = expf(logit[1] - m), e2 = expf(logit[2] - m);
        float s = e0 + e1 + e2;
        y[0] = e0 / s; y[1] = e1 / s; y[2] = e2 / s;
    }
}

// ---------------- host dispatch -----------------------------------------------
static void launch_mgemm(int akc, int bkc,
                         const float* A, long sA, const float* B, long sB,
                         const float* bias, const float* rowdiv,
                         float* C, long ldc, long sliceStride,
                         int M, int N, int K, int splits, int relu) {
    int kps = (K + splits - 1) / splits;
    kps = ((kps + 31) / 32) * 32;
    dim3 grid((N + 127) / 128, M / 128, splits);
    if (akc && bkc)
        mgemm<true, true ><<<grid, 256>>>(A, sA, B, sB, bias, rowdiv, C, ldc, sliceStride, M, N, K, kps, relu);
    else if (akc)
        mgemm<true, false><<<grid, 256>>>(A, sA, B, sB, bias, rowdiv, C, ldc, sliceStride, M, N, K, kps, relu);
    else if (bkc)
        mgemm<false, true><<<grid, 256>>>(A, sA, B, sB, bias, rowdiv, C, ldc, sliceStride, M, N, K, kps, relu);
    else
        mgemm<false, false><<<grid, 256>>>(A, sA, B, sB, bias, rowdiv, C, ldc, sliceStride, M, N, K, kps, relu);
}

extern "C" void kernel_launch(void* const* d_in, const int* in_sizes, int n_in,
                              void* d_out, int out_size) {
    const int*   p_idx = (const int*)  d_in[0];
    const int*   h_idx = (const int*)  d_in[1];
    const float* emb   = (const float*)d_in[2];
    const float* W_a1  = (const float*)d_in[3];
    const float* b_a1  = (const float*)d_in[4];
    const float* W_a2  = (const float*)d_in[5];
    const float* b_a2  = (const float*)d_in[6];
    const float* W_c1  = (const float*)d_in[7];
    const float* b_c1  = (const float*)d_in[8];
    const float* W_c2  = (const float*)d_in[9];
    const float* b_c2  = (const float*)d_in[10];
    const float* W_g1  = (const float*)d_in[11];
    const float* b_g1  = (const float*)d_in[12];
    const float* W_g2  = (const float*)d_in[13];
    const float* b_g2  = (const float*)d_in[14];
    const float* W_g3  = (const float*)d_in[15];
    const float* b_g3  = (const float*)d_in[16];

    float* out = (float*)d_out;
    const long E_OFF    = 0;
    const long BETA_OFF = (long)LPN * LHN;
    const long ALPHA_OFF= BETA_OFF + (long)LPN * DN;
    const long V1_OFF   = ALPHA_OFF + (long)LHN * DN;
    const long V2_OFF   = V1_OFF + HN;
    const long Y_OFF    = V2_OFF + HN;

    float *pemb, *hemb, *t, *fp, *fh, *x, *u, *eik, *ekj, *part, *split;
    cudaGetSymbolAddress((void**)&pemb,  g_pemb);
    cudaGetSymbolAddress((void**)&hemb,  g_hemb);
    cudaGetSymbolAddress((void**)&t,     g_t);
    cudaGetSymbolAddress((void**)&fp,    g_fp);
    cudaGetSymbolAddress((void**)&fh,    g_fh);
    cudaGetSymbolAddress((void**)&x,     g_x);
    cudaGetSymbolAddress((void**)&u,     g_u);
    cudaGetSymbolAddress((void**)&eik,   g_eik);
    cudaGetSymbolAddress((void**)&ekj,   g_ekj);
    cudaGetSymbolAddress((void**)&part,  g_part);
    cudaGetSymbolAddress((void**)&split, g_split);

    // 1) gathers
    gather_kernel<<<LPN, 128>>>(emb, p_idx, pemb, DN);
    gather_kernel<<<LHN, 128>>>(emb, h_idx, hemb, DN);

    // 2) attend(p): fp = relu(relu(pemb@Wa1^T+b)@Wa2^T+b)
    launch_mgemm(1, 1, pemb, DN, W_a1, DN, b_a1, nullptr, t,  HN, 0, LPN, HN, DN, 1, 1);
    launch_mgemm(1, 1, t,    HN, W_a2, HN, b_a2, nullptr, fp, HN, 0, LPN, HN, HN, 1, 1);
    // 3) attend(h)
    launch_mgemm(1, 1, hemb, DN, W_a1, DN, b_a1, nullptr, t,  HN, 0, LHN, HN, DN, 1, 1);
    launch_mgemm(1, 1, t,    HN, W_a2, HN, b_a2, nullptr, fh, HN, 0, LHN, HN, HN, 1, 1);

    // 4) E = fp @ reshape(fh,[H,LH]): B(n,k) = fh_flat[k*LHN + n] -> BKC=false
    launch_mgemm(1, 0, fp, HN, fh, LHN, nullptr, nullptr,
                 out + E_OFF, LHN, 0, LPN, LHN, HN, 1, 0);

    // 5) eik = rowsum(E), ekj = colsum(E)
    rowsum_kernel<<<LPN, 256>>>(out + E_OFF, eik, LHN);
    {
        dim3 g((LHN + 255) / 256, 32);
        colsum_part_kernel<<<g, 256>>>(out + E_OFF, part, LPN, LHN, 128);
        colsum_reduce_kernel<<<(LHN + 255) / 256, 256>>>(part, ekj, LHN, 32);
    }

    // 6) beta = (E @ h_emb) / eik : A=E KC, B(n,k)=hemb[k*DN+n] -> BKC=false, split-K x2
    launch_mgemm(1, 0, out + E_OFF, LHN, hemb, DN, nullptr, nullptr,
                 split, DN, (long)LPN * DN, LPN, DN, LHN, 2, 0);
    {
        long total = (long)LPN * DN;
        splitk_reduce_kernel<<<(int)((total + 255) / 256), 256>>>(
            split, eik, out + BETA_OFF, DN, LPN, DN, 2);
    }
    // 7) alpha = (E^T @ p_emb) / ekj : A(m,k)=E[k*LHN+m] -> AKC=false; B=pemb BKC=false
    launch_mgemm(0, 0, out + E_OFF, LHN, pemb, DN, nullptr, nullptr,
                 split, DN, (long)LHN * DN, LHN, DN, LPN, 2, 0);
    {
        long total = (long)LHN * DN;
        splitk_reduce_kernel<<<(int)((total + 255) / 256), 256>>>(
            split, ekj, out + ALPHA_OFF, DN, LHN, DN, 2);
    }

    // 8) v1 = colsum(comp([p_emb | beta]))
    {
        long total = (long)LPN * 2 * DN;
        concat_kernel<<<(int)((total + 255) / 256), 256>>>(pemb, out + BETA_OFF, x, LPN, DN, DN);
        launch_mgemm(1, 1, x, 2 * DN, W_c1, 2 * DN, b_c1, nullptr, t, HN, 0, LPN, HN, 2 * DN, 1, 1);
        launch_mgemm(1, 1, t, HN,     W_c2, HN,     b_c2, nullptr, u, HN, 0, LPN, HN, HN, 1, 1);
        dim3 g((HN + 255) / 256, 8);
        colsum_part_kernel<<<g, 256>>>(u, part, LPN, HN, 512);
        colsum_reduce_kernel<<<(HN + 255) / 256, 256>>>(part, out + V1_OFF, HN, 8);
    }
    // 9) v2 = colsum(comp([h_emb | alpha]))
    {
        long total = (long)LHN * 2 * DN;
        concat_kernel<<<(int)((total + 255) / 256), 256>>>(hemb, out + ALPHA_OFF, x, LHN, DN, DN);
        launch_mgemm(1, 1, x, 2 * DN, W_c1, 2 * DN, b_c1, nullptr, t, HN, 0, LHN, HN, 2 * DN, 1, 1);
        launch_mgemm(1, 1, t, HN,     W_c2, HN,     b_c2, nullptr, u, HN, 0, LHN, HN, HN, 1, 1);
        dim3 g((HN + 255) / 256, 8);
        colsum_part_kernel<<<g, 256>>>(u, part, LHN, HN, 512);
        colsum_reduce_kernel<<<(HN + 255) / 256, 256>>>(part, out + V2_OFF, HN, 8);
    }

    // 10) head
    head_kernel<<<1, HN>>>(out + V1_OFF, W_g1, b_g1, W_g2, b_g2, W_g3, b_g3, out + Y_OFF);

    (void)in_sizes; (void)n_in; (void)out_size;
}

// round 5
// speedup vs baseline: 1.7023x; 1.7023x over previous
#include <cuda_runtime.h>
#include <cuda_bf16.h>
#include <cstdint>
#include <cmath>

#define LPN 4096
#define LHN 4096
#define DN  300
#define HN  512
#define DP  320          // DN padded to 32
#define D2P 608          // 2*DN padded to 32
#define NROWS_PAD 384    // DN padded to 128 (B-operand rows for beta/alpha)

// ---------------- scratch (static device globals) ---------------------------
__device__ float g_pemb[LPN * DN];
__device__ float g_hemb[LHN * DN];
__device__ float g_t   [LPN * HN];
__device__ float g_fp  [LPN * HN];
__device__ float g_fh  [LHN * HN];
__device__ float g_u   [LPN * HN];
__device__ float g_eik [LPN];
__device__ float g_ekj [LHN];
__device__ float g_part[32 * 4096];
__device__ float g_split[2 * LPN * DN];

// bf16 hi/lo split operand buffers
__device__ __nv_bfloat16 g_pembs_h[LPN * DP],  g_pembs_l[LPN * DP];
__device__ __nv_bfloat16 g_hembs_h[LHN * DP],  g_hembs_l[LHN * DP];
__device__ __nv_bfloat16 g_ths_h [LPN * HN],   g_ths_l [LPN * HN];
__device__ __nv_bfloat16 g_fps_h [LPN * HN],   g_fps_l [LPN * HN];
__device__ __nv_bfloat16 g_fhTs_h[LHN * HN],   g_fhTs_l[LHN * HN];
__device__ __nv_bfloat16 g_Es_h [(long)LPN * LHN], g_Es_l [(long)LPN * LHN];
__device__ __nv_bfloat16 g_ETs_h[(long)LPN * LHN], g_ETs_l[(long)LPN * LHN];
__device__ __nv_bfloat16 g_hTs_h[NROWS_PAD * LHN], g_hTs_l[NROWS_PAD * LHN];
__device__ __nv_bfloat16 g_pTs_h[NROWS_PAD * LPN], g_pTs_l[NROWS_PAD * LPN];
__device__ __nv_bfloat16 g_xs_h [LPN * D2P],   g_xs_l [LPN * D2P];
__device__ __nv_bfloat16 g_Wa1s_h[HN * DP],    g_Wa1s_l[HN * DP];
__device__ __nv_bfloat16 g_Wa2s_h[HN * HN],    g_Wa2s_l[HN * HN];
__device__ __nv_bfloat16 g_Wc1s_h[HN * D2P],   g_Wc1s_l[HN * D2P];
__device__ __nv_bfloat16 g_Wc2s_h[HN * HN],    g_Wc2s_l[HN * HN];

// ---------------- PTX helpers ------------------------------------------------
__device__ __forceinline__ uint32_t smem_u32(const void* p) {
    uint32_t a;
    asm("{ .reg .u64 t; cvta.to.shared.u64 t, %1; cvt.u32.u64 %0, t; }" : "=r"(a) : "l"(p));
    return a;
}
__device__ __forceinline__ void ldsm4(uint32_t& r0, uint32_t& r1, uint32_t& r2,
                                      uint32_t& r3, uint32_t addr) {
    asm volatile("ldmatrix.sync.aligned.m8n8.x4.shared.b16 {%0,%1,%2,%3}, [%4];"
                 : "=r"(r0), "=r"(r1), "=r"(r2), "=r"(r3) : "r"(addr));
}
__device__ __forceinline__ void mma16816(float* c, const uint32_t* a,
                                         const uint32_t b0, const uint32_t b1) {
    asm volatile(
        "mma.sync.aligned.m16n8k16.row.col.f32.bf16.bf16.f32 "
        "{%0,%1,%2,%3}, {%4,%5,%6,%7}, {%8,%9}, {%0,%1,%2,%3};"
        : "+f"(c[0]), "+f"(c[1]), "+f"(c[2]), "+f"(c[3])
        : "r"(a[0]), "r"(a[1]), "r"(a[2]), "r"(a[3]), "r"(b0), "r"(b1));
}
__device__ __forceinline__ void cvt_split(float x, __nv_bfloat16& hi, __nv_bfloat16& lo) {
    hi = __float2bfloat16(x);
    lo = __float2bfloat16(x - __bfloat162float(hi));
}
__device__ __forceinline__ void cp16(uint32_t dst, const void* src) {
    asm volatile("cp.async.cg.shared.global [%0], [%1], 16;"
                 :: "r"(dst), "l"(__cvta_generic_to_global(src)));
}
__device__ __forceinline__ void cp_commit() {
    asm volatile("cp.async.commit_group;");
}
template <int NN> __device__ __forceinline__ void cp_wait() {
    asm volatile("cp.async.wait_group %0;" :: "n"(NN));
}

// ---------------- bf16x3 mma.sync SGEMM, pre-split operands, cp.async 2-stage
// C[m,n] = epi( sum_k A(m,k)*B(n,k) ); A = Ah+Al, B = Bh+Bl (bf16 hi/lo, K-contig)
// Requirements: M % 128 == 0; B has >= gridX*128 valid (zero-padded) rows;
// ldA/ldB/K multiples of 32 (zero-padded); kPerSlice multiple of 32.
__global__ __launch_bounds__(256)
void bgemm(const __nv_bfloat16* __restrict__ Agh, const __nv_bfloat16* __restrict__ Agl, long ldA,
           const __nv_bfloat16* __restrict__ Bgh, const __nv_bfloat16* __restrict__ Bgl, long ldB,
           const float* __restrict__ bias, const float* __restrict__ rowdiv,
           float* __restrict__ C, long ldc, long sliceStride,
           __nv_bfloat16* __restrict__ Chi, __nv_bfloat16* __restrict__ Clo, long ldS,
           int M, int N, int K, int kPerSlice, int relu) {
    extern __shared__ __align__(16) char smraw[];
    // layout: stage(2) x [Ah(10240) Al(10240) Bh(10240) Bl(10240)]
    const int tid = threadIdx.x, lane = tid & 31, wid = tid >> 5;
    const int wm = wid >> 1, wn = wid & 1;
    const int m0 = blockIdx.y * 128, n0 = blockIdx.x * 128;
    const int kbeg = blockIdx.z * kPerSlice;
    const int kend = min(K, kbeg + kPerSlice);
    const int nch = (kend - kbeg) >> 5;
    C += (long)blockIdx.z * sliceStride;

    const uint32_t sb = smem_u32(smraw);

    float acc[2][8][4];
    #pragma unroll
    for (int i = 0; i < 2; i++)
        #pragma unroll
        for (int j = 0; j < 8; j++)
            #pragma unroll
            for (int e = 0; e < 4; e++) acc[i][j][e] = 0.f;

    const int lrow = (((lane >> 3) & 1) << 3) + (lane & 7);
    const int lcol = (lane >> 4) << 4;

    // stage loader: 2048 x 16B chunks, 8 per thread
    auto load_stage = [&](int st, int k0) {
        uint32_t sbase = sb + st * 40960;
        #pragma unroll
        for (int i = 0; i < 2; i++) {
            int c = tid + i * 256;          // 0..511
            int r = c >> 2, kq = c & 3;
            uint32_t dso = (uint32_t)(r * 80 + kq * 16);
            long ao = (long)(m0 + r) * ldA + k0 + kq * 8;
            long bo = (long)(n0 + r) * ldB + k0 + kq * 8;
            cp16(sbase + dso,          Agh + ao);
            cp16(sbase + 10240 + dso,  Agl + ao);
            cp16(sbase + 20480 + dso,  Bgh + bo);
            cp16(sbase + 30720 + dso,  Bgl + bo);
        }
    };

    load_stage(0, kbeg);
    cp_commit();

    for (int i = 0; i < nch; i++) {
        if (i + 1 < nch) {
            load_stage((i + 1) & 1, kbeg + (i + 1) * 32);
            cp_commit();
            cp_wait<1>();
        } else {
            cp_wait<0>();
        }
        __syncthreads();

        const uint32_t aAh = sb + (i & 1) * 40960;
        const uint32_t aAl = aAh + 10240;
        const uint32_t aBh = aAh + 20480;
        const uint32_t aBl = aAh + 30720;

        #pragma unroll
        for (int s = 0; s < 2; s++) {
            const int sbyte = s * 32;
            uint32_t ah[2][4], al[2][4];
            #pragma unroll
            for (int mf = 0; mf < 2; mf++) {
                int row = wm * 32 + mf * 16 + lrow;
                ldsm4(ah[mf][0], ah[mf][1], ah[mf][2], ah[mf][3],
                      aAh + row * 80 + lcol + sbyte);
                ldsm4(al[mf][0], al[mf][1], al[mf][2], al[mf][3],
                      aAl + row * 80 + lcol + sbyte);
            }
            #pragma unroll
            for (int nf = 0; nf < 4; nf++) {
                int row = wn * 64 + nf * 16 + lrow;
                uint32_t bh[4], bl[4];
                ldsm4(bh[0], bh[1], bh[2], bh[3], aBh + row * 80 + lcol + sbyte);
                ldsm4(bl[0], bl[1], bl[2], bl[3], aBl + row * 80 + lcol + sbyte);
                #pragma unroll
                for (int j = 0; j < 2; j++) {
                    #pragma unroll
                    for (int mf = 0; mf < 2; mf++) {
                        float* c = acc[mf][nf * 2 + j];
                        mma16816(c, ah[mf], bh[j], bh[j + 2]);
                        mma16816(c, al[mf], bh[j], bh[j + 2]);
                        mma16816(c, ah[mf], bl[j], bl[j + 2]);
                    }
                }
            }
        }
        __syncthreads();
    }

    // ---- epilogue ----
    const int tg = lane >> 2;
    const int tn = (lane & 3) << 1;
    #pragma unroll
    for (int mf = 0; mf < 2; mf++) {
        #pragma unroll
        for (int h2 = 0; h2 < 2; h2++) {
            int m = m0 + wm * 32 + mf * 16 + h2 * 8 + tg;
            float rd = rowdiv ? rowdiv[m] : 1.f;
            #pragma unroll
            for (int nfj = 0; nfj < 8; nfj++) {
                int n = n0 + wn * 64 + nfj * 8 + tn;
                if (n >= N) continue;
                float2 v;
                v.x = acc[mf][nfj][h2 * 2 + 0];
                v.y = acc[mf][nfj][h2 * 2 + 1];
                if (bias) { v.x += bias[n]; v.y += bias[n + 1]; }
                if (relu) { v.x = fmaxf(v.x, 0.f); v.y = fmaxf(v.y, 0.f); }
                if (rowdiv) { v.x /= rd; v.y /= rd; }
                *(float2*)(C + (long)m * ldc + n) = v;
                if (Chi) {
                    __nv_bfloat16 h0, l0, h1, l1;
                    cvt_split(v.x, h0, l0);
                    cvt_split(v.y, h1, l1);
                    long o = (long)m * ldS + n;
                    Chi[o] = h0; Chi[o + 1] = h1;
                    Clo[o] = l0; Clo[o + 1] = l1;
                }
            }
        }
    }
}

static const int BGEMM_SMEM = 2 * 40960;

// ---------------- transpose + split: dst[r][c] = split(src[c][r]) -----------
// src: [R][C] fp32. dst: [dR][R] bf16 hi/lo, rows >= C are zeroed (dR >= C).
__global__ void transpose_split_kernel(const float* __restrict__ src, int R, int C,
                                       __nv_bfloat16* __restrict__ dh,
                                       __nv_bfloat16* __restrict__ dl, int dR) {
    __shared__ float tile[32][33];
    int c0 = blockIdx.x * 32, r0 = blockIdx.y * 32;
    int x = threadIdx.x, y = threadIdx.y;
    #pragma unroll
    for (int i = y; i < 32; i += 8) {
        int r = r0 + i, c = c0 + x;
        tile[i][x] = (r < R && c < C) ? src[(long)r * C + c] : 0.f;
    }
    __syncthreads();
    #pragma unroll
    for (int i = y; i < 32; i += 8) {
        int dr = c0 + i, dc = r0 + x;
        if (dr < dR && dc < R) {
            __nv_bfloat16 hi, lo;
            cvt_split(tile[x][i], hi, lo);
            dh[(long)dr * R + dc] = hi;
            dl[(long)dr * R + dc] = lo;
        }
    }
}

// ---------------- split with K padding: dst[m][kpad] --------------------------
__global__ void split_pad_kernel(const float* __restrict__ src, int M, int K, int Kpad,
                                 __nv_bfloat16* __restrict__ dh,
                                 __nv_bfloat16* __restrict__ dl) {
    long i = (long)blockIdx.x * blockDim.x + threadIdx.x;
    long total = (long)M * Kpad;
    if (i >= total) return;
    int m = (int)(i / Kpad), k = (int)(i % Kpad);
    float v = (k < K) ? src[(long)m * K + k] : 0.f;
    __nv_bfloat16 hi, lo;
    cvt_split(v, hi, lo);
    dh[i] = hi; dl[i] = lo;
}

// ---------------- concat + split: [a | b | zeros] -----------------------------
__global__ void concat_split_kernel(const float* __restrict__ a,
                                    const float* __restrict__ b,
                                    int n, int da, int db, int Kpad,
                                    __nv_bfloat16* __restrict__ dh,
                                    __nv_bfloat16* __restrict__ dl) {
    long i = (long)blockIdx.x * blockDim.x + threadIdx.x;
    long total = (long)n * Kpad;
    if (i >= total) return;
    int r = (int)(i / Kpad), c = (int)(i % Kpad);
    float v = 0.f;
    if (c < da) v = a[(long)r * da + c];
    else if (c < da + db) v = b[(long)r * db + (c - da)];
    __nv_bfloat16 hi, lo;
    cvt_split(v, hi, lo);
    dh[i] = hi; dl[i] = lo;
}

// ---------------- gather -----------------------------------------------------
__global__ void gather_kernel(const float* __restrict__ emb,
                              const int* __restrict__ idx,
                              float* __restrict__ out, int d) {
    int r = blockIdx.x;
    long src = idx[r];
    const float* s = emb + src * (long)d;
    float* o = out + (long)r * d;
    for (int c = threadIdx.x; c < d; c += blockDim.x) o[c] = s[c];
}

// ---------------- split-K reduce with per-row divide --------------------------
__global__ void splitk_reduce_kernel(const float* __restrict__ part,
                                     const float* __restrict__ rowdiv,
                                     float* __restrict__ C, long ldc,
                                     int M, int N, int S) {
    long i = (long)blockIdx.x * blockDim.x + threadIdx.x;
    long total = (long)M * N;
    if (i >= total) return;
    int m = (int)(i / N), n = (int)(i % N);
    float s = 0.f;
    for (int p = 0; p < S; p++) s += part[(long)p * total + i];
    C[(long)m * ldc + n] = s / rowdiv[m];
}

// ---------------- row sums ----------------------------------------------------
__global__ void rowsum_kernel(const float* __restrict__ A,
                              float* __restrict__ out, int cols) {
    __shared__ float sm[256];
    int r = blockIdx.x;
    const float* a = A + (long)r * cols;
    float s = 0.f;
    for (int c = threadIdx.x; c < cols; c += 256) s += a[c];
    sm[threadIdx.x] = s;
    __syncthreads();
    for (int o = 128; o > 0; o >>= 1) {
        if (threadIdx.x < o) sm[threadIdx.x] += sm[threadIdx.x + o];
        __syncthreads();
    }
    if (threadIdx.x == 0) out[r] = sm[0];
}

// ---------------- column sums (two-stage, deterministic) ----------------------
__global__ void colsum_part_kernel(const float* __restrict__ A,
                                   float* __restrict__ part,
                                   int R, int C, int rows_per) {
    int c = blockIdx.x * blockDim.x + threadIdx.x;
    if (c >= C) return;
    int r0 = blockIdx.y * rows_per;
    int r1 = min(r0 + rows_per, R);
    float s = 0.f;
    for (int r = r0; r < r1; r++) s += A[(long)r * C + c];
    part[(long)blockIdx.y * C + c] = s;
}

__global__ void colsum_reduce_kernel(const float* __restrict__ part,
                                     float* __restrict__ out, int C, int P) {
    int c = blockIdx.x * blockDim.x + threadIdx.x;
    if (c >= C) return;
    float s = 0.f;
    for (int p = 0; p < P; p++) s += part[(long)p * C + c];
    out[c] = s;
}

// ---------------- final MLP head + softmax -------------------------------------
__global__ void head_kernel(const float* __restrict__ v,
                            const float* __restrict__ Wg1, const float* __restrict__ bg1,
                            const float* __restrict__ Wg2, const float* __restrict__ bg2,
                            const float* __restrict__ Wg3, const float* __restrict__ bg3,
                            float* __restrict__ y) {
    __shared__ float sv[2 * HN];
    __shared__ float y1[HN];
    __shared__ float y2[HN];
    __shared__ float logit[3];
    int t = threadIdx.x;
    sv[t] = v[t];
    sv[t + HN] = v[t + HN];
    __syncthreads();
    {
        float acc = bg1[t];
        const float* w = Wg1 + (long)t * (2 * HN);
        for (int k = 0; k < 2 * HN; k++) acc += sv[k] * w[k];
        y1[t] = fmaxf(acc, 0.f);
    }
    __syncthreads();
    {
        float acc = bg2[t];
        const float* w = Wg2 + (long)t * HN;
        for (int k = 0; k < HN; k++) acc += y1[k] * w[k];
        y2[t] = fmaxf(acc, 0.f);
    }
    __syncthreads();
    if (t < 3) {
        float a = bg3[t];
        const float* w = Wg3 + (long)t * HN;
        for (int k = 0; k < HN; k++) a += y2[k] * w[k];
        logit[t] = a;
    }
    __syncthreads();
    if (t == 0) {
        float m = fmaxf(logit[0], fmaxf(logit[1], logit[2]));
        float e0 = expf(logit[0] - m), e1 = expf(logit[1] - m), e2 = expf(logit[2] - m);
        float s = e0 + e1 + e2;
        y[0] = e0 / s; y[1] = e1 / s; y[2] = e2 / s;
    }
}

// ---------------- host dispatch -----------------------------------------------
static void launch_bgemm(const __nv_bfloat16* Ah, const __nv_bfloat16* Al, long ldA,
                         const __nv_bfloat16* Bh, const __nv_bfloat16* Bl, long ldB,
                         const float* bias, const float* rowdiv,
                         float* C, long ldc, long sliceStride,
                         __nv_bfloat16* Chi, __nv_bfloat16* Clo, long ldS,
                         int M, int N, int K, int splits, int relu) {
    cudaFuncSetAttribute(bgemm, cudaFuncAttributeMaxDynamicSharedMemorySize, BGEMM_SMEM);
    int kps = (K + splits - 1) / splits;
    kps = ((kps + 31) / 32) * 32;
    dim3 grid((N + 127) / 128, M / 128, splits);
    bgemm<<<grid, 256, BGEMM_SMEM>>>(Ah, Al, ldA, Bh, Bl, ldB, bias, rowdiv,
                                     C, ldc, sliceStride, Chi, Clo, ldS,
                                     M, N, K, kps, relu);
}

#define GETSYM(var, sym) cudaGetSymbolAddress((void**)&var, sym)

extern "C" void kernel_launch(void* const* d_in, const int* in_sizes, int n_in,
                              void* d_out, int out_size) {
    const int*   p_idx = (const int*)  d_in[0];
    const int*   h_idx = (const int*)  d_in[1];
    const float* emb   = (const float*)d_in[2];
    const float* W_a1  = (const float*)d_in[3];
    const float* b_a1  = (const float*)d_in[4];
    const float* W_a2  = (const float*)d_in[5];
    const float* b_a2  = (const float*)d_in[6];
    const float* W_c1  = (const float*)d_in[7];
    const float* b_c1  = (const float*)d_in[8];
    const float* W_c2  = (const float*)d_in[9];
    const float* b_c2  = (const float*)d_in[10];
    const float* W_g1  = (const float*)d_in[11];
    const float* b_g1  = (const float*)d_in[12];
    const float* W_g2  = (const float*)d_in[13];
    const float* b_g2  = (const float*)d_in[14];
    const float* W_g3  = (const float*)d_in[15];
    const float* b_g3  = (const float*)d_in[16];

    float* out = (float*)d_out;
    const long E_OFF    = 0;
    const long BETA_OFF = (long)LPN * LHN;
    const long ALPHA_OFF= BETA_OFF + (long)LPN * DN;
    const long V1_OFF   = ALPHA_OFF + (long)LHN * DN;
    const long V2_OFF   = V1_OFF + HN;
    const long Y_OFF    = V2_OFF + HN;

    float *pemb, *hemb, *t, *fp, *fh, *u, *eik, *ekj, *part, *split;
    GETSYM(pemb, g_pemb); GETSYM(hemb, g_hemb); GETSYM(t, g_t);
    GETSYM(fp, g_fp); GETSYM(fh, g_fh); GETSYM(u, g_u);
    GETSYM(eik, g_eik); GETSYM(ekj, g_ekj); GETSYM(part, g_part);
    GETSYM(split, g_split);

    __nv_bfloat16 *pembs_h, *pembs_l, *hembs_h, *hembs_l, *ths_h, *ths_l;
    __nv_bfloat16 *fps_h, *fps_l, *fhTs_h, *fhTs_l, *Es_h, *Es_l, *ETs_h, *ETs_l;
    __nv_bfloat16 *hTs_h, *hTs_l, *pTs_h, *pTs_l, *xs_h, *xs_l;
    __nv_bfloat16 *Wa1s_h, *Wa1s_l, *Wa2s_h, *Wa2s_l, *Wc1s_h, *Wc1s_l, *Wc2s_h, *Wc2s_l;
    GETSYM(pembs_h, g_pembs_h); GETSYM(pembs_l, g_pembs_l);
    GETSYM(hembs_h, g_hembs_h); GETSYM(hembs_l, g_hembs_l);
    GETSYM(ths_h, g_ths_h);     GETSYM(ths_l, g_ths_l);
    GETSYM(fps_h, g_fps_h);     GETSYM(fps_l, g_fps_l);
    GETSYM(fhTs_h, g_fhTs_h);   GETSYM(fhTs_l, g_fhTs_l);
    GETSYM(Es_h, g_Es_h);       GETSYM(Es_l, g_Es_l);
    GETSYM(ETs_h, g_ETs_h);     GETSYM(ETs_l, g_ETs_l);
    GETSYM(hTs_h, g_hTs_h);     GETSYM(hTs_l, g_hTs_l);
    GETSYM(pTs_h, g_pTs_h);     GETSYM(pTs_l, g_pTs_l);
    GETSYM(xs_h, g_xs_h);       GETSYM(xs_l, g_xs_l);
    GETSYM(Wa1s_h, g_Wa1s_h);   GETSYM(Wa1s_l, g_Wa1s_l);
    GETSYM(Wa2s_h, g_Wa2s_h);   GETSYM(Wa2s_l, g_Wa2s_l);
    GETSYM(Wc1s_h, g_Wc1s_h);   GETSYM(Wc1s_l, g_Wc1s_l);
    GETSYM(Wc2s_h, g_Wc2s_h);   GETSYM(Wc2s_l, g_Wc2s_l);

    // 0) weight splits
    split_pad_kernel<<<(HN * DP + 255) / 256, 256>>>(W_a1, HN, DN, DP, Wa1s_h, Wa1s_l);
    split_pad_kernel<<<(HN * HN + 255) / 256, 256>>>(W_a2, HN, HN, HN, Wa2s_h, Wa2s_l);
    split_pad_kernel<<<(HN * D2P + 255) / 256, 256>>>(W_c1, HN, 2 * DN, D2P, Wc1s_h, Wc1s_l);
    split_pad_kernel<<<(HN * HN + 255) / 256, 256>>>(W_c2, HN, HN, HN, Wc2s_h, Wc2s_l);

    // 1) gathers + splits
    gather_kernel<<<LPN, 128>>>(emb, p_idx, pemb, DN);
    gather_kernel<<<LHN, 128>>>(emb, h_idx, hemb, DN);
    split_pad_kernel<<<(LPN * DP + 255) / 256, 256>>>(pemb, LPN, DN, DP, pembs_h, pembs_l);
    split_pad_kernel<<<(LHN * DP + 255) / 256, 256>>>(hemb, LHN, DN, DP, hembs_h, hembs_l);

    // 2) attend(p): t = relu(pemb@Wa1^T+b)  [splits fused] ; fp = relu(t@Wa2^T+b)
    launch_bgemm(pembs_h, pembs_l, DP, Wa1s_h, Wa1s_l, DP, b_a1, nullptr,
                 t, HN, 0, ths_h, ths_l, HN, LPN, HN, DP, 1, 1);
    launch_bgemm(ths_h, ths_l, HN, Wa2s_h, Wa2s_l, HN, b_a2, nullptr,
                 fp, HN, 0, fps_h, fps_l, HN, LPN, HN, HN, 1, 1);
    // 3) attend(h)
    launch_bgemm(hembs_h, hembs_l, DP, Wa1s_h, Wa1s_l, DP, b_a1, nullptr,
                 t, HN, 0, ths_h, ths_l, HN, LHN, HN, DP, 1, 1);
    launch_bgemm(ths_h, ths_l, HN, Wa2s_h, Wa2s_l, HN, b_a2, nullptr,
                 fh, HN, 0, nullptr, nullptr, 0, LHN, HN, HN, 1, 1);

    // 4) fhT = transpose(reshape(fh,[H,LH])) -> [LH, H], split
    {
        dim3 g((LHN + 31) / 32, (HN + 31) / 32), b(32, 8);
        transpose_split_kernel<<<g, b>>>(fh, HN, LHN, fhTs_h, fhTs_l, LHN);
    }
    // 5) E = fp @ reshape(fh) ; splits fused
    launch_bgemm(fps_h, fps_l, HN, fhTs_h, fhTs_l, HN, nullptr, nullptr,
                 out + E_OFF, LHN, 0, Es_h, Es_l, LHN, LPN, LHN, HN, 1, 0);

    // 6) eik / ekj
    rowsum_kernel<<<LPN, 256>>>(out + E_OFF, eik, LHN);
    {
        dim3 g((LHN + 255) / 256, 32);
        colsum_part_kernel<<<g, 256>>>(out + E_OFF, part, LPN, LHN, 128);
        colsum_reduce_kernel<<<(LHN + 255) / 256, 256>>>(part, ekj, LHN, 32);
    }

    // 7) transposes for alpha / beta operands
    {
        dim3 b(32, 8);
        dim3 gE((LHN + 31) / 32, (LPN + 31) / 32);
        transpose_split_kernel<<<gE, b>>>(out + E_OFF, LPN, LHN, ETs_h, ETs_l, LHN);
        dim3 gh((NROWS_PAD + 31) / 32, (LHN + 31) / 32);
        transpose_split_kernel<<<gh, b>>>(hemb, LHN, DN, hTs_h, hTs_l, NROWS_PAD);
        dim3 gp((NROWS_PAD + 31) / 32, (LPN + 31) / 32);
        transpose_split_kernel<<<gp, b>>>(pemb, LPN, DN, pTs_h, pTs_l, NROWS_PAD);
    }

    // 8) beta = (E @ h_emb) / eik   -- split-K x2
    launch_bgemm(Es_h, Es_l, LHN, hTs_h, hTs_l, LHN, nullptr, nullptr,
                 split, DN, (long)LPN * DN, nullptr, nullptr, 0,
                 LPN, DN, LHN, 2, 0);
    splitk_reduce_kernel<<<(int)(((long)LPN * DN + 255) / 256), 256>>>(
        split, eik, out + BETA_OFF, DN, LPN, DN, 2);
    // 9) alpha = (E^T @ p_emb) / ekj -- split-K x2
    launch_bgemm(ETs_h, ETs_l, LPN, pTs_h, pTs_l, LPN, nullptr, nullptr,
                 split, DN, (long)LHN * DN, nullptr, nullptr, 0,
                 LHN, DN, LPN, 2, 0);
    splitk_reduce_kernel<<<(int)(((long)LHN * DN + 255) / 256), 256>>>(
        split, ekj, out + ALPHA_OFF, DN, LHN, DN, 2);

    // 10) v1 = colsum(comp([p_emb | beta]))
    concat_split_kernel<<<(int)(((long)LPN * D2P + 255) / 256), 256>>>(
        pemb, out + BETA_OFF, LPN, DN, DN, D2P, xs_h, xs_l);
    launch_bgemm(xs_h, xs_l, D2P, Wc1s_h, Wc1s_l, D2P, b_c1, nullptr,
                 t, HN, 0, ths_h, ths_l, HN, LPN, HN, D2P, 1, 1);
    launch_bgemm(ths_h, ths_l, HN, Wc2s_h, Wc2s_l, HN, b_c2, nullptr,
                 u, HN, 0, nullptr, nullptr, 0, LPN, HN, HN, 1, 1);
    {
        dim3 g((HN + 255) / 256, 8);
        colsum_part_kernel<<<g, 256>>>(u, part, LPN, HN, 512);
        colsum_reduce_kernel<<<(HN + 255) / 256, 256>>>(part, out + V1_OFF, HN, 8);
    }
    // 11) v2 = colsum(comp([h_emb | alpha]))
    concat_split_kernel<<<(int)(((long)LHN * D2P + 255) / 256), 256>>>(
        hemb, out + ALPHA_OFF, LHN, DN, DN, D2P, xs_h, xs_l);
    launch_bgemm(xs_h, xs_l, D2P, Wc1s_h, Wc1s_l, D2P, b_c1, nullptr,
                 t, HN, 0, ths_h, ths_l, HN, LHN, HN, D2P, 1, 1);
    launch_bgemm(ths_h, ths_l, HN, Wc2s_h, Wc2s_l, HN, b_c2, nullptr,
                 u, HN, 0, nullptr, nullptr, 0, LHN, HN, HN, 1, 1);
    {
        dim3 g((HN + 255) / 256, 8);
        colsum_part_kernel<<<g, 256>>>(u, part, LHN, HN, 512);
        colsum_reduce_kernel<<<(HN + 255) / 256, 256>>>(part, out + V2_OFF, HN, 8);
    }

    // 12) head
    head_kernel<<<1, HN>>>(out + V1_OFF, W_g1, b_g1, W_g2, b_g2, W_g3, b_g3, out + Y_OFF);

    (void)in_sizes; (void)n_in; (void)out_size;
}

// round 6
// speedup vs baseline: 1.9879x; 1.1678x over previous
#include <cuda_runtime.h>
#include <cuda_bf16.h>
#include <cstdint>
#include <cmath>

#define LPN 4096
#define LHN 4096
#define DN  300
#define HN  512
#define DP  320          // DN padded to 32
#define D2P 608          // 2*DN padded to 32
#define NROWS_PAD 384    // DN padded to 128
#define M2  8192         // batched p+h rows

// ---------------- scratch (static device globals) ---------------------------
__device__ float g_emb2[M2 * DN];          // [p rows | h rows]
__device__ float g_f2  [M2 * HN];          // fp | fh (fp32)
__device__ float g_u   [M2 * HN];
__device__ float g_eik [LPN];
__device__ float g_ekj [LHN];
__device__ float g_part [32 * 4096];
__device__ float g_part2[32 * 4096];
__device__ float g_split[4 * LPN * DN];    // 4 split-K slices (beta x2, alpha x2)

__device__ __nv_bfloat16 g_emb2s_h[M2 * DP],  g_emb2s_l[M2 * DP];
__device__ __nv_bfloat16 g_ths_h [M2 * HN],   g_ths_l [M2 * HN];
__device__ __nv_bfloat16 g_fps_h [M2 * HN],   g_fps_l [M2 * HN];
__device__ __nv_bfloat16 g_fhTs_h[LHN * HN],  g_fhTs_l[LHN * HN];
__device__ __nv_bfloat16 g_Es_h [(long)LPN * LHN], g_Es_l [(long)LPN * LHN];
__device__ __nv_bfloat16 g_ETs_h[(long)LPN * LHN], g_ETs_l[(long)LPN * LHN];
__device__ __nv_bfloat16 g_hTs_h[NROWS_PAD * LHN], g_hTs_l[NROWS_PAD * LHN];
__device__ __nv_bfloat16 g_pTs_h[NROWS_PAD * LPN], g_pTs_l[NROWS_PAD * LPN];
__device__ __nv_bfloat16 g_xs_h [M2 * D2P],   g_xs_l [M2 * D2P];
__device__ __nv_bfloat16 g_Wa1s_h[HN * DP],   g_Wa1s_l[HN * DP];
__device__ __nv_bfloat16 g_Wa2s_h[HN * HN],   g_Wa2s_l[HN * HN];
__device__ __nv_bfloat16 g_Wc1s_h[HN * D2P],  g_Wc1s_l[HN * D2P];
__device__ __nv_bfloat16 g_Wc2s_h[HN * HN],   g_Wc2s_l[HN * HN];

// ---------------- PTX helpers ------------------------------------------------
__device__ __forceinline__ uint32_t smem_u32(const void* p) {
    uint32_t a;
    asm("{ .reg .u64 t; cvta.to.shared.u64 t, %1; cvt.u32.u64 %0, t; }" : "=r"(a) : "l"(p));
    return a;
}
__device__ __forceinline__ void ldsm4(uint32_t& r0, uint32_t& r1, uint32_t& r2,
                                      uint32_t& r3, uint32_t addr) {
    asm volatile("ldmatrix.sync.aligned.m8n8.x4.shared.b16 {%0,%1,%2,%3}, [%4];"
                 : "=r"(r0), "=r"(r1), "=r"(r2), "=r"(r3) : "r"(addr));
}
__device__ __forceinline__ void mma16816(float* c, const uint32_t* a,
                                         const uint32_t b0, const uint32_t b1) {
    asm volatile(
        "mma.sync.aligned.m16n8k16.row.col.f32.bf16.bf16.f32 "
        "{%0,%1,%2,%3}, {%4,%5,%6,%7}, {%8,%9}, {%0,%1,%2,%3};"
        : "+f"(c[0]), "+f"(c[1]), "+f"(c[2]), "+f"(c[3])
        : "r"(a[0]), "r"(a[1]), "r"(a[2]), "r"(a[3]), "r"(b0), "r"(b1));
}
__device__ __forceinline__ void cvt_split(float x, __nv_bfloat16& hi, __nv_bfloat16& lo) {
    hi = __float2bfloat16(x);
    lo = __float2bfloat16(x - __bfloat162float(hi));
}
__device__ __forceinline__ void cp16(uint32_t dst, const void* src) {
    asm volatile("cp.async.cg.shared.global [%0], [%1], 16;"
                 :: "r"(dst), "l"(__cvta_generic_to_global(src)));
}
__device__ __forceinline__ void cp_commit() {
    asm volatile("cp.async.commit_group;");
}
template <int NN> __device__ __forceinline__ void cp_wait() {
    asm volatile("cp.async.wait_group %0;" :: "n"(NN));
}

// ---------------- bf16x3 mma.sync SGEMM -------------------------------------
// C[m,n] = epi( sum_k A(m,k)*B(n,k) ), operands pre-split bf16 hi/lo K-contig.
// Dual-problem: blocks with blockIdx.z >= zSecond use A2/B2 (same shape).
// Optional fused outputs: Chi/Clo bf16 split of C; Th/Tl transposed split +
// rowpart/colpart per-CTA partial sums (for E).
__global__ __launch_bounds__(256)
void bgemm(const __nv_bfloat16* __restrict__ Agh, const __nv_bfloat16* __restrict__ Agl, long ldA,
           const __nv_bfloat16* __restrict__ Bgh, const __nv_bfloat16* __restrict__ Bgl, long ldB,
           const __nv_bfloat16* __restrict__ A2gh, const __nv_bfloat16* __restrict__ A2gl,
           const __nv_bfloat16* __restrict__ B2gh, const __nv_bfloat16* __restrict__ B2gl,
           int zSecond,
           const float* __restrict__ bias,
           float* __restrict__ C, long ldc, long sliceStride,
           __nv_bfloat16* __restrict__ Chi, __nv_bfloat16* __restrict__ Clo, long ldS,
           __nv_bfloat16* __restrict__ Th, __nv_bfloat16* __restrict__ Tl, long ldT,
           float* __restrict__ rowpart, float* __restrict__ colpart,
           int M, int N, int K, int kPerSlice, int relu) {
    extern __shared__ __align__(16) char smraw[];
    const int tid = threadIdx.x, lane = tid & 31, wid = tid >> 5;
    const int wm = wid >> 1, wn = wid & 1;
    const int m0 = blockIdx.y * 128, n0 = blockIdx.x * 128;
    const int zz = blockIdx.z;
    if (A2gh && zz >= zSecond) { Agh = A2gh; Agl = A2gl; Bgh = B2gh; Bgl = B2gl; }
    const int kbeg = (zz % zSecond) * kPerSlice;
    const int kend = min(K, kbeg + kPerSlice);
    const int nch = (kend - kbeg) >> 5;
    C += (long)zz * sliceStride;

    const uint32_t sb = smem_u32(smraw);

    float acc[2][8][4];
    #pragma unroll
    for (int i = 0; i < 2; i++)
        #pragma unroll
        for (int j = 0; j < 8; j++)
            #pragma unroll
            for (int e = 0; e < 4; e++) acc[i][j][e] = 0.f;

    const int lrow = (((lane >> 3) & 1) << 3) + (lane & 7);
    const int lcol = (lane >> 4) << 4;

    auto load_stage = [&](int st, int k0) {
        uint32_t sbase = sb + st * 40960;
        #pragma unroll
        for (int i = 0; i < 2; i++) {
            int c = tid + i * 256;
            int r = c >> 2, kq = c & 3;
            uint32_t dso = (uint32_t)(r * 80 + kq * 16);
            long ao = (long)(m0 + r) * ldA + k0 + kq * 8;
            long bo = (long)(n0 + r) * ldB + k0 + kq * 8;
            cp16(sbase + dso,          Agh + ao);
            cp16(sbase + 10240 + dso,  Agl + ao);
            cp16(sbase + 20480 + dso,  Bgh + bo);
            cp16(sbase + 30720 + dso,  Bgl + bo);
        }
    };

    load_stage(0, kbeg);
    cp_commit();

    for (int i = 0; i < nch; i++) {
        if (i + 1 < nch) {
            load_stage((i + 1) & 1, kbeg + (i + 1) * 32);
            cp_commit();
            cp_wait<1>();
        } else {
            cp_wait<0>();
        }
        __syncthreads();

        const uint32_t aAh = sb + (i & 1) * 40960;
        const uint32_t aAl = aAh + 10240;
        const uint32_t aBh = aAh + 20480;
        const uint32_t aBl = aAh + 30720;

        #pragma unroll
        for (int s = 0; s < 2; s++) {
            const int sbyte = s * 32;
            uint32_t ah[2][4], al[2][4];
            #pragma unroll
            for (int mf = 0; mf < 2; mf++) {
                int row = wm * 32 + mf * 16 + lrow;
                ldsm4(ah[mf][0], ah[mf][1], ah[mf][2], ah[mf][3],
                      aAh + row * 80 + lcol + sbyte);
                ldsm4(al[mf][0], al[mf][1], al[mf][2], al[mf][3],
                      aAl + row * 80 + lcol + sbyte);
            }
            #pragma unroll
            for (int nf = 0; nf < 4; nf++) {
                int row = wn * 64 + nf * 16 + lrow;
                uint32_t bh[4], bl[4];
                ldsm4(bh[0], bh[1], bh[2], bh[3], aBh + row * 80 + lcol + sbyte);
                ldsm4(bl[0], bl[1], bl[2], bl[3], aBl + row * 80 + lcol + sbyte);
                #pragma unroll
                for (int j = 0; j < 2; j++) {
                    #pragma unroll
                    for (int mf = 0; mf < 2; mf++) {
                        float* c = acc[mf][nf * 2 + j];
                        mma16816(c, ah[mf], bh[j], bh[j + 2]);
                        mma16816(c, al[mf], bh[j], bh[j + 2]);
                        mma16816(c, ah[mf], bl[j], bl[j + 2]);
                    }
                }
            }
        }
        __syncthreads();
    }

    // ---- epilogue ----
    const int tg = lane >> 2;
    const int tn = (lane & 3) << 1;
    #pragma unroll
    for (int mf = 0; mf < 2; mf++) {
        #pragma unroll
        for (int h2 = 0; h2 < 2; h2++) {
            int m = m0 + wm * 32 + mf * 16 + h2 * 8 + tg;
            #pragma unroll
            for (int nfj = 0; nfj < 8; nfj++) {
                int n = n0 + wn * 64 + nfj * 8 + tn;
                if (n >= N) continue;
                float2 v;
                v.x = acc[mf][nfj][h2 * 2 + 0];
                v.y = acc[mf][nfj][h2 * 2 + 1];
                if (bias) { v.x += bias[n]; v.y += bias[n + 1]; }
                if (relu) { v.x = fmaxf(v.x, 0.f); v.y = fmaxf(v.y, 0.f); }
                if (C) *(float2*)(C + (long)m * ldc + n) = v;
                if (Chi) {
                    __nv_bfloat16 h0, l0, h1, l1;
                    cvt_split(v.x, h0, l0);
                    cvt_split(v.y, h1, l1);
                    long o = (long)m * ldS + n;
                    Chi[o] = h0; Chi[o + 1] = h1;
                    Clo[o] = l0; Clo[o + 1] = l1;
                }
            }
        }
    }

    // ---- fused transposed split + row/col partial sums (E only) ----
    if (Th) {
        __syncthreads();                       // pipeline smem reuse
        float* ts = (float*)smraw;             // [128][129] padded
        #pragma unroll
        for (int mf = 0; mf < 2; mf++) {
            #pragma unroll
            for (int h2 = 0; h2 < 2; h2++) {
                int ml = wm * 32 + mf * 16 + h2 * 8 + tg;
                #pragma unroll
                for (int nfj = 0; nfj < 8; nfj++) {
                    int nl = wn * 64 + nfj * 8 + tn;
                    ts[(nl + 0) * 129 + ml] = acc[mf][nfj][h2 * 2 + 0];
                    ts[(nl + 1) * 129 + ml] = acc[mf][nfj][h2 * 2 + 1];
                }
            }
        }
        __syncthreads();
        if (tid < 128) {
            float s = 0.f, s2 = 0.f;
            #pragma unroll 8
            for (int n = 0; n < 128; n++) s += ts[n * 129 + tid];
            #pragma unroll 8
            for (int m = 0; m < 128; m++) s2 += ts[tid * 129 + m];
            rowpart[(long)blockIdx.x * M + m0 + tid] = s;   // partial over this n-tile
            colpart[(long)blockIdx.y * N + n0 + tid] = s2;  // partial over this m-tile
        }
        for (int idx = tid; idx < 16384; idx += 256) {
            int n = idx >> 7, m = idx & 127;
            __nv_bfloat16 hi, lo;
            cvt_split(ts[n * 129 + m], hi, lo);
            long o = (long)(n0 + n) * ldT + m0 + m;
            Th[o] = hi; Tl[o] = lo;
        }
    }
}

static const int BGEMM_SMEM = 2 * 40960;

// ---------------- transpose + split ------------------------------------------
__global__ void transpose_split_kernel(const float* __restrict__ src, int R, int C,
                                       __nv_bfloat16* __restrict__ dh,
                                       __nv_bfloat16* __restrict__ dl, int dR) {
    __shared__ float tile[32][33];
    int c0 = blockIdx.x * 32, r0 = blockIdx.y * 32;
    int x = threadIdx.x, y = threadIdx.y;
    #pragma unroll
    for (int i = y; i < 32; i += 8) {
        int r = r0 + i, c = c0 + x;
        tile[i][x] = (r < R && c < C) ? src[(long)r * C + c] : 0.f;
    }
    __syncthreads();
    #pragma unroll
    for (int i = y; i < 32; i += 8) {
        int dr = c0 + i, dc = r0 + x;
        if (dr < dR && dc < R) {
            __nv_bfloat16 hi, lo;
            cvt_split(tile[x][i], hi, lo);
            dh[(long)dr * R + dc] = hi;
            dl[(long)dr * R + dc] = lo;
        }
    }
}

// ---------------- split with K padding ----------------------------------------
__global__ void split_pad_kernel(const float* __restrict__ src, int M, int K, int Kpad,
                                 __nv_bfloat16* __restrict__ dh,
                                 __nv_bfloat16* __restrict__ dl) {
    long i = (long)blockIdx.x * blockDim.x + threadIdx.x;
    long total = (long)M * Kpad;
    if (i >= total) return;
    int m = (int)(i / Kpad), k = (int)(i % Kpad);
    float v = (k < K) ? src[(long)m * K + k] : 0.f;
    __nv_bfloat16 hi, lo;
    cvt_split(v, hi, lo);
    dh[i] = hi; dl[i] = lo;
}

// ---------------- concat + split ----------------------------------------------
__global__ void concat_split_kernel(const float* __restrict__ a,
                                    const float* __restrict__ b,
                                    int n, int da, int db, int Kpad,
                                    __nv_bfloat16* __restrict__ dh,
                                    __nv_bfloat16* __restrict__ dl) {
    long i = (long)blockIdx.x * blockDim.x + threadIdx.x;
    long total = (long)n * Kpad;
    if (i >= total) return;
    int r = (int)(i / Kpad), c = (int)(i % Kpad);
    float v = 0.f;
    if (c < da) v = a[(long)r * da + c];
    else if (c < da + db) v = b[(long)r * db + (c - da)];
    __nv_bfloat16 hi, lo;
    cvt_split(v, hi, lo);
    dh[i] = hi; dl[i] = lo;
}

// ---------------- gather -----------------------------------------------------
__global__ void gather_kernel(const float* __restrict__ emb,
                              const int* __restrict__ idx,
                              float* __restrict__ out, int d) {
    int r = blockIdx.x;
    long src = idx[r];
    const float* s = emb + src * (long)d;
    float* o = out + (long)r * d;
    for (int c = threadIdx.x; c < d; c += blockDim.x) o[c] = s[c];
}

// ---------------- split-K reduce with per-row divide --------------------------
__global__ void splitk_reduce_kernel(const float* __restrict__ part,
                                     const float* __restrict__ rowdiv,
                                     float* __restrict__ C, long ldc,
                                     int M, int N, int S) {
    long i = (long)blockIdx.x * blockDim.x + threadIdx.x;
    long total = (long)M * N;
    if (i >= total) return;
    int m = (int)(i / N), n = (int)(i % N);
    float s = 0.f;
    for (int p = 0; p < S; p++) s += part[(long)p * total + i];
    C[(long)m * ldc + n] = s / rowdiv[m];
}

// ---------------- column sums (two-stage, deterministic) ----------------------
__global__ void colsum_part_kernel(const float* __restrict__ A,
                                   float* __restrict__ part,
                                   int R, int C, int rows_per) {
    int c = blockIdx.x * blockDim.x + threadIdx.x;
    if (c >= C) return;
    int r0 = blockIdx.y * rows_per;
    int r1 = min(r0 + rows_per, R);
    float s = 0.f;
    for (int r = r0; r < r1; r++) s += A[(long)r * C + c];
    part[(long)blockIdx.y * C + c] = s;
}

__global__ void colsum_reduce_kernel(const float* __restrict__ part,
                                     float* __restrict__ out, int C, int P) {
    int c = blockIdx.x * blockDim.x + threadIdx.x;
    if (c >= C) return;
    float s = 0.f;
    for (int p = 0; p < P; p++) s += part[(long)p * C + c];
    out[c] = s;
}

// ---------------- final MLP head + softmax -------------------------------------
__global__ void head_kernel(const float* __restrict__ v,
                            const float* __restrict__ Wg1, const float* __restrict__ bg1,
                            const float* __restrict__ Wg2, const float* __restrict__ bg2,
                            const float* __restrict__ Wg3, const float* __restrict__ bg3,
                            float* __restrict__ y) {
    __shared__ float sv[2 * HN];
    __shared__ float y1[HN];
    __shared__ float y2[HN];
    __shared__ float logit[3];
    int t = threadIdx.x;
    sv[t] = v[t];
    sv[t + HN] = v[t + HN];
    __syncthreads();
    {
        float acc = bg1[t];
        const float* w = Wg1 + (long)t * (2 * HN);
        for (int k = 0; k < 2 * HN; k++) acc += sv[k] * w[k];
        y1[t] = fmaxf(acc, 0.f);
    }
    __syncthreads();
    {
        float acc = bg2[t];
        const float* w = Wg2 + (long)t * HN;
        for (int k = 0; k < HN; k++) acc += y1[k] * w[k];
        y2[t] = fmaxf(acc, 0.f);
    }
    __syncthreads();
    if (t < 3) {
        float a = bg3[t];
        const float* w = Wg3 + (long)t * HN;
        for (int k = 0; k < HN; k++) a += y2[k] * w[k];
        logit[t] = a;
    }
    __syncthreads();
    if (t == 0) {
        float m = fmaxf(logit[0], fmaxf(logit[1], logit[2]));
        float e0 = expf(logit[0] - m), e1 = expf(logit[1] - m), e2 = expf(logit[2] - m);
        float s = e0 + e1 + e2;
        y[0] = e0 / s; y[1] = e1 / s; y[2] = e2 / s;
    }
}

// ---------------- host dispatch -----------------------------------------------
struct BArgs {
    const __nv_bfloat16 *Ah, *Al; long ldA;
    const __nv_bfloat16 *Bh, *Bl; long ldB;
    const __nv_bfloat16 *A2h = nullptr, *A2l = nullptr, *B2h = nullptr, *B2l = nullptr;
    const float* bias = nullptr;
    float* C = nullptr; long ldc = 0; long sliceStride = 0;
    __nv_bfloat16 *Chi = nullptr, *Clo = nullptr; long ldS = 0;
    __nv_bfloat16 *Th = nullptr, *Tl = nullptr; long ldT = 0;
    float *rowpart = nullptr, *colpart = nullptr;
    int M, N, K, splits = 1, zTotal = 0, relu = 0;
};

static void launch_bgemm(const BArgs& a) {
    cudaFuncSetAttribute(bgemm, cudaFuncAttributeMaxDynamicSharedMemorySize, BGEMM_SMEM);
    int kps = (a.K + a.splits - 1) / a.splits;
    kps = ((kps + 31) / 32) * 32;
    int zt = a.zTotal ? a.zTotal : a.splits;
    dim3 grid((a.N + 127) / 128, a.M / 128, zt);
    bgemm<<<grid, 256, BGEMM_SMEM>>>(a.Ah, a.Al, a.ldA, a.Bh, a.Bl, a.ldB,
                                     a.A2h, a.A2l, a.B2h, a.B2l, a.splits,
                                     a.bias, a.C, a.ldc, a.sliceStride,
                                     a.Chi, a.Clo, a.ldS, a.Th, a.Tl, a.ldT,
                                     a.rowpart, a.colpart,
                                     a.M, a.N, a.K, kps, a.relu);
}

#define GETSYM(var, sym) cudaGetSymbolAddress((void**)&var, sym)

extern "C" void kernel_launch(void* const* d_in, const int* in_sizes, int n_in,
                              void* d_out, int out_size) {
    const int*   p_idx = (const int*)  d_in[0];
    const int*   h_idx = (const int*)  d_in[1];
    const float* emb   = (const float*)d_in[2];
    const float* W_a1  = (const float*)d_in[3];
    const float* b_a1  = (const float*)d_in[4];
    const float* W_a2  = (const float*)d_in[5];
    const float* b_a2  = (const float*)d_in[6];
    const float* W_c1  = (const float*)d_in[7];
    const float* b_c1  = (const float*)d_in[8];
    const float* W_c2  = (const float*)d_in[9];
    const float* b_c2  = (const float*)d_in[10];
    const float* W_g1  = (const float*)d_in[11];
    const float* b_g1  = (const float*)d_in[12];
    const float* W_g2  = (const float*)d_in[13];
    const float* b_g2  = (const float*)d_in[14];
    const float* W_g3  = (const float*)d_in[15];
    const float* b_g3  = (const float*)d_in[16];

    float* out = (float*)d_out;
    const long E_OFF    = 0;
    const long BETA_OFF = (long)LPN * LHN;
    const long ALPHA_OFF= BETA_OFF + (long)LPN * DN;
    const long V1_OFF   = ALPHA_OFF + (long)LHN * DN;
    const long V2_OFF   = V1_OFF + HN;
    const long Y_OFF    = V2_OFF + HN;

    float *emb2, *f2, *u, *eik, *ekj, *part, *part2, *split;
    GETSYM(emb2, g_emb2); GETSYM(f2, g_f2); GETSYM(u, g_u);
    GETSYM(eik, g_eik); GETSYM(ekj, g_ekj);
    GETSYM(part, g_part); GETSYM(part2, g_part2); GETSYM(split, g_split);

    __nv_bfloat16 *emb2s_h, *emb2s_l, *ths_h, *ths_l, *fps_h, *fps_l;
    __nv_bfloat16 *fhTs_h, *fhTs_l, *Es_h, *Es_l, *ETs_h, *ETs_l;
    __nv_bfloat16 *hTs_h, *hTs_l, *pTs_h, *pTs_l, *xs_h, *xs_l;
    __nv_bfloat16 *Wa1s_h, *Wa1s_l, *Wa2s_h, *Wa2s_l, *Wc1s_h, *Wc1s_l, *Wc2s_h, *Wc2s_l;
    GETSYM(emb2s_h, g_emb2s_h); GETSYM(emb2s_l, g_emb2s_l);
    GETSYM(ths_h, g_ths_h);     GETSYM(ths_l, g_ths_l);
    GETSYM(fps_h, g_fps_h);     GETSYM(fps_l, g_fps_l);
    GETSYM(fhTs_h, g_fhTs_h);   GETSYM(fhTs_l, g_fhTs_l);
    GETSYM(Es_h, g_Es_h);       GETSYM(Es_l, g_Es_l);
    GETSYM(ETs_h, g_ETs_h);     GETSYM(ETs_l, g_ETs_l);
    GETSYM(hTs_h, g_hTs_h);     GETSYM(hTs_l, g_hTs_l);
    GETSYM(pTs_h, g_pTs_h);     GETSYM(pTs_l, g_pTs_l);
    GETSYM(xs_h, g_xs_h);       GETSYM(xs_l, g_xs_l);
    GETSYM(Wa1s_h, g_Wa1s_h);   GETSYM(Wa1s_l, g_Wa1s_l);
    GETSYM(Wa2s_h, g_Wa2s_h);   GETSYM(Wa2s_l, g_Wa2s_l);
    GETSYM(Wc1s_h, g_Wc1s_h);   GETSYM(Wc1s_l, g_Wc1s_l);
    GETSYM(Wc2s_h, g_Wc2s_h);   GETSYM(Wc2s_l, g_Wc2s_l);

    // 0) weight splits
    split_pad_kernel<<<(HN * DP + 255) / 256, 256>>>(W_a1, HN, DN, DP, Wa1s_h, Wa1s_l);
    split_pad_kernel<<<(HN * HN + 255) / 256, 256>>>(W_a2, HN, HN, HN, Wa2s_h, Wa2s_l);
    split_pad_kernel<<<(HN * D2P + 255) / 256, 256>>>(W_c1, HN, 2 * DN, D2P, Wc1s_h, Wc1s_l);
    split_pad_kernel<<<(HN * HN + 255) / 256, 256>>>(W_c2, HN, HN, HN, Wc2s_h, Wc2s_l);

    // 1) gathers (p | h stacked) + split
    gather_kernel<<<LPN, 128>>>(emb, p_idx, emb2, DN);
    gather_kernel<<<LHN, 128>>>(emb, h_idx, emb2 + (long)LPN * DN, DN);
    split_pad_kernel<<<(int)(((long)M2 * DP + 255) / 256), 256>>>(
        emb2, M2, DN, DP, emb2s_h, emb2s_l);

    // 2) attend (batched p+h): t = relu(emb@Wa1^T+b); f = relu(t@Wa2^T+b)
    {
        BArgs a{emb2s_h, emb2s_l, DP, Wa1s_h, Wa1s_l, DP};
        a.bias = b_a1; a.Chi = ths_h; a.Clo = ths_l; a.ldS = HN;
        a.M = M2; a.N = HN; a.K = DP; a.relu = 1;
        launch_bgemm(a);
    }
    {
        BArgs a{ths_h, ths_l, HN, Wa2s_h, Wa2s_l, HN};
        a.bias = b_a2; a.C = f2; a.ldc = HN;
        a.Chi = fps_h; a.Clo = fps_l; a.ldS = HN;
        a.M = M2; a.N = HN; a.K = HN; a.relu = 1;
        launch_bgemm(a);
    }

    // 3) fhT = transpose(reshape(fh,[H,LH])) (fh = f2 rows 4096..8191)
    {
        dim3 g((LHN + 31) / 32, (HN + 31) / 32), b(32, 8);
        transpose_split_kernel<<<g, b>>>(f2 + (long)LPN * HN, HN, LHN, fhTs_h, fhTs_l, LHN);
    }

    // 4) E = fp @ reshape(fh) with fused split + transposed split + row/col partials
    {
        BArgs a{fps_h, fps_l, HN, fhTs_h, fhTs_l, HN};
        a.C = out + E_OFF; a.ldc = LHN;
        a.Chi = Es_h; a.Clo = Es_l; a.ldS = LHN;
        a.Th = ETs_h; a.Tl = ETs_l; a.ldT = LHN;
        a.rowpart = part; a.colpart = part2;
        a.M = LPN; a.N = LHN; a.K = HN;
        launch_bgemm(a);
    }
    colsum_reduce_kernel<<<(LPN + 255) / 256, 256>>>(part,  eik, LPN, 32);
    colsum_reduce_kernel<<<(LHN + 255) / 256, 256>>>(part2, ekj, LHN, 32);

    // 5) transposes of embeddings for beta/alpha B-operands
    {
        dim3 b(32, 8);
        dim3 gh((NROWS_PAD + 31) / 32, (LHN + 31) / 32);
        transpose_split_kernel<<<gh, b>>>(emb2 + (long)LPN * DN, LHN, DN, hTs_h, hTs_l, NROWS_PAD);
        dim3 gp((NROWS_PAD + 31) / 32, (LPN + 31) / 32);
        transpose_split_kernel<<<gp, b>>>(emb2, LPN, DN, pTs_h, pTs_l, NROWS_PAD);
    }

    // 6) beta & alpha in ONE launch: z{0,1}=E@hT slices, z{2,3}=ET@pT slices
    {
        BArgs a{Es_h, Es_l, LHN, hTs_h, hTs_l, LHN};
        a.A2h = ETs_h; a.A2l = ETs_l; a.B2h = pTs_h; a.B2l = pTs_l;
        a.C = split; a.ldc = DN; a.sliceStride = (long)LPN * DN;
        a.M = LPN; a.N = DN; a.K = LHN; a.splits = 2; a.zTotal = 4;
        launch_bgemm(a);
    }
    splitk_reduce_kernel<<<(int)(((long)LPN * DN + 255) / 256), 256>>>(
        split, eik, out + BETA_OFF, DN, LPN, DN, 2);
    splitk_reduce_kernel<<<(int)(((long)LHN * DN + 255) / 256), 256>>>(
        split + 2 * (long)LPN * DN, ekj, out + ALPHA_OFF, DN, LHN, DN, 2);

    // 7) comp (batched): x = [emb2 | beta,alpha]; u = relu(relu(x@Wc1^T+b)@Wc2^T+b)
    concat_split_kernel<<<(int)(((long)M2 * D2P + 255) / 256), 256>>>(
        emb2, out + BETA_OFF, M2, DN, DN, D2P, xs_h, xs_l);
    {
        BArgs a{xs_h, xs_l, D2P, Wc1s_h, Wc1s_l, D2P};
        a.bias = b_c1; a.Chi = ths_h; a.Clo = ths_l; a.ldS = HN;
        a.M = M2; a.N = HN; a.K = D2P; a.relu = 1;
        launch_bgemm(a);
    }
    {
        BArgs a{ths_h, ths_l, HN, Wc2s_h, Wc2s_l, HN};
        a.bias = b_c2; a.C = u; a.ldc = HN;
        a.M = M2; a.N = HN; a.K = HN; a.relu = 1;
        launch_bgemm(a);
    }

    // 8) v1 / v2 column sums
    {
        dim3 g((HN + 255) / 256, 8);
        colsum_part_kernel<<<g, 256>>>(u, part, LPN, HN, 512);
        colsum_reduce_kernel<<<(HN + 255) / 256, 256>>>(part, out + V1_OFF, HN, 8);
        colsum_part_kernel<<<g, 256>>>(u + (long)LPN * HN, part, LHN, HN, 512);
        colsum_reduce_kernel<<<(HN + 255) / 256, 256>>>(part, out + V2_OFF, HN, 8);
    }

    // 9) head
    head_kernel<<<1, HN>>>(out + V1_OFF, W_g1, b_g1, W_g2, b_g2, W_g3, b_g3, out + Y_OFF);

    (void)in_sizes; (void)n_in; (void)out_size;
}

// round 7
// speedup vs baseline: 2.0372x; 1.0248x over previous
#include <cuda_runtime.h>
#include <cuda_bf16.h>
#include <cstdint>
#include <cmath>

#define LPN 4096
#define LHN 4096
#define DN  300
#define HN  512
#define DP  320          // DN padded to 32
#define D2P 608          // 2*DN padded to 32
#define NROWS_PAD 384    // DN padded to 128
#define M2  8192         // batched p+h rows

// ---------------- scratch (static device globals) ---------------------------
__device__ float g_emb2[M2 * DN];          // [p rows | h rows]
__device__ float g_f2  [M2 * HN];          // fp | fh (fp32)
__device__ float g_eik [LPN];
__device__ float g_ekj [LHN];
__device__ float g_part [32 * 4096];
__device__ float g_part2[32 * 4096];
__device__ float g_split[4 * LPN * DN];    // 4 split-K slices (beta x2, alpha x2)

__device__ __nv_bfloat16 g_emb2s_h[M2 * DP],  g_emb2s_l[M2 * DP];
__device__ __nv_bfloat16 g_ths_h [M2 * HN],   g_ths_l [M2 * HN];
__device__ __nv_bfloat16 g_fps_h [M2 * HN],   g_fps_l [M2 * HN];
__device__ __nv_bfloat16 g_fhTs_h[LHN * HN],  g_fhTs_l[LHN * HN];
__device__ __nv_bfloat16 g_Es_h [(long)LPN * LHN], g_Es_l [(long)LPN * LHN];
__device__ __nv_bfloat16 g_ETs_h[(long)LPN * LHN], g_ETs_l[(long)LPN * LHN];
__device__ __nv_bfloat16 g_hTs_h[NROWS_PAD * LHN], g_hTs_l[NROWS_PAD * LHN];
__device__ __nv_bfloat16 g_pTs_h[NROWS_PAD * LPN], g_pTs_l[NROWS_PAD * LPN];
__device__ __nv_bfloat16 g_xs_h [M2 * D2P],   g_xs_l [M2 * D2P];
__device__ __nv_bfloat16 g_Wa1s_h[HN * DP],   g_Wa1s_l[HN * DP];
__device__ __nv_bfloat16 g_Wa2s_h[HN * HN],   g_Wa2s_l[HN * HN];
__device__ __nv_bfloat16 g_Wc1s_h[HN * D2P],  g_Wc1s_l[HN * D2P];
__device__ __nv_bfloat16 g_Wc2s_h[HN * HN],   g_Wc2s_l[HN * HN];

// ---------------- PTX helpers ------------------------------------------------
__device__ __forceinline__ uint32_t smem_u32(const void* p) {
    uint32_t a;
    asm("{ .reg .u64 t; cvta.to.shared.u64 t, %1; cvt.u32.u64 %0, t; }" : "=r"(a) : "l"(p));
    return a;
}
__device__ __forceinline__ void ldsm4(uint32_t& r0, uint32_t& r1, uint32_t& r2,
                                      uint32_t& r3, uint32_t addr) {
    asm volatile("ldmatrix.sync.aligned.m8n8.x4.shared.b16 {%0,%1,%2,%3}, [%4];"
                 : "=r"(r0), "=r"(r1), "=r"(r2), "=r"(r3) : "r"(addr));
}
__device__ __forceinline__ void mma16816(float* c, const uint32_t* a,
                                         const uint32_t b0, const uint32_t b1) {
    asm volatile(
        "mma.sync.aligned.m16n8k16.row.col.f32.bf16.bf16.f32 "
        "{%0,%1,%2,%3}, {%4,%5,%6,%7}, {%8,%9}, {%0,%1,%2,%3};"
        : "+f"(c[0]), "+f"(c[1]), "+f"(c[2]), "+f"(c[3])
        : "r"(a[0]), "r"(a[1]), "r"(a[2]), "r"(a[3]), "r"(b0), "r"(b1));
}
__device__ __forceinline__ void cvt_split(float x, __nv_bfloat16& hi, __nv_bfloat16& lo) {
    hi = __float2bfloat16(x);
    lo = __float2bfloat16(x - __bfloat162float(hi));
}
__device__ __forceinline__ void cp16(uint32_t dst, const void* src) {
    asm volatile("cp.async.cg.shared.global [%0], [%1], 16;"
                 :: "r"(dst), "l"(__cvta_generic_to_global(src)));
}
__device__ __forceinline__ void cp_commit() {
    asm volatile("cp.async.commit_group;");
}
template <int NN> __device__ __forceinline__ void cp_wait() {
    asm volatile("cp.async.wait_group %0;" :: "n"(NN));
}

// ---------------- bf16x3 mma.sync SGEMM -------------------------------------
// C[m,n] = epi( sum_k A(m,k)*B(n,k) ), operands pre-split bf16 hi/lo K-contig.
// Dual-problem via blockIdx.z >= zSecond. Optional fused outputs: Chi/Clo split
// of C; Th/Tl transposed split; rowpart/colpart per-CTA partial sums.
__global__ __launch_bounds__(256, 2)
void bgemm(const __nv_bfloat16* __restrict__ Agh, const __nv_bfloat16* __restrict__ Agl, long ldA,
           const __nv_bfloat16* __restrict__ Bgh, const __nv_bfloat16* __restrict__ Bgl, long ldB,
           const __nv_bfloat16* __restrict__ A2gh, const __nv_bfloat16* __restrict__ A2gl,
           const __nv_bfloat16* __restrict__ B2gh, const __nv_bfloat16* __restrict__ B2gl,
           int zSecond,
           const float* __restrict__ bias,
           float* __restrict__ C, long ldc, long sliceStride,
           __nv_bfloat16* __restrict__ Chi, __nv_bfloat16* __restrict__ Clo, long ldS,
           __nv_bfloat16* __restrict__ Th, __nv_bfloat16* __restrict__ Tl, long ldT,
           float* __restrict__ rowpart, float* __restrict__ colpart,
           int M, int N, int K, int kPerSlice, int relu) {
    extern __shared__ __align__(16) char smraw[];
    const int tid = threadIdx.x, lane = tid & 31, wid = tid >> 5;
    const int wm = wid >> 1, wn = wid & 1;
    const int m0 = blockIdx.y * 128, n0 = blockIdx.x * 128;
    const int zz = blockIdx.z;
    if (A2gh && zz >= zSecond) { Agh = A2gh; Agl = A2gl; Bgh = B2gh; Bgl = B2gl; }
    const int kbeg = (zz % zSecond) * kPerSlice;
    const int kend = min(K, kbeg + kPerSlice);
    const int nch = (kend - kbeg) >> 5;
    C += (long)zz * sliceStride;

    const uint32_t sb = smem_u32(smraw);

    float acc[2][8][4];
    #pragma unroll
    for (int i = 0; i < 2; i++)
        #pragma unroll
        for (int j = 0; j < 8; j++)
            #pragma unroll
            for (int e = 0; e < 4; e++) acc[i][j][e] = 0.f;

    const int lrow = (((lane >> 3) & 1) << 3) + (lane & 7);
    const int lcol = (lane >> 4) << 4;

    auto load_stage = [&](int st, int k0) {
        uint32_t sbase = sb + st * 40960;
        #pragma unroll
        for (int i = 0; i < 2; i++) {
            int c = tid + i * 256;
            int r = c >> 2, kq = c & 3;
            uint32_t dso = (uint32_t)(r * 80 + kq * 16);
            long ao = (long)(m0 + r) * ldA + k0 + kq * 8;
            long bo = (long)(n0 + r) * ldB + k0 + kq * 8;
            cp16(sbase + dso,          Agh + ao);
            cp16(sbase + 10240 + dso,  Agl + ao);
            cp16(sbase + 20480 + dso,  Bgh + bo);
            cp16(sbase + 30720 + dso,  Bgl + bo);
        }
    };

    load_stage(0, kbeg);
    cp_commit();

    for (int i = 0; i < nch; i++) {
        if (i + 1 < nch) {
            load_stage((i + 1) & 1, kbeg + (i + 1) * 32);
            cp_commit();
            cp_wait<1>();
        } else {
            cp_wait<0>();
        }
        __syncthreads();

        const uint32_t aAh = sb + (i & 1) * 40960;
        const uint32_t aAl = aAh + 10240;
        const uint32_t aBh = aAh + 20480;
        const uint32_t aBl = aAh + 30720;

        #pragma unroll
        for (int s = 0; s < 2; s++) {
            const int sbyte = s * 32;
            uint32_t ah[2][4], al[2][4], bh[4][4];
            #pragma unroll
            for (int mf = 0; mf < 2; mf++) {
                int row = wm * 32 + mf * 16 + lrow;
                ldsm4(ah[mf][0], ah[mf][1], ah[mf][2], ah[mf][3],
                      aAh + row * 80 + lcol + sbyte);
                ldsm4(al[mf][0], al[mf][1], al[mf][2], al[mf][3],
                      aAl + row * 80 + lcol + sbyte);
            }
            #pragma unroll
            for (int nf = 0; nf < 4; nf++) {
                int row = wn * 64 + nf * 16 + lrow;
                ldsm4(bh[nf][0], bh[nf][1], bh[nf][2], bh[nf][3],
                      aBh + row * 80 + lcol + sbyte);
            }
            // pass 1: hi*hi — 16 independent accumulators
            #pragma unroll
            for (int nf = 0; nf < 4; nf++)
                #pragma unroll
                for (int j = 0; j < 2; j++)
                    #pragma unroll
                    for (int mf = 0; mf < 2; mf++)
                        mma16816(acc[mf][nf * 2 + j], ah[mf], bh[nf][j], bh[nf][j + 2]);
            // pass 2: lo*hi — 16 independent accumulators
            #pragma unroll
            for (int nf = 0; nf < 4; nf++)
                #pragma unroll
                for (int j = 0; j < 2; j++)
                    #pragma unroll
                    for (int mf = 0; mf < 2; mf++)
                        mma16816(acc[mf][nf * 2 + j], al[mf], bh[nf][j], bh[nf][j + 2]);
            // pass 3: hi*lo — bl loaded inline, 4-way ILP per nf
            #pragma unroll
            for (int nf = 0; nf < 4; nf++) {
                int row = wn * 64 + nf * 16 + lrow;
                uint32_t bl[4];
                ldsm4(bl[0], bl[1], bl[2], bl[3], aBl + row * 80 + lcol + sbyte);
                #pragma unroll
                for (int j = 0; j < 2; j++)
                    #pragma unroll
                    for (int mf = 0; mf < 2; mf++)
                        mma16816(acc[mf][nf * 2 + j], ah[mf], bl[j], bl[j + 2]);
            }
        }
        __syncthreads();
    }

    // ---- epilogue: apply bias/relu in-place ----
    const int tg = lane >> 2;
    const int tn = (lane & 3) << 1;
    if (bias || relu) {
        #pragma unroll
        for (int mf = 0; mf < 2; mf++)
            #pragma unroll
            for (int nfj = 0; nfj < 8; nfj++) {
                int n = n0 + (wn * 64 + nfj * 8 + tn);
                #pragma unroll
                for (int h2 = 0; h2 < 2; h2++) {
                    float vx = acc[mf][nfj][h2 * 2 + 0];
                    float vy = acc[mf][nfj][h2 * 2 + 1];
                    if (bias && n < N) { vx += bias[n]; vy += bias[n + 1]; }
                    if (relu) { vx = fmaxf(vx, 0.f); vy = fmaxf(vy, 0.f); }
                    acc[mf][nfj][h2 * 2 + 0] = vx;
                    acc[mf][nfj][h2 * 2 + 1] = vy;
                }
            }
    }

    // ---- direct writes ----
    if (C || Chi) {
        #pragma unroll
        for (int mf = 0; mf < 2; mf++) {
            #pragma unroll
            for (int h2 = 0; h2 < 2; h2++) {
                int m = m0 + wm * 32 + mf * 16 + h2 * 8 + tg;
                #pragma unroll
                for (int nfj = 0; nfj < 8; nfj++) {
                    int n = n0 + wn * 64 + nfj * 8 + tn;
                    if (n >= N) continue;
                    float2 v;
                    v.x = acc[mf][nfj][h2 * 2 + 0];
                    v.y = acc[mf][nfj][h2 * 2 + 1];
                    if (C) *(float2*)(C + (long)m * ldc + n) = v;
                    if (Chi) {
                        __nv_bfloat16 h0, l0, h1, l1;
                        cvt_split(v.x, h0, l0);
                        cvt_split(v.y, h1, l1);
                        long o = (long)m * ldS + n;
                        Chi[o] = h0; Chi[o + 1] = h1;
                        Clo[o] = l0; Clo[o + 1] = l1;
                    }
                }
            }
        }
    }

    // ---- fused staging: transposed split and/or row+col partial sums ----
    if (Th || rowpart || colpart) {
        __syncthreads();
        float* ts = (float*)smraw;             // [128][129] padded
        #pragma unroll
        for (int mf = 0; mf < 2; mf++) {
            #pragma unroll
            for (int h2 = 0; h2 < 2; h2++) {
                int ml = wm * 32 + mf * 16 + h2 * 8 + tg;
                #pragma unroll
                for (int nfj = 0; nfj < 8; nfj++) {
                    int nl = wn * 64 + nfj * 8 + tn;
                    ts[(nl + 0) * 129 + ml] = acc[mf][nfj][h2 * 2 + 0];
                    ts[(nl + 1) * 129 + ml] = acc[mf][nfj][h2 * 2 + 1];
                }
            }
        }
        __syncthreads();
        if (tid < 128) {
            if (rowpart) {
                float s = 0.f;
                #pragma unroll 8
                for (int n = 0; n < 128; n++) s += ts[n * 129 + tid];
                rowpart[(long)blockIdx.x * M + m0 + tid] = s;
            }
            if (colpart) {
                float s2 = 0.f;
                #pragma unroll 8
                for (int m = 0; m < 128; m++) s2 += ts[tid * 129 + m];
                colpart[(long)blockIdx.y * N + n0 + tid] = s2;
            }
        }
        if (Th) {
            for (int idx = tid; idx < 16384; idx += 256) {
                int n = idx >> 7, m = idx & 127;
                __nv_bfloat16 hi, lo;
                cvt_split(ts[n * 129 + m], hi, lo);
                long o = (long)(n0 + n) * ldT + m0 + m;
                Th[o] = hi; Tl[o] = lo;
            }
        }
    }
}

static const int BGEMM_SMEM = 2 * 40960;

// ---------------- transpose + split ------------------------------------------
__global__ void transpose_split_kernel(const float* __restrict__ src, int R, int C,
                                       __nv_bfloat16* __restrict__ dh,
                                       __nv_bfloat16* __restrict__ dl, int dR) {
    __shared__ float tile[32][33];
    int c0 = blockIdx.x * 32, r0 = blockIdx.y * 32;
    int x = threadIdx.x, y = threadIdx.y;
    #pragma unroll
    for (int i = y; i < 32; i += 8) {
        int r = r0 + i, c = c0 + x;
        tile[i][x] = (r < R && c < C) ? src[(long)r * C + c] : 0.f;
    }
    __syncthreads();
    #pragma unroll
    for (int i = y; i < 32; i += 8) {
        int dr = c0 + i, dc = r0 + x;
        if (dr < dR && dc < R) {
            __nv_bfloat16 hi, lo;
            cvt_split(tile[x][i], hi, lo);
            dh[(long)dr * R + dc] = hi;
            dl[(long)dr * R + dc] = lo;
        }
    }
}

// ---------------- split with K padding ----------------------------------------
__global__ void split_pad_kernel(const float* __restrict__ src, int M, int K, int Kpad,
                                 __nv_bfloat16* __restrict__ dh,
                                 __nv_bfloat16* __restrict__ dl) {
    long i = (long)blockIdx.x * blockDim.x + threadIdx.x;
    long total = (long)M * Kpad;
    if (i >= total) return;
    int m = (int)(i / Kpad), k = (int)(i % Kpad);
    float v = (k < K) ? src[(long)m * K + k] : 0.f;
    __nv_bfloat16 hi, lo;
    cvt_split(v, hi, lo);
    dh[i] = hi; dl[i] = lo;
}

// ---------------- xs fill: cols [0,DN) from emb2, [2DN,D2P) zero ---------------
__global__ void xs_fill_kernel(const float* __restrict__ emb2,
                               __nv_bfloat16* __restrict__ dh,
                               __nv_bfloat16* __restrict__ dl) {
    long i = (long)blockIdx.x * blockDim.x + threadIdx.x;
    long total = (long)M2 * D2P;
    if (i >= total) return;
    int r = (int)(i / D2P), c = (int)(i % D2P);
    if (c >= DN && c < 2 * DN) return;     // filled by splitk_concat
    float v = (c < DN) ? emb2[(long)r * DN + c] : 0.f;
    __nv_bfloat16 hi, lo;
    cvt_split(v, hi, lo);
    dh[i] = hi; dl[i] = lo;
}

// ---------------- gather -----------------------------------------------------
__global__ void gather_kernel(const float* __restrict__ emb,
                              const int* __restrict__ idx,
                              float* __restrict__ out, int d) {
    int r = blockIdx.x;
    long src = idx[r];
    const float* s = emb + src * (long)d;
    float* o = out + (long)r * d;
    for (int c = threadIdx.x; c < d; c += blockDim.x) o[c] = s[c];
}

// ---------------- split-K reduce + rowdiv + fused concat-split ----------------
__global__ void splitk_concat_kernel(const float* __restrict__ part,
                                     const float* __restrict__ rowdiv,
                                     float* __restrict__ C,
                                     __nv_bfloat16* __restrict__ xh,
                                     __nv_bfloat16* __restrict__ xl,
                                     long xRowOff, int M, int N, int S) {
    long i = (long)blockIdx.x * blockDim.x + threadIdx.x;
    long total = (long)M * N;
    if (i >= total) return;
    int m = (int)(i / N), n = (int)(i % N);
    float s = 0.f;
    for (int p = 0; p < S; p++) s += part[(long)p * total + i];
    float v = s / rowdiv[m];
    C[(long)m * N + n] = v;
    __nv_bfloat16 hi, lo;
    cvt_split(v, hi, lo);
    long o = (xRowOff + m) * (long)D2P + DN + n;
    xh[o] = hi; xl[o] = lo;
}

// ---------------- column reduce ------------------------------------------------
__global__ void colsum_reduce_kernel(const float* __restrict__ part,
                                     float* __restrict__ out, int C, int P) {
    int c = blockIdx.x * blockDim.x + threadIdx.x;
    if (c >= C) return;
    float s = 0.f;
    for (int p = 0; p < P; p++) s += part[(long)p * C + c];
    out[c] = s;
}

// ---------------- final MLP head + softmax -------------------------------------
__global__ void head_kernel(const float* __restrict__ v,
                            const float* __restrict__ Wg1, const float* __restrict__ bg1,
                            const float* __restrict__ Wg2, const float* __restrict__ bg2,
                            const float* __restrict__ Wg3, const float* __restrict__ bg3,
                            float* __restrict__ y) {
    __shared__ float sv[2 * HN];
    __shared__ float y1[HN];
    __shared__ float y2[HN];
    __shared__ float logit[3];
    int t = threadIdx.x;
    sv[t] = v[t];
    sv[t + HN] = v[t + HN];
    __syncthreads();
    {
        float acc = bg1[t];
        const float* w = Wg1 + (long)t * (2 * HN);
        for (int k = 0; k < 2 * HN; k++) acc += sv[k] * w[k];
        y1[t] = fmaxf(acc, 0.f);
    }
    __syncthreads();
    {
        float acc = bg2[t];
        const float* w = Wg2 + (long)t * HN;
        for (int k = 0; k < HN; k++) acc += y1[k] * w[k];
        y2[t] = fmaxf(acc, 0.f);
    }
    __syncthreads();
    if (t < 3) {
        float a = bg3[t];
        const float* w = Wg3 + (long)t * HN;
        for (int k = 0; k < HN; k++) a += y2[k] * w[k];
        logit[t] = a;
    }
    __syncthreads();
    if (t == 0) {
        float m = fmaxf(logit[0], fmaxf(logit[1], logit[2]));
        float e0 = expf(logit[0] - m), e1 = expf(logit[1] - m), e2 = expf(logit[2] - m);
        float s = e0 + e1 + e2;
        y[0] = e0 / s; y[1] = e1 / s; y[2] = e2 / s;
    }
}

// ---------------- host dispatch -----------------------------------------------
struct BArgs {
    const __nv_bfloat16 *Ah, *Al; long ldA;
    const __nv_bfloat16 *Bh, *Bl; long ldB;
    const __nv_bfloat16 *A2h = nullptr, *A2l = nullptr, *B2h = nullptr, *B2l = nullptr;
    const float* bias = nullptr;
    float* C = nullptr; long ldc = 0; long sliceStride = 0;
    __nv_bfloat16 *Chi = nullptr, *Clo = nullptr; long ldS = 0;
    __nv_bfloat16 *Th = nullptr, *Tl = nullptr; long ldT = 0;
    float *rowpart = nullptr, *colpart = nullptr;
    int M, N, K, splits = 1, zTotal = 0, relu = 0;
};

static void launch_bgemm(const BArgs& a) {
    cudaFuncSetAttribute(bgemm, cudaFuncAttributeMaxDynamicSharedMemorySize, BGEMM_SMEM);
    int kps = (a.K + a.splits - 1) / a.splits;
    kps = ((kps + 31) / 32) * 32;
    int zt = a.zTotal ? a.zTotal : a.splits;
    dim3 grid((a.N + 127) / 128, a.M / 128, zt);
    bgemm<<<grid, 256, BGEMM_SMEM>>>(a.Ah, a.Al, a.ldA, a.Bh, a.Bl, a.ldB,
                                     a.A2h, a.A2l, a.B2h, a.B2l, a.splits,
                                     a.bias, a.C, a.ldc, a.sliceStride,
                                     a.Chi, a.Clo, a.ldS, a.Th, a.Tl, a.ldT,
                                     a.rowpart, a.colpart,
                                     a.M, a.N, a.K, kps, a.relu);
}

#define GETSYM(var, sym) cudaGetSymbolAddress((void**)&var, sym)

extern "C" void kernel_launch(void* const* d_in, const int* in_sizes, int n_in,
                              void* d_out, int out_size) {
    const int*   p_idx = (const int*)  d_in[0];
    const int*   h_idx = (const int*)  d_in[1];
    const float* emb   = (const float*)d_in[2];
    const float* W_a1  = (const float*)d_in[3];
    const float* b_a1  = (const float*)d_in[4];
    const float* W_a2  = (const float*)d_in[5];
    const float* b_a2  = (const float*)d_in[6];
    const float* W_c1  = (const float*)d_in[7];
    const float* b_c1  = (const float*)d_in[8];
    const float* W_c2  = (const float*)d_in[9];
    const float* b_c2  = (const float*)d_in[10];
    const float* W_g1  = (const float*)d_in[11];
    const float* b_g1  = (const float*)d_in[12];
    const float* W_g2  = (const float*)d_in[13];
    const float* b_g2  = (const float*)d_in[14];
    const float* W_g3  = (const float*)d_in[15];
    const float* b_g3  = (const float*)d_in[16];

    float* out = (float*)d_out;
    const long E_OFF    = 0;
    const long BETA_OFF = (long)LPN * LHN;
    const long ALPHA_OFF= BETA_OFF + (long)LPN * DN;
    const long V1_OFF   = ALPHA_OFF + (long)LHN * DN;
    const long V2_OFF   = V1_OFF + HN;
    const long Y_OFF    = V2_OFF + HN;

    float *emb2, *f2, *eik, *ekj, *part, *part2, *split;
    GETSYM(emb2, g_emb2); GETSYM(f2, g_f2);
    GETSYM(eik, g_eik); GETSYM(ekj, g_ekj);
    GETSYM(part, g_part); GETSYM(part2, g_part2); GETSYM(split, g_split);

    __nv_bfloat16 *emb2s_h, *emb2s_l, *ths_h, *ths_l, *fps_h, *fps_l;
    __nv_bfloat16 *fhTs_h, *fhTs_l, *Es_h, *Es_l, *ETs_h, *ETs_l;
    __nv_bfloat16 *hTs_h, *hTs_l, *pTs_h, *pTs_l, *xs_h, *xs_l;
    __nv_bfloat16 *Wa1s_h, *Wa1s_l, *Wa2s_h, *Wa2s_l, *Wc1s_h, *Wc1s_l, *Wc2s_h, *Wc2s_l;
    GETSYM(emb2s_h, g_emb2s_h); GETSYM(emb2s_l, g_emb2s_l);
    GETSYM(ths_h, g_ths_h);     GETSYM(ths_l, g_ths_l);
    GETSYM(fps_h, g_fps_h);     GETSYM(fps_l, g_fps_l);
    GETSYM(fhTs_h, g_fhTs_h);   GETSYM(fhTs_l, g_fhTs_l);
    GETSYM(Es_h, g_Es_h);       GETSYM(Es_l, g_Es_l);
    GETSYM(ETs_h, g_ETs_h);     GETSYM(ETs_l, g_ETs_l);
    GETSYM(hTs_h, g_hTs_h);     GETSYM(hTs_l, g_hTs_l);
    GETSYM(pTs_h, g_pTs_h);     GETSYM(pTs_l, g_pTs_l);
    GETSYM(xs_h, g_xs_h);       GETSYM(xs_l, g_xs_l);
    GETSYM(Wa1s_h, g_Wa1s_h);   GETSYM(Wa1s_l, g_Wa1s_l);
    GETSYM(Wa2s_h, g_Wa2s_h);   GETSYM(Wa2s_l, g_Wa2s_l);
    GETSYM(Wc1s_h, g_Wc1s_h);   GETSYM(Wc1s_l, g_Wc1s_l);
    GETSYM(Wc2s_h, g_Wc2s_h);   GETSYM(Wc2s_l, g_Wc2s_l);

    // 0) weight splits
    split_pad_kernel<<<(HN * DP + 255) / 256, 256>>>(W_a1, HN, DN, DP, Wa1s_h, Wa1s_l);
    split_pad_kernel<<<(HN * HN + 255) / 256, 256>>>(W_a2, HN, HN, HN, Wa2s_h, Wa2s_l);
    split_pad_kernel<<<(HN * D2P + 255) / 256, 256>>>(W_c1, HN, 2 * DN, D2P, Wc1s_h, Wc1s_l);
    split_pad_kernel<<<(HN * HN + 255) / 256, 256>>>(W_c2, HN, HN, HN, Wc2s_h, Wc2s_l);

    // 1) gathers (p | h stacked) + splits + xs emb-half fill
    gather_kernel<<<LPN, 128>>>(emb, p_idx, emb2, DN);
    gather_kernel<<<LHN, 128>>>(emb, h_idx, emb2 + (long)LPN * DN, DN);
    split_pad_kernel<<<(int)(((long)M2 * DP + 255) / 256), 256>>>(
        emb2, M2, DN, DP, emb2s_h, emb2s_l);
    xs_fill_kernel<<<(int)(((long)M2 * D2P + 255) / 256), 256>>>(emb2, xs_h, xs_l);

    // 2) attend (batched p+h)
    {
        BArgs a{emb2s_h, emb2s_l, DP, Wa1s_h, Wa1s_l, DP};
        a.bias = b_a1; a.Chi = ths_h; a.Clo = ths_l; a.ldS = HN;
        a.M = M2; a.N = HN; a.K = DP; a.relu = 1;
        launch_bgemm(a);
    }
    {
        BArgs a{ths_h, ths_l, HN, Wa2s_h, Wa2s_l, HN};
        a.bias = b_a2; a.C = f2; a.ldc = HN;
        a.Chi = fps_h; a.Clo = fps_l; a.ldS = HN;
        a.M = M2; a.N = HN; a.K = HN; a.relu = 1;
        launch_bgemm(a);
    }

    // 3) fhT = transpose(reshape(fh,[H,LH]))
    {
        dim3 g((LHN + 31) / 32, (HN + 31) / 32), b(32, 8);
        transpose_split_kernel<<<g, b>>>(f2 + (long)LPN * HN, HN, LHN, fhTs_h, fhTs_l, LHN);
    }

    // 4) E GEMM with fused split + transposed split + row/col partials
    {
        BArgs a{fps_h, fps_l, HN, fhTs_h, fhTs_l, HN};
        a.C = out + E_OFF; a.ldc = LHN;
        a.Chi = Es_h; a.Clo = Es_l; a.ldS = LHN;
        a.Th = ETs_h; a.Tl = ETs_l; a.ldT = LHN;
        a.rowpart = part; a.colpart = part2;
        a.M = LPN; a.N = LHN; a.K = HN;
        launch_bgemm(a);
    }
    colsum_reduce_kernel<<<(LPN + 255) / 256, 256>>>(part,  eik, LPN, 32);
    colsum_reduce_kernel<<<(LHN + 255) / 256, 256>>>(part2, ekj, LHN, 32);

    // 5) embedding transposes for beta/alpha B-operands
    {
        dim3 b(32, 8);
        dim3 gh((NROWS_PAD + 31) / 32, (LHN + 31) / 32);
        transpose_split_kernel<<<gh, b>>>(emb2 + (long)LPN * DN, LHN, DN, hTs_h, hTs_l, NROWS_PAD);
        dim3 gp((NROWS_PAD + 31) / 32, (LPN + 31) / 32);
        transpose_split_kernel<<<gp, b>>>(emb2, LPN, DN, pTs_h, pTs_l, NROWS_PAD);
    }

    // 6) beta & alpha in ONE launch (split-K x2 each)
    {
        BArgs a{Es_h, Es_l, LHN, hTs_h, hTs_l, LHN};
        a.A2h = ETs_h; a.A2l = ETs_l; a.B2h = pTs_h; a.B2l = pTs_l;
        a.C = split; a.ldc = DN; a.sliceStride = (long)LPN * DN;
        a.M = LPN; a.N = DN; a.K = LHN; a.splits = 2; a.zTotal = 4;
        launch_bgemm(a);
    }
    // reduce + rowdiv + fused concat into xs
    splitk_concat_kernel<<<(int)(((long)LPN * DN + 255) / 256), 256>>>(
        split, eik, out + BETA_OFF, xs_h, xs_l, 0, LPN, DN, 2);
    splitk_concat_kernel<<<(int)(((long)LHN * DN + 255) / 256), 256>>>(
        split + 2 * (long)LPN * DN, ekj, out + ALPHA_OFF, xs_h, xs_l, LPN, LHN, DN, 2);

    // 7) comp (batched), u never materialized — colsums fused into comp2
    {
        BArgs a{xs_h, xs_l, D2P, Wc1s_h, Wc1s_l, D2P};
        a.bias = b_c1; a.Chi = ths_h; a.Clo = ths_l; a.ldS = HN;
        a.M = M2; a.N = HN; a.K = D2P; a.relu = 1;
        launch_bgemm(a);
    }
    {
        BArgs a{ths_h, ths_l, HN, Wc2s_h, Wc2s_l, HN};
        a.bias = b_c2; a.colpart = part;
        a.M = M2; a.N = HN; a.K = HN; a.relu = 1;
        launch_bgemm(a);
    }
    // part: [64 m-tiles][512]; tiles 0..31 = p rows -> v1, 32..63 = h rows -> v2
    colsum_reduce_kernel<<<(HN + 255) / 256, 256>>>(part, out + V1_OFF, HN, 32);
    colsum_reduce_kernel<<<(HN + 255) / 256, 256>>>(part + 32 * HN, out + V2_OFF, HN, 32);

    // 8) head
    head_kernel<<<1, HN>>>(out + V1_OFF, W_g1, b_g1, W_g2, b_g2, W_g3, b_g3, out + Y_OFF);

    (void)in_sizes; (void)n_in; (void)out_size;
}

// round 8
// speedup vs baseline: 2.0853x; 1.0236x over previous
#include <cuda_runtime.h>
#include <cuda_bf16.h>
#include <cstdint>
#include <cmath>

#define LPN 4096
#define LHN 4096
#define DN  300
#define HN  512
#define DP  320          // DN padded to 32
#define D2P 608          // 2*DN padded to 32
#define NROWS_PAD 384    // DN padded to 128
#define M2  8192         // batched p+h rows

// ---------------- scratch (static device globals) ---------------------------
__device__ float g_emb2[M2 * DN];          // [p rows | h rows]
__device__ float g_f2  [M2 * HN];          // fp | fh (fp32)
__device__ float g_eik [LPN];
__device__ float g_ekj [LHN];
__device__ float g_part [64 * 4096];
__device__ float g_part2[64 * 4096];
__device__ float g_split[8 * LPN * DN];    // 8 split-K slices (beta x4, alpha x4)

__device__ __nv_bfloat16 g_emb2s_h[M2 * DP],  g_emb2s_l[M2 * DP];
__device__ __nv_bfloat16 g_ths_h [M2 * HN],   g_ths_l [M2 * HN];
__device__ __nv_bfloat16 g_fps_h [M2 * HN],   g_fps_l [M2 * HN];
__device__ __nv_bfloat16 g_fhTs_h[LHN * HN],  g_fhTs_l[LHN * HN];
__device__ __nv_bfloat16 g_Es_h [(long)LPN * LHN], g_Es_l [(long)LPN * LHN];
__device__ __nv_bfloat16 g_ETs_h[(long)LPN * LHN], g_ETs_l[(long)LPN * LHN];
__device__ __nv_bfloat16 g_hTs_h[NROWS_PAD * LHN], g_hTs_l[NROWS_PAD * LHN];
__device__ __nv_bfloat16 g_pTs_h[NROWS_PAD * LPN], g_pTs_l[NROWS_PAD * LPN];
__device__ __nv_bfloat16 g_xs_h [M2 * D2P],   g_xs_l [M2 * D2P];
__device__ __nv_bfloat16 g_Wa1s_h[HN * DP],   g_Wa1s_l[HN * DP];
__device__ __nv_bfloat16 g_Wa2s_h[HN * HN],   g_Wa2s_l[HN * HN];
__device__ __nv_bfloat16 g_Wc1s_h[HN * D2P],  g_Wc1s_l[HN * D2P];
__device__ __nv_bfloat16 g_Wc2s_h[HN * HN],   g_Wc2s_l[HN * HN];

// ---------------- PTX helpers ------------------------------------------------
__device__ __forceinline__ uint32_t smem_u32(const void* p) {
    uint32_t a;
    asm("{ .reg .u64 t; cvta.to.shared.u64 t, %1; cvt.u32.u64 %0, t; }" : "=r"(a) : "l"(p));
    return a;
}
__device__ __forceinline__ void ldsm4(uint32_t& r0, uint32_t& r1, uint32_t& r2,
                                      uint32_t& r3, uint32_t addr) {
    asm volatile("ldmatrix.sync.aligned.m8n8.x4.shared.b16 {%0,%1,%2,%3}, [%4];"
                 : "=r"(r0), "=r"(r1), "=r"(r2), "=r"(r3) : "r"(addr));
}
__device__ __forceinline__ void mma16816(float* c, const uint32_t* a,
                                         const uint32_t b0, const uint32_t b1) {
    asm volatile(
        "mma.sync.aligned.m16n8k16.row.col.f32.bf16.bf16.f32 "
        "{%0,%1,%2,%3}, {%4,%5,%6,%7}, {%8,%9}, {%0,%1,%2,%3};"
        : "+f"(c[0]), "+f"(c[1]), "+f"(c[2]), "+f"(c[3])
        : "r"(a[0]), "r"(a[1]), "r"(a[2]), "r"(a[3]), "r"(b0), "r"(b1));
}
__device__ __forceinline__ void cvt_split(float x, __nv_bfloat16& hi, __nv_bfloat16& lo) {
    hi = __float2bfloat16(x);
    lo = __float2bfloat16(x - __bfloat162float(hi));
}
__device__ __forceinline__ void cp16(uint32_t dst, const void* src) {
    asm volatile("cp.async.cg.shared.global [%0], [%1], 16;"
                 :: "r"(dst), "l"(__cvta_generic_to_global(src)));
}
__device__ __forceinline__ void cp_commit() {
    asm volatile("cp.async.commit_group;");
}
template <int NN> __device__ __forceinline__ void cp_wait() {
    asm volatile("cp.async.wait_group %0;" :: "n"(NN));
}

// ---------------- bf16x3 mma.sync SGEMM -------------------------------------
__global__ __launch_bounds__(256, 2)
void bgemm(const __nv_bfloat16* __restrict__ Agh, const __nv_bfloat16* __restrict__ Agl, long ldA,
           const __nv_bfloat16* __restrict__ Bgh, const __nv_bfloat16* __restrict__ Bgl, long ldB,
           const __nv_bfloat16* __restrict__ A2gh, const __nv_bfloat16* __restrict__ A2gl,
           const __nv_bfloat16* __restrict__ B2gh, const __nv_bfloat16* __restrict__ B2gl,
           int zSecond,
           const float* __restrict__ bias,
           float* __restrict__ C, long ldc, long sliceStride,
           __nv_bfloat16* __restrict__ Chi, __nv_bfloat16* __restrict__ Clo, long ldS,
           __nv_bfloat16* __restrict__ Th, __nv_bfloat16* __restrict__ Tl, long ldT,
           float* __restrict__ rowpart, float* __restrict__ colpart,
           int M, int N, int K, int kPerSlice, int relu) {
    extern __shared__ __align__(16) char smraw[];
    const int tid = threadIdx.x, lane = tid & 31, wid = tid >> 5;
    const int wm = wid >> 1, wn = wid & 1;
    const int m0 = blockIdx.y * 128, n0 = blockIdx.x * 128;
    const int zz = blockIdx.z;
    if (A2gh && zz >= zSecond) { Agh = A2gh; Agl = A2gl; Bgh = B2gh; Bgl = B2gl; }
    const int kbeg = (zz % zSecond) * kPerSlice;
    const int kend = min(K, kbeg + kPerSlice);
    const int nch = (kend - kbeg) >> 5;
    C += (long)zz * sliceStride;

    const uint32_t sb = smem_u32(smraw);

    float acc[2][8][4];
    #pragma unroll
    for (int i = 0; i < 2; i++)
        #pragma unroll
        for (int j = 0; j < 8; j++)
            #pragma unroll
            for (int e = 0; e < 4; e++) acc[i][j][e] = 0.f;

    const int lrow = (((lane >> 3) & 1) << 3) + (lane & 7);
    const int lcol = (lane >> 4) << 4;

    auto load_stage = [&](int st, int k0) {
        uint32_t sbase = sb + st * 40960;
        #pragma unroll
        for (int i = 0; i < 2; i++) {
            int c = tid + i * 256;
            int r = c >> 2, kq = c & 3;
            uint32_t dso = (uint32_t)(r * 80 + kq * 16);
            long ao = (long)(m0 + r) * ldA + k0 + kq * 8;
            long bo = (long)(n0 + r) * ldB + k0 + kq * 8;
            cp16(sbase + dso,          Agh + ao);
            cp16(sbase + 10240 + dso,  Agl + ao);
            cp16(sbase + 20480 + dso,  Bgh + bo);
            cp16(sbase + 30720 + dso,  Bgl + bo);
        }
    };

    load_stage(0, kbeg);
    cp_commit();

    for (int i = 0; i < nch; i++) {
        if (i + 1 < nch) {
            load_stage((i + 1) & 1, kbeg + (i + 1) * 32);
            cp_commit();
            cp_wait<1>();
        } else {
            cp_wait<0>();
        }
        __syncthreads();

        const uint32_t aAh = sb + (i & 1) * 40960;
        const uint32_t aAl = aAh + 10240;
        const uint32_t aBh = aAh + 20480;
        const uint32_t aBl = aAh + 30720;

        #pragma unroll
        for (int s = 0; s < 2; s++) {
            const int sbyte = s * 32;
            uint32_t ah[2][4], al[2][4], bh[4][4];
            #pragma unroll
            for (int mf = 0; mf < 2; mf++) {
                int row = wm * 32 + mf * 16 + lrow;
                ldsm4(ah[mf][0], ah[mf][1], ah[mf][2], ah[mf][3],
                      aAh + row * 80 + lcol + sbyte);
                ldsm4(al[mf][0], al[mf][1], al[mf][2], al[mf][3],
                      aAl + row * 80 + lcol + sbyte);
            }
            #pragma unroll
            for (int nf = 0; nf < 4; nf++) {
                int row = wn * 64 + nf * 16 + lrow;
                ldsm4(bh[nf][0], bh[nf][1], bh[nf][2], bh[nf][3],
                      aBh + row * 80 + lcol + sbyte);
            }
            #pragma unroll
            for (int nf = 0; nf < 4; nf++)
                #pragma unroll
                for (int j = 0; j < 2; j++)
                    #pragma unroll
                    for (int mf = 0; mf < 2; mf++)
                        mma16816(acc[mf][nf * 2 + j], ah[mf], bh[nf][j], bh[nf][j + 2]);
            #pragma unroll
            for (int nf = 0; nf < 4; nf++)
                #pragma unroll
                for (int j = 0; j < 2; j++)
                    #pragma unroll
                    for (int mf = 0; mf < 2; mf++)
                        mma16816(acc[mf][nf * 2 + j], al[mf], bh[nf][j], bh[nf][j + 2]);
            #pragma unroll
            for (int nf = 0; nf < 4; nf++) {
                int row = wn * 64 + nf * 16 + lrow;
                uint32_t bl[4];
                ldsm4(bl[0], bl[1], bl[2], bl[3], aBl + row * 80 + lcol + sbyte);
                #pragma unroll
                for (int j = 0; j < 2; j++)
                    #pragma unroll
                    for (int mf = 0; mf < 2; mf++)
                        mma16816(acc[mf][nf * 2 + j], ah[mf], bl[j], bl[j + 2]);
            }
        }
        __syncthreads();
    }

    // ---- epilogue: bias/relu in-place ----
    const int tg = lane >> 2;
    const int tn = (lane & 3) << 1;
    if (bias || relu) {
        #pragma unroll
        for (int mf = 0; mf < 2; mf++)
            #pragma unroll
            for (int nfj = 0; nfj < 8; nfj++) {
                int n = n0 + (wn * 64 + nfj * 8 + tn);
                #pragma unroll
                for (int h2 = 0; h2 < 2; h2++) {
                    float vx = acc[mf][nfj][h2 * 2 + 0];
                    float vy = acc[mf][nfj][h2 * 2 + 1];
                    if (bias && n < N) { vx += bias[n]; vy += bias[n + 1]; }
                    if (relu) { vx = fmaxf(vx, 0.f); vy = fmaxf(vy, 0.f); }
                    acc[mf][nfj][h2 * 2 + 0] = vx;
                    acc[mf][nfj][h2 * 2 + 1] = vy;
                }
            }
    }

    if (C || Chi) {
        #pragma unroll
        for (int mf = 0; mf < 2; mf++) {
            #pragma unroll
            for (int h2 = 0; h2 < 2; h2++) {
                int m = m0 + wm * 32 + mf * 16 + h2 * 8 + tg;
                #pragma unroll
                for (int nfj = 0; nfj < 8; nfj++) {
                    int n = n0 + wn * 64 + nfj * 8 + tn;
                    if (n >= N) continue;
                    float2 v;
                    v.x = acc[mf][nfj][h2 * 2 + 0];
                    v.y = acc[mf][nfj][h2 * 2 + 1];
                    if (C) *(float2*)(C + (long)m * ldc + n) = v;
                    if (Chi) {
                        __nv_bfloat16 h0, l0, h1, l1;
                        cvt_split(v.x, h0, l0);
                        cvt_split(v.y, h1, l1);
                        long o = (long)m * ldS + n;
                        Chi[o] = h0; Chi[o + 1] = h1;
                        Clo[o] = l0; Clo[o + 1] = l1;
                    }
                }
            }
        }
    }

    if (Th || rowpart || colpart) {
        __syncthreads();
        float* ts = (float*)smraw;             // [128][129]
        #pragma unroll
        for (int mf = 0; mf < 2; mf++) {
            #pragma unroll
            for (int h2 = 0; h2 < 2; h2++) {
                int ml = wm * 32 + mf * 16 + h2 * 8 + tg;
                #pragma unroll
                for (int nfj = 0; nfj < 8; nfj++) {
                    int nl = wn * 64 + nfj * 8 + tn;
                    ts[(nl + 0) * 129 + ml] = acc[mf][nfj][h2 * 2 + 0];
                    ts[(nl + 1) * 129 + ml] = acc[mf][nfj][h2 * 2 + 1];
                }
            }
        }
        __syncthreads();
        if (tid < 128) {
            if (rowpart) {
                float s = 0.f;
                #pragma unroll 8
                for (int n = 0; n < 128; n++) s += ts[n * 129 + tid];
                rowpart[(long)blockIdx.x * M + m0 + tid] = s;
            }
            if (colpart) {
                float s2 = 0.f;
                #pragma unroll 8
                for (int m = 0; m < 128; m++) s2 += ts[tid * 129 + m];
                colpart[(long)blockIdx.y * N + n0 + tid] = s2;
            }
        }
        if (Th) {
            for (int idx = tid; idx < 16384; idx += 256) {
                int n = idx >> 7, m = idx & 127;
                __nv_bfloat16 hi, lo;
                cvt_split(ts[n * 129 + m], hi, lo);
                long o = (long)(n0 + n) * ldT + m0 + m;
                Th[o] = hi; Tl[o] = lo;
            }
        }
    }
}

static const int BGEMM_SMEM = 2 * 40960;

// ---------------- fused gather + fp32 + split-pad + xs fill -------------------
// One block per row of emb2 (M2 rows). Writes:
//   emb2[r][0:DN] fp32 ; emb2s hi/lo [r][0:DP] (pad 0) ;
//   xs hi/lo [r][0:DN] = emb, [2DN:D2P] = 0 (middle left for splitk_concat)
__global__ void gather_split_kernel(const float* __restrict__ emb,
                                    const int* __restrict__ p_idx,
                                    const int* __restrict__ h_idx,
                                    float* __restrict__ emb2,
                                    __nv_bfloat16* __restrict__ e_h,
                                    __nv_bfloat16* __restrict__ e_l,
                                    __nv_bfloat16* __restrict__ x_h,
                                    __nv_bfloat16* __restrict__ x_l) {
    int r = blockIdx.x;
    long src = (r < LPN) ? p_idx[r] : h_idx[r - LPN];
    const float* s = emb + src * (long)DN;
    for (int c = threadIdx.x; c < DP; c += blockDim.x) {
        float v = (c < DN) ? s[c] : 0.f;
        __nv_bfloat16 hi, lo;
        cvt_split(v, hi, lo);
        long eo = (long)r * DP + c;
        e_h[eo] = hi; e_l[eo] = lo;
        if (c < DN) {
            emb2[(long)r * DN + c] = v;
            long xo = (long)r * D2P + c;
            x_h[xo] = hi; x_l[xo] = lo;
        }
    }
    // zero tail cols [2*DN, D2P)
    for (int c = 2 * DN + threadIdx.x; c < D2P; c += blockDim.x) {
        long xo = (long)r * D2P + c;
        x_h[xo] = __float2bfloat16(0.f);
        x_l[xo] = __float2bfloat16(0.f);
    }
}

// ---------------- transpose + split ------------------------------------------
__global__ void transpose_split_kernel(const float* __restrict__ src, int R, int C,
                                       __nv_bfloat16* __restrict__ dh,
                                       __nv_bfloat16* __restrict__ dl, int dR) {
    __shared__ float tile[32][33];
    int c0 = blockIdx.x * 32, r0 = blockIdx.y * 32;
    int x = threadIdx.x, y = threadIdx.y;
    #pragma unroll
    for (int i = y; i < 32; i += 8) {
        int r = r0 + i, c = c0 + x;
        tile[i][x] = (r < R && c < C) ? src[(long)r * C + c] : 0.f;
    }
    __syncthreads();
    #pragma unroll
    for (int i = y; i < 32; i += 8) {
        int dr = c0 + i, dc = r0 + x;
        if (dr < dR && dc < R) {
            __nv_bfloat16 hi, lo;
            cvt_split(tile[x][i], hi, lo);
            dh[(long)dr * R + dc] = hi;
            dl[(long)dr * R + dc] = lo;
        }
    }
}

// ---------------- split with K padding ----------------------------------------
__global__ void split_pad_kernel(const float* __restrict__ src, int M, int K, int Kpad,
                                 __nv_bfloat16* __restrict__ dh,
                                 __nv_bfloat16* __restrict__ dl) {
    long i = (long)blockIdx.x * blockDim.x + threadIdx.x;
    long total = (long)M * Kpad;
    if (i >= total) return;
    int m = (int)(i / Kpad), k = (int)(i % Kpad);
    float v = (k < K) ? src[(long)m * K + k] : 0.f;
    __nv_bfloat16 hi, lo;
    cvt_split(v, hi, lo);
    dh[i] = hi; dl[i] = lo;
}

// ---------------- split-K reduce + rowdiv + fused concat-split ----------------
__global__ void splitk_concat_kernel(const float* __restrict__ part,
                                     const float* __restrict__ rowdiv,
                                     float* __restrict__ C,
                                     __nv_bfloat16* __restrict__ xh,
                                     __nv_bfloat16* __restrict__ xl,
                                     long xRowOff, int M, int N, int S) {
    long i = (long)blockIdx.x * blockDim.x + threadIdx.x;
    long total = (long)M * N;
    if (i >= total) return;
    int m = (int)(i / N), n = (int)(i % N);
    float s = 0.f;
    for (int p = 0; p < S; p++) s += part[(long)p * total + i];
    float v = s / rowdiv[m];
    C[(long)m * N + n] = v;
    __nv_bfloat16 hi, lo;
    cvt_split(v, hi, lo);
    long o = (xRowOff + m) * (long)D2P + DN + n;
    xh[o] = hi; xl[o] = lo;
}

// ---------------- column reduce ------------------------------------------------
__global__ void colsum_reduce_kernel(const float* __restrict__ part,
                                     float* __restrict__ out, int C, int P) {
    int c = blockIdx.x * blockDim.x + threadIdx.x;
    if (c >= C) return;
    float s = 0.f;
    for (int p = 0; p < P; p++) s += part[(long)p * C + c];
    out[c] = s;
}

// ---------------- final MLP head + softmax -------------------------------------
__global__ void head_kernel(const float* __restrict__ v,
                            const float* __restrict__ Wg1, const float* __restrict__ bg1,
                            const float* __restrict__ Wg2, const float* __restrict__ bg2,
                            const float* __restrict__ Wg3, const float* __restrict__ bg3,
                            float* __restrict__ y) {
    __shared__ float sv[2 * HN];
    __shared__ float y1[HN];
    __shared__ float y2[HN];
    __shared__ float logit[3];
    int t = threadIdx.x;
    sv[t] = v[t];
    sv[t + HN] = v[t + HN];
    __syncthreads();
    {
        float acc = bg1[t];
        const float* w = Wg1 + (long)t * (2 * HN);
        for (int k = 0; k < 2 * HN; k++) acc += sv[k] * w[k];
        y1[t] = fmaxf(acc, 0.f);
    }
    __syncthreads();
    {
        float acc = bg2[t];
        const float* w = Wg2 + (long)t * HN;
        for (int k = 0; k < HN; k++) acc += y1[k] * w[k];
        y2[t] = fmaxf(acc, 0.f);
    }
    __syncthreads();
    if (t < 3) {
        float a = bg3[t];
        const float* w = Wg3 + (long)t * HN;
        for (int k = 0; k < HN; k++) a += y2[k] * w[k];
        logit[t] = a;
    }
    __syncthreads();
    if (t == 0) {
        float m = fmaxf(logit[0], fmaxf(logit[1], logit[2]));
        float e0 = expf(logit[0] - m), e1 = expf(logit[1] - m), e2 = expf(logit[2] - m);
        float s = e0 + e1 + e2;
        y[0] = e0 / s; y[1] = e1 / s; y[2] = e2 / s;
    }
}

// ---------------- host dispatch -----------------------------------------------
struct BArgs {
    const __nv_bfloat16 *Ah, *Al; long ldA;
    const __nv_bfloat16 *Bh, *Bl; long ldB;
    const __nv_bfloat16 *A2h = nullptr, *A2l = nullptr, *B2h = nullptr, *B2l = nullptr;
    const float* bias = nullptr;
    float* C = nullptr; long ldc = 0; long sliceStride = 0;
    __nv_bfloat16 *Chi = nullptr, *Clo = nullptr; long ldS = 0;
    __nv_bfloat16 *Th = nullptr, *Tl = nullptr; long ldT = 0;
    float *rowpart = nullptr, *colpart = nullptr;
    int M, N, K, splits = 1, zTotal = 0, relu = 0;
};

static void launch_bgemm(const BArgs& a) {
    cudaFuncSetAttribute(bgemm, cudaFuncAttributeMaxDynamicSharedMemorySize, BGEMM_SMEM);
    int kps = (a.K + a.splits - 1) / a.splits;
    kps = ((kps + 31) / 32) * 32;
    int zt = a.zTotal ? a.zTotal : a.splits;
    dim3 grid((a.N + 127) / 128, a.M / 128, zt);
    bgemm<<<grid, 256, BGEMM_SMEM>>>(a.Ah, a.Al, a.ldA, a.Bh, a.Bl, a.ldB,
                                     a.A2h, a.A2l, a.B2h, a.B2l, a.splits,
                                     a.bias, a.C, a.ldc, a.sliceStride,
                                     a.Chi, a.Clo, a.ldS, a.Th, a.Tl, a.ldT,
                                     a.rowpart, a.colpart,
                                     a.M, a.N, a.K, kps, a.relu);
}

#define GETSYM(var, sym) cudaGetSymbolAddress((void**)&var, sym)

extern "C" void kernel_launch(void* const* d_in, const int* in_sizes, int n_in,
                              void* d_out, int out_size) {
    const int*   p_idx = (const int*)  d_in[0];
    const int*   h_idx = (const int*)  d_in[1];
    const float* emb   = (const float*)d_in[2];
    const float* W_a1  = (const float*)d_in[3];
    const float* b_a1  = (const float*)d_in[4];
    const float* W_a2  = (const float*)d_in[5];
    const float* b_a2  = (const float*)d_in[6];
    const float* W_c1  = (const float*)d_in[7];
    const float* b_c1  = (const float*)d_in[8];
    const float* W_c2  = (const float*)d_in[9];
    const float* b_c2  = (const float*)d_in[10];
    const float* W_g1  = (const float*)d_in[11];
    const float* b_g1  = (const float*)d_in[12];
    const float* W_g2  = (const float*)d_in[13];
    const float* b_g2  = (const float*)d_in[14];
    const float* W_g3  = (const float*)d_in[15];
    const float* b_g3  = (const float*)d_in[16];

    float* out = (float*)d_out;
    const long E_OFF    = 0;
    const long BETA_OFF = (long)LPN * LHN;
    const long ALPHA_OFF= BETA_OFF + (long)LPN * DN;
    const long V1_OFF   = ALPHA_OFF + (long)LHN * DN;
    const long V2_OFF   = V1_OFF + HN;
    const long Y_OFF    = V2_OFF + HN;

    float *emb2, *f2, *eik, *ekj, *part, *part2, *split;
    GETSYM(emb2, g_emb2); GETSYM(f2, g_f2);
    GETSYM(eik, g_eik); GETSYM(ekj, g_ekj);
    GETSYM(part, g_part); GETSYM(part2, g_part2); GETSYM(split, g_split);

    __nv_bfloat16 *emb2s_h, *emb2s_l, *ths_h, *ths_l, *fps_h, *fps_l;
    __nv_bfloat16 *fhTs_h, *fhTs_l, *Es_h, *Es_l, *ETs_h, *ETs_l;
    __nv_bfloat16 *hTs_h, *hTs_l, *pTs_h, *pTs_l, *xs_h, *xs_l;
    __nv_bfloat16 *Wa1s_h, *Wa1s_l, *Wa2s_h, *Wa2s_l, *Wc1s_h, *Wc1s_l, *Wc2s_h, *Wc2s_l;
    GETSYM(emb2s_h, g_emb2s_h); GETSYM(emb2s_l, g_emb2s_l);
    GETSYM(ths_h, g_ths_h);     GETSYM(ths_l, g_ths_l);
    GETSYM(fps_h, g_fps_h);     GETSYM(fps_l, g_fps_l);
    GETSYM(fhTs_h, g_fhTs_h);   GETSYM(fhTs_l, g_fhTs_l);
    GETSYM(Es_h, g_Es_h);       GETSYM(Es_l, g_Es_l);
    GETSYM(ETs_h, g_ETs_h);     GETSYM(ETs_l, g_ETs_l);
    GETSYM(hTs_h, g_hTs_h);     GETSYM(hTs_l, g_hTs_l);
    GETSYM(pTs_h, g_pTs_h);     GETSYM(pTs_l, g_pTs_l);
    GETSYM(xs_h, g_xs_h);       GETSYM(xs_l, g_xs_l);
    GETSYM(Wa1s_h, g_Wa1s_h);   GETSYM(Wa1s_l, g_Wa1s_l);
    GETSYM(Wa2s_h, g_Wa2s_h);   GETSYM(Wa2s_l, g_Wa2s_l);
    GETSYM(Wc1s_h, g_Wc1s_h);   GETSYM(Wc1s_l, g_Wc1s_l);
    GETSYM(Wc2s_h, g_Wc2s_h);   GETSYM(Wc2s_l, g_Wc2s_l);

    // 0) weight splits
    split_pad_kernel<<<(HN * DP + 255) / 256, 256>>>(W_a1, HN, DN, DP, Wa1s_h, Wa1s_l);
    split_pad_kernel<<<(HN * HN + 255) / 256, 256>>>(W_a2, HN, HN, HN, Wa2s_h, Wa2s_l);
    split_pad_kernel<<<(HN * D2P + 255) / 256, 256>>>(W_c1, HN, 2 * DN, D2P, Wc1s_h, Wc1s_l);
    split_pad_kernel<<<(HN * HN + 255) / 256, 256>>>(W_c2, HN, HN, HN, Wc2s_h, Wc2s_l);

    // 1) fused gather + splits + xs fill (one pass)
    gather_split_kernel<<<M2, 128>>>(emb, p_idx, h_idx, emb2,
                                     emb2s_h, emb2s_l, xs_h, xs_l);

    // 2) attend (batched p+h)
    {
        BArgs a{emb2s_h, emb2s_l, DP, Wa1s_h, Wa1s_l, DP};
        a.bias = b_a1; a.Chi = ths_h; a.Clo = ths_l; a.ldS = HN;
        a.M = M2; a.N = HN; a.K = DP; a.relu = 1;
        launch_bgemm(a);
    }
    {
        BArgs a{ths_h, ths_l, HN, Wa2s_h, Wa2s_l, HN};
        a.bias = b_a2; a.C = f2; a.ldc = HN;
        a.Chi = fps_h; a.Clo = fps_l; a.ldS = HN;
        a.M = M2; a.N = HN; a.K = HN; a.relu = 1;
        launch_bgemm(a);
    }

    // 3) fhT = transpose(reshape(fh,[H,LH]))
    {
        dim3 g((LHN + 31) / 32, (HN + 31) / 32), b(32, 8);
        transpose_split_kernel<<<g, b>>>(f2 + (long)LPN * HN, HN, LHN, fhTs_h, fhTs_l, LHN);
    }

    // 4) E GEMM with fused split + transposed split + row/col partials
    {
        BArgs a{fps_h, fps_l, HN, fhTs_h, fhTs_l, HN};
        a.C = out + E_OFF; a.ldc = LHN;
        a.Chi = Es_h; a.Clo = Es_l; a.ldS = LHN;
        a.Th = ETs_h; a.Tl = ETs_l; a.ldT = LHN;
        a.rowpart = part; a.colpart = part2;
        a.M = LPN; a.N = LHN; a.K = HN;
        launch_bgemm(a);
    }
    colsum_reduce_kernel<<<(LPN + 255) / 256, 256>>>(part,  eik, LPN, 32);
    colsum_reduce_kernel<<<(LHN + 255) / 256, 256>>>(part2, ekj, LHN, 32);

    // 5) embedding transposes for beta/alpha B-operands
    {
        dim3 b(32, 8);
        dim3 gh((NROWS_PAD + 31) / 32, (LHN + 31) / 32);
        transpose_split_kernel<<<gh, b>>>(emb2 + (long)LPN * DN, LHN, DN, hTs_h, hTs_l, NROWS_PAD);
        dim3 gp((NROWS_PAD + 31) / 32, (LPN + 31) / 32);
        transpose_split_kernel<<<gp, b>>>(emb2, LPN, DN, pTs_h, pTs_l, NROWS_PAD);
    }

    // 6) beta & alpha in ONE launch, split-K x4 each (wave quantization fix)
    {
        BArgs a{Es_h, Es_l, LHN, hTs_h, hTs_l, LHN};
        a.A2h = ETs_h; a.A2l = ETs_l; a.B2h = pTs_h; a.B2l = pTs_l;
        a.C = split; a.ldc = DN; a.sliceStride = (long)LPN * DN;
        a.M = LPN; a.N = DN; a.K = LHN; a.splits = 4; a.zTotal = 8;
        launch_bgemm(a);
    }
    splitk_concat_kernel<<<(int)(((long)LPN * DN + 255) / 256), 256>>>(
        split, eik, out + BETA_OFF, xs_h, xs_l, 0, LPN, DN, 4);
    splitk_concat_kernel<<<(int)(((long)LHN * DN + 255) / 256), 256>>>(
        split + 4 * (long)LPN * DN, ekj, out + ALPHA_OFF, xs_h, xs_l, LPN, LHN, DN, 4);

    // 7) comp (batched), colsums fused into comp2
    {
        BArgs a{xs_h, xs_l, D2P, Wc1s_h, Wc1s_l, D2P};
        a.bias = b_c1; a.Chi = ths_h; a.Clo = ths_l; a.ldS = HN;
        a.M = M2; a.N = HN; a.K = D2P; a.relu = 1;
        launch_bgemm(a);
    }
    {
        BArgs a{ths_h, ths_l, HN, Wc2s_h, Wc2s_l, HN};
        a.bias = b_c2; a.colpart = part;
        a.M = M2; a.N = HN; a.K = HN; a.relu = 1;
        launch_bgemm(a);
    }
    colsum_reduce_kernel<<<(HN + 255) / 256, 256>>>(part, out + V1_OFF, HN, 32);
    colsum_reduce_kernel<<<(HN + 255) / 256, 256>>>(part + 32 * HN, out + V2_OFF, HN, 32);

    // 8) head
    head_kernel<<<1, HN>>>(out + V1_OFF, W_g1, b_g1, W_g2, b_g2, W_g3, b_g3, out + Y_OFF);

    (void)in_sizes; (void)n_in; (void)out_size;
}

// round 9
// speedup vs baseline: 2.1198x; 1.0166x over previous
#include <cuda_runtime.h>
#include <cuda_bf16.h>
#include <cstdint>
#include <cmath>

#define LPN 4096
#define LHN 4096
#define DN  300
#define HN  512
#define DP  320          // DN padded to 32
#define D2P 608          // 2*DN padded to 32
#define NROWS_PAD 384    // DN padded to 128
#define M2  8192         // batched p+h rows

// ---------------- scratch (static device globals) ---------------------------
__device__ float g_emb2[M2 * DN];          // [p rows | h rows]
__device__ float g_eik [LPN];
__device__ float g_ekj [LHN];
__device__ float g_part [64 * 4096];
__device__ float g_part2[64 * 4096];
__device__ float g_split[8 * LPN * DN];    // 8 split-K slices (beta x4, alpha x4)

__device__ __nv_bfloat16 g_emb2s_h[M2 * DP],  g_emb2s_l[M2 * DP];
__device__ __nv_bfloat16 g_ths_h [M2 * HN],   g_ths_l [M2 * HN];
__device__ __nv_bfloat16 g_fps_h [LPN * HN],  g_fps_l [LPN * HN];
__device__ __nv_bfloat16 g_fhTs_h[LHN * HN],  g_fhTs_l[LHN * HN];
__device__ __nv_bfloat16 g_Es_h [(long)LPN * LHN], g_Es_l [(long)LPN * LHN];
__device__ __nv_bfloat16 g_ETs_h[(long)LPN * LHN], g_ETs_l[(long)LPN * LHN];
__device__ __nv_bfloat16 g_hTs_h[NROWS_PAD * LHN], g_hTs_l[NROWS_PAD * LHN];
__device__ __nv_bfloat16 g_pTs_h[NROWS_PAD * LPN], g_pTs_l[NROWS_PAD * LPN];
__device__ __nv_bfloat16 g_xs_h [M2 * D2P],   g_xs_l [M2 * D2P];
__device__ __nv_bfloat16 g_Wa1s_h[HN * DP],   g_Wa1s_l[HN * DP];
__device__ __nv_bfloat16 g_Wa2s_h[HN * HN],   g_Wa2s_l[HN * HN];
__device__ __nv_bfloat16 g_Wc1s_h[HN * D2P],  g_Wc1s_l[HN * D2P];
__device__ __nv_bfloat16 g_Wc2s_h[HN * HN],   g_Wc2s_l[HN * HN];

// ---------------- PTX helpers ------------------------------------------------
__device__ __forceinline__ uint32_t smem_u32(const void* p) {
    uint32_t a;
    asm("{ .reg .u64 t; cvta.to.shared.u64 t, %1; cvt.u32.u64 %0, t; }" : "=r"(a) : "l"(p));
    return a;
}
__device__ __forceinline__ void ldsm4(uint32_t& r0, uint32_t& r1, uint32_t& r2,
                                      uint32_t& r3, uint32_t addr) {
    asm volatile("ldmatrix.sync.aligned.m8n8.x4.shared.b16 {%0,%1,%2,%3}, [%4];"
                 : "=r"(r0), "=r"(r1), "=r"(r2), "=r"(r3) : "r"(addr));
}
__device__ __forceinline__ void mma16816(float* c, const uint32_t* a,
                                         const uint32_t b0, const uint32_t b1) {
    asm volatile(
        "mma.sync.aligned.m16n8k16.row.col.f32.bf16.bf16.f32 "
        "{%0,%1,%2,%3}, {%4,%5,%6,%7}, {%8,%9}, {%0,%1,%2,%3};"
        : "+f"(c[0]), "+f"(c[1]), "+f"(c[2]), "+f"(c[3])
        : "r"(a[0]), "r"(a[1]), "r"(a[2]), "r"(a[3]), "r"(b0), "r"(b1));
}
__device__ __forceinline__ void cvt_split(float x, __nv_bfloat16& hi, __nv_bfloat16& lo) {
    hi = __float2bfloat16(x);
    lo = __float2bfloat16(x - __bfloat162float(hi));
}
__device__ __forceinline__ void cp16(uint32_t dst, const void* src) {
    asm volatile("cp.async.cg.shared.global [%0], [%1], 16;"
                 :: "r"(dst), "l"(__cvta_generic_to_global(src)));
}
__device__ __forceinline__ void cp_commit() {
    asm volatile("cp.async.commit_group;");
}
template <int NN> __device__ __forceinline__ void cp_wait() {
    asm volatile("cp.async.wait_group %0;" :: "n"(NN));
}

// ---------------- bf16x3 mma.sync SGEMM -------------------------------------
// reshapeRow >= 0 enables attend2 mode: tiles with m0 >= reshapeRow write a
// fused reshape([H,LH])-transpose into Th/Tl instead of Chi/Clo.
__global__ __launch_bounds__(256, 2)
void bgemm(const __nv_bfloat16* __restrict__ Agh, const __nv_bfloat16* __restrict__ Agl, long ldA,
           const __nv_bfloat16* __restrict__ Bgh, const __nv_bfloat16* __restrict__ Bgl, long ldB,
           const __nv_bfloat16* __restrict__ A2gh, const __nv_bfloat16* __restrict__ A2gl,
           const __nv_bfloat16* __restrict__ B2gh, const __nv_bfloat16* __restrict__ B2gl,
           int zSecond,
           const float* __restrict__ bias,
           float* __restrict__ C, long ldc, long sliceStride,
           __nv_bfloat16* __restrict__ Chi, __nv_bfloat16* __restrict__ Clo, long ldS,
           __nv_bfloat16* __restrict__ Th, __nv_bfloat16* __restrict__ Tl, long ldT,
           float* __restrict__ rowpart, float* __restrict__ colpart,
           int reshapeRow,
           int M, int N, int K, int kPerSlice, int relu) {
    extern __shared__ __align__(16) char smraw[];
    const int tid = threadIdx.x, lane = tid & 31, wid = tid >> 5;
    const int wm = wid >> 1, wn = wid & 1;
    const int m0 = blockIdx.y * 128, n0 = blockIdx.x * 128;
    const int zz = blockIdx.z;
    if (A2gh && zz >= zSecond) { Agh = A2gh; Agl = A2gl; Bgh = B2gh; Bgl = B2gl; }
    const int kbeg = (zz % zSecond) * kPerSlice;
    const int kend = min(K, kbeg + kPerSlice);
    const int nch = (kend - kbeg) >> 5;
    C += (long)zz * sliceStride;

    const uint32_t sb = smem_u32(smraw);

    float acc[2][8][4];
    #pragma unroll
    for (int i = 0; i < 2; i++)
        #pragma unroll
        for (int j = 0; j < 8; j++)
            #pragma unroll
            for (int e = 0; e < 4; e++) acc[i][j][e] = 0.f;

    const int lrow = (((lane >> 3) & 1) << 3) + (lane & 7);
    const int lcol = (lane >> 4) << 4;

    auto load_stage = [&](int st, int k0) {
        uint32_t sbase = sb + st * 40960;
        #pragma unroll
        for (int i = 0; i < 2; i++) {
            int c = tid + i * 256;
            int r = c >> 2, kq = c & 3;
            uint32_t dso = (uint32_t)(r * 80 + kq * 16);
            long ao = (long)(m0 + r) * ldA + k0 + kq * 8;
            long bo = (long)(n0 + r) * ldB + k0 + kq * 8;
            cp16(sbase + dso,          Agh + ao);
            cp16(sbase + 10240 + dso,  Agl + ao);
            cp16(sbase + 20480 + dso,  Bgh + bo);
            cp16(sbase + 30720 + dso,  Bgl + bo);
        }
    };

    load_stage(0, kbeg);
    cp_commit();

    for (int i = 0; i < nch; i++) {
        if (i + 1 < nch) {
            load_stage((i + 1) & 1, kbeg + (i + 1) * 32);
            cp_commit();
            cp_wait<1>();
        } else {
            cp_wait<0>();
        }
        __syncthreads();

        const uint32_t aAh = sb + (i & 1) * 40960;
        const uint32_t aAl = aAh + 10240;
        const uint32_t aBh = aAh + 20480;
        const uint32_t aBl = aAh + 30720;

        #pragma unroll
        for (int s = 0; s < 2; s++) {
            const int sbyte = s * 32;
            uint32_t ah[2][4], al[2][4], bh[4][4];
            #pragma unroll
            for (int mf = 0; mf < 2; mf++) {
                int row = wm * 32 + mf * 16 + lrow;
                ldsm4(ah[mf][0], ah[mf][1], ah[mf][2], ah[mf][3],
                      aAh + row * 80 + lcol + sbyte);
                ldsm4(al[mf][0], al[mf][1], al[mf][2], al[mf][3],
                      aAl + row * 80 + lcol + sbyte);
            }
            #pragma unroll
            for (int nf = 0; nf < 4; nf++) {
                int row = wn * 64 + nf * 16 + lrow;
                ldsm4(bh[nf][0], bh[nf][1], bh[nf][2], bh[nf][3],
                      aBh + row * 80 + lcol + sbyte);
            }
            #pragma unroll
            for (int nf = 0; nf < 4; nf++)
                #pragma unroll
                for (int j = 0; j < 2; j++)
                    #pragma unroll
                    for (int mf = 0; mf < 2; mf++)
                        mma16816(acc[mf][nf * 2 + j], ah[mf], bh[nf][j], bh[nf][j + 2]);
            #pragma unroll
            for (int nf = 0; nf < 4; nf++)
                #pragma unroll
                for (int j = 0; j < 2; j++)
                    #pragma unroll
                    for (int mf = 0; mf < 2; mf++)
                        mma16816(acc[mf][nf * 2 + j], al[mf], bh[nf][j], bh[nf][j + 2]);
            #pragma unroll
            for (int nf = 0; nf < 4; nf++) {
                int row = wn * 64 + nf * 16 + lrow;
                uint32_t bl[4];
                ldsm4(bl[0], bl[1], bl[2], bl[3], aBl + row * 80 + lcol + sbyte);
                #pragma unroll
                for (int j = 0; j < 2; j++)
                    #pragma unroll
                    for (int mf = 0; mf < 2; mf++)
                        mma16816(acc[mf][nf * 2 + j], ah[mf], bl[j], bl[j + 2]);
            }
        }
        __syncthreads();
    }

    // ---- epilogue: bias/relu in-place ----
    const int tg = lane >> 2;
    const int tn = (lane & 3) << 1;
    if (bias || relu) {
        #pragma unroll
        for (int mf = 0; mf < 2; mf++)
            #pragma unroll
            for (int nfj = 0; nfj < 8; nfj++) {
                int n = n0 + (wn * 64 + nfj * 8 + tn);
                #pragma unroll
                for (int h2 = 0; h2 < 2; h2++) {
                    float vx = acc[mf][nfj][h2 * 2 + 0];
                    float vy = acc[mf][nfj][h2 * 2 + 1];
                    if (bias && n < N) { vx += bias[n]; vy += bias[n + 1]; }
                    if (relu) { vx = fmaxf(vx, 0.f); vy = fmaxf(vy, 0.f); }
                    acc[mf][nfj][h2 * 2 + 0] = vx;
                    acc[mf][nfj][h2 * 2 + 1] = vy;
                }
            }
    }

    const bool rsh = (reshapeRow >= 0);
    const bool isH = rsh && (m0 >= reshapeRow);

    if (C || (Chi && !isH)) {
        #pragma unroll
        for (int mf = 0; mf < 2; mf++) {
            #pragma unroll
            for (int h2 = 0; h2 < 2; h2++) {
                int m = m0 + wm * 32 + mf * 16 + h2 * 8 + tg;
                #pragma unroll
                for (int nfj = 0; nfj < 8; nfj++) {
                    int n = n0 + wn * 64 + nfj * 8 + tn;
                    if (n >= N) continue;
                    float2 v;
                    v.x = acc[mf][nfj][h2 * 2 + 0];
                    v.y = acc[mf][nfj][h2 * 2 + 1];
                    if (C) *(float2*)(C + (long)m * ldc + n) = v;
                    if (Chi && !isH) {
                        __nv_bfloat16 h0, l0, h1, l1;
                        cvt_split(v.x, h0, l0);
                        cvt_split(v.y, h1, l1);
                        long o = (long)m * ldS + n;
                        Chi[o] = h0; Chi[o + 1] = h1;
                        Clo[o] = l0; Clo[o + 1] = l1;
                    }
                }
            }
        }
    }

    const bool doStage = (Th && (!rsh || isH)) || rowpart || colpart;
    if (doStage) {
        __syncthreads();
        float* ts = (float*)smraw;             // [128][129]
        #pragma unroll
        for (int mf = 0; mf < 2; mf++) {
            #pragma unroll
            for (int h2 = 0; h2 < 2; h2++) {
                int ml = wm * 32 + mf * 16 + h2 * 8 + tg;
                #pragma unroll
                for (int nfj = 0; nfj < 8; nfj++) {
                    int nl = wn * 64 + nfj * 8 + tn;
                    ts[(nl + 0) * 129 + ml] = acc[mf][nfj][h2 * 2 + 0];
                    ts[(nl + 1) * 129 + ml] = acc[mf][nfj][h2 * 2 + 1];
                }
            }
        }
        __syncthreads();
        if (tid < 128) {
            if (rowpart) {
                float s = 0.f;
                #pragma unroll 8
                for (int n = 0; n < 128; n++) s += ts[n * 129 + tid];
                rowpart[(long)blockIdx.x * M + m0 + tid] = s;
            }
            if (colpart) {
                float s2 = 0.f;
                #pragma unroll 8
                for (int m = 0; m < 128; m++) s2 += ts[tid * 129 + m];
                colpart[(long)blockIdx.y * N + n0 + tid] = s2;
            }
        }
        if (Th && (!rsh || isH)) {
            if (rsh) {
                // fused reshape([HN, LHN]) transpose:
                // f[m][n] (m>=reshapeRow) -> fhT[(mm%8)*HN + n][mm/8], mm = m - reshapeRow
                long kb = (long)(m0 - reshapeRow) >> 3;
                for (int idx = tid; idx < 1024; idx += 256) {
                    int r8 = idx >> 7, nl = idx & 127;
                    long j = (long)r8 * HN + n0 + nl;
                    __align__(16) __nv_bfloat16 hb[16], lb[16];
                    #pragma unroll
                    for (int q = 0; q < 16; q++) {
                        __nv_bfloat16 hi, lo;
                        cvt_split(ts[nl * 129 + r8 + 8 * q], hi, lo);
                        hb[q] = hi; lb[q] = lo;
                    }
                    long o = j * ldT + kb;
                    *(uint4*)(Th + o)     = *(uint4*)(hb);
                    *(uint4*)(Th + o + 8) = *(uint4*)(hb + 8);
                    *(uint4*)(Tl + o)     = *(uint4*)(lb);
                    *(uint4*)(Tl + o + 8) = *(uint4*)(lb + 8);
                }
            } else {
                for (int idx = tid; idx < 16384; idx += 256) {
                    int n = idx >> 7, m = idx & 127;
                    __nv_bfloat16 hi, lo;
                    cvt_split(ts[n * 129 + m], hi, lo);
                    long o = (long)(n0 + n) * ldT + m0 + m;
                    Th[o] = hi; Tl[o] = lo;
                }
            }
        }
    }
}

static const int BGEMM_SMEM = 2 * 40960;

// ---------------- all 4 weight splits in ONE kernel ---------------------------
__global__ void split_weights_kernel(const float* __restrict__ Wa1, const float* __restrict__ Wa2,
                                     const float* __restrict__ Wc1, const float* __restrict__ Wc2,
                                     __nv_bfloat16* __restrict__ a1h, __nv_bfloat16* __restrict__ a1l,
                                     __nv_bfloat16* __restrict__ a2h, __nv_bfloat16* __restrict__ a2l,
                                     __nv_bfloat16* __restrict__ c1h, __nv_bfloat16* __restrict__ c1l,
                                     __nv_bfloat16* __restrict__ c2h, __nv_bfloat16* __restrict__ c2l) {
    const long s1 = (long)HN * DP, s2 = (long)HN * HN, s3 = (long)HN * D2P, s4 = (long)HN * HN;
    long i = (long)blockIdx.x * blockDim.x + threadIdx.x;
    const float* src; __nv_bfloat16 *dh, *dl; int K, Kpad; long li;
    if (i < s1)                { src = Wa1; dh = a1h; dl = a1l; K = DN;     Kpad = DP;  li = i; }
    else if (i < s1 + s2)      { src = Wa2; dh = a2h; dl = a2l; K = HN;     Kpad = HN;  li = i - s1; }
    else if (i < s1 + s2 + s3) { src = Wc1; dh = c1h; dl = c1l; K = 2 * DN; Kpad = D2P; li = i - s1 - s2; }
    else if (i < s1 + s2 + s3 + s4) { src = Wc2; dh = c2h; dl = c2l; K = HN; Kpad = HN; li = i - s1 - s2 - s3; }
    else return;
    int m = (int)(li / Kpad), k = (int)(li % Kpad);
    float v = (k < K) ? src[(long)m * K + k] : 0.f;
    __nv_bfloat16 hi, lo;
    cvt_split(v, hi, lo);
    dh[li] = hi; dl[li] = lo;
}

// ---------------- fused gather + fp32 + split-pad + xs fill -------------------
__global__ void gather_split_kernel(const float* __restrict__ emb,
                                    const int* __restrict__ p_idx,
                                    const int* __restrict__ h_idx,
                                    float* __restrict__ emb2,
                                    __nv_bfloat16* __restrict__ e_h,
                                    __nv_bfloat16* __restrict__ e_l,
                                    __nv_bfloat16* __restrict__ x_h,
                                    __nv_bfloat16* __restrict__ x_l) {
    int r = blockIdx.x;
    long src = (r < LPN) ? p_idx[r] : h_idx[r - LPN];
    const float* s = emb + src * (long)DN;
    for (int c = threadIdx.x; c < DP; c += blockDim.x) {
        float v = (c < DN) ? s[c] : 0.f;
        __nv_bfloat16 hi, lo;
        cvt_split(v, hi, lo);
        long eo = (long)r * DP + c;
        e_h[eo] = hi; e_l[eo] = lo;
        if (c < DN) {
            emb2[(long)r * DN + c] = v;
            long xo = (long)r * D2P + c;
            x_h[xo] = hi; x_l[xo] = lo;
        }
    }
    for (int c = 2 * DN + threadIdx.x; c < D2P; c += blockDim.x) {
        long xo = (long)r * D2P + c;
        x_h[xo] = __float2bfloat16(0.f);
        x_l[xo] = __float2bfloat16(0.f);
    }
}

// ---------------- transpose + split (dual-source via blockIdx.z) --------------
__global__ void transpose_split2_kernel(const float* __restrict__ srcA,
                                        __nv_bfloat16* __restrict__ dhA, __nv_bfloat16* __restrict__ dlA,
                                        const float* __restrict__ srcB,
                                        __nv_bfloat16* __restrict__ dhB, __nv_bfloat16* __restrict__ dlB,
                                        int R, int C, int dR) {
    const float* src = blockIdx.z ? srcB : srcA;
    __nv_bfloat16* dh = blockIdx.z ? dhB : dhA;
    __nv_bfloat16* dl = blockIdx.z ? dlB : dlA;
    __shared__ float tile[32][33];
    int c0 = blockIdx.x * 32, r0 = blockIdx.y * 32;
    int x = threadIdx.x, y = threadIdx.y;
    #pragma unroll
    for (int i = y; i < 32; i += 8) {
        int r = r0 + i, c = c0 + x;
        tile[i][x] = (r < R && c < C) ? src[(long)r * C + c] : 0.f;
    }
    __syncthreads();
    #pragma unroll
    for (int i = y; i < 32; i += 8) {
        int dr = c0 + i, dc = r0 + x;
        if (dr < dR && dc < R) {
            __nv_bfloat16 hi, lo;
            cvt_split(tile[x][i], hi, lo);
            dh[(long)dr * R + dc] = hi;
            dl[(long)dr * R + dc] = lo;
        }
    }
}

// ---------------- split-K reduce + rowdiv + fused concat, dual via grid.y -----
__global__ void splitk_concat2_kernel(const float* __restrict__ partA, const float* __restrict__ rdA,
                                      float* __restrict__ CA,
                                      const float* __restrict__ partB, const float* __restrict__ rdB,
                                      float* __restrict__ CB,
                                      __nv_bfloat16* __restrict__ xh, __nv_bfloat16* __restrict__ xl,
                                      int M, int N, int S) {
    const float* part = blockIdx.y ? partB : partA;
    const float* rowdiv = blockIdx.y ? rdB : rdA;
    float* C = blockIdx.y ? CB : CA;
    long xRowOff = blockIdx.y ? (long)M : 0;
    long i = (long)blockIdx.x * blockDim.x + threadIdx.x;
    long total = (long)M * N;
    if (i >= total) return;
    int m = (int)(i / N), n = (int)(i % N);
    float s = 0.f;
    for (int p = 0; p < S; p++) s += part[(long)p * total + i];
    float v = s / rowdiv[m];
    C[(long)m * N + n] = v;
    __nv_bfloat16 hi, lo;
    cvt_split(v, hi, lo);
    long o = (xRowOff + m) * (long)D2P + DN + n;
    xh[o] = hi; xl[o] = lo;
}

// ---------------- dual column reduce (grid.y selects) --------------------------
__global__ void colsum_reduce2_kernel(const float* __restrict__ partA, float* __restrict__ outA,
                                      const float* __restrict__ partB, float* __restrict__ outB,
                                      int C, int P) {
    const float* part = blockIdx.y ? partB : partA;
    float* out = blockIdx.y ? outB : outA;
    int c = blockIdx.x * blockDim.x + threadIdx.x;
    if (c >= C) return;
    float s = 0.f;
    for (int p = 0; p < P; p++) s += part[(long)p * C + c];
    out[c] = s;
}

// ---------------- final MLP head + softmax -------------------------------------
__global__ void head_kernel(const float* __restrict__ v,
                            const float* __restrict__ Wg1, const float* __restrict__ bg1,
                            const float* __restrict__ Wg2, const float* __restrict__ bg2,
                            const float* __restrict__ Wg3, const float* __restrict__ bg3,
                            float* __restrict__ y) {
    __shared__ float sv[2 * HN];
    __shared__ float y1[HN];
    __shared__ float y2[HN];
    __shared__ float logit[3];
    int t = threadIdx.x;
    sv[t] = v[t];
    sv[t + HN] = v[t + HN];
    __syncthreads();
    {
        float acc = bg1[t];
        const float* w = Wg1 + (long)t * (2 * HN);
        for (int k = 0; k < 2 * HN; k++) acc += sv[k] * w[k];
        y1[t] = fmaxf(acc, 0.f);
    }
    __syncthreads();
    {
        float acc = bg2[t];
        const float* w = Wg2 + (long)t * HN;
        for (int k = 0; k < HN; k++) acc += y1[k] * w[k];
        y2[t] = fmaxf(acc, 0.f);
    }
    __syncthreads();
    if (t < 3) {
        float a = bg3[t];
        const float* w = Wg3 + (long)t * HN;
        for (int k = 0; k < HN; k++) a += y2[k] * w[k];
        logit[t] = a;
    }
    __syncthreads();
    if (t == 0) {
        float m = fmaxf(logit[0], fmaxf(logit[1], logit[2]));
        float e0 = expf(logit[0] - m), e1 = expf(logit[1] - m), e2 = expf(logit[2] - m);
        float s = e0 + e1 + e2;
        y[0] = e0 / s; y[1] = e1 / s; y[2] = e2 / s;
    }
}

// ---------------- host dispatch -----------------------------------------------
struct BArgs {
    const __nv_bfloat16 *Ah, *Al; long ldA;
    const __nv_bfloat16 *Bh, *Bl; long ldB;
    const __nv_bfloat16 *A2h = nullptr, *A2l = nullptr, *B2h = nullptr, *B2l = nullptr;
    const float* bias = nullptr;
    float* C = nullptr; long ldc = 0; long sliceStride = 0;
    __nv_bfloat16 *Chi = nullptr, *Clo = nullptr; long ldS = 0;
    __nv_bfloat16 *Th = nullptr, *Tl = nullptr; long ldT = 0;
    float *rowpart = nullptr, *colpart = nullptr;
    int reshapeRow = -1;
    int M, N, K, splits = 1, zTotal = 0, relu = 0;
};

static void launch_bgemm(const BArgs& a) {
    cudaFuncSetAttribute(bgemm, cudaFuncAttributeMaxDynamicSharedMemorySize, BGEMM_SMEM);
    int kps = (a.K + a.splits - 1) / a.splits;
    kps = ((kps + 31) / 32) * 32;
    int zt = a.zTotal ? a.zTotal : a.splits;
    dim3 grid((a.N + 127) / 128, a.M / 128, zt);
    bgemm<<<grid, 256, BGEMM_SMEM>>>(a.Ah, a.Al, a.ldA, a.Bh, a.Bl, a.ldB,
                                     a.A2h, a.A2l, a.B2h, a.B2l, a.splits,
                                     a.bias, a.C, a.ldc, a.sliceStride,
                                     a.Chi, a.Clo, a.ldS, a.Th, a.Tl, a.ldT,
                                     a.rowpart, a.colpart, a.reshapeRow,
                                     a.M, a.N, a.K, kps, a.relu);
}

#define GETSYM(var, sym) cudaGetSymbolAddress((void**)&var, sym)

extern "C" void kernel_launch(void* const* d_in, const int* in_sizes, int n_in,
                              void* d_out, int out_size) {
    const int*   p_idx = (const int*)  d_in[0];
    const int*   h_idx = (const int*)  d_in[1];
    const float* emb   = (const float*)d_in[2];
    const float* W_a1  = (const float*)d_in[3];
    const float* b_a1  = (const float*)d_in[4];
    const float* W_a2  = (const float*)d_in[5];
    const float* b_a2  = (const float*)d_in[6];
    const float* W_c1  = (const float*)d_in[7];
    const float* b_c1  = (const float*)d_in[8];
    const float* W_c2  = (const float*)d_in[9];
    const float* b_c2  = (const float*)d_in[10];
    const float* W_g1  = (const float*)d_in[11];
    const float* b_g1  = (const float*)d_in[12];
    const float* W_g2  = (const float*)d_in[13];
    const float* b_g2  = (const float*)d_in[14];
    const float* W_g3  = (const float*)d_in[15];
    const float* b_g3  = (const float*)d_in[16];

    float* out = (float*)d_out;
    const long E_OFF    = 0;
    const long BETA_OFF = (long)LPN * LHN;
    const long ALPHA_OFF= BETA_OFF + (long)LPN * DN;
    const long V1_OFF   = ALPHA_OFF + (long)LHN * DN;
    const long V2_OFF   = V1_OFF + HN;
    const long Y_OFF    = V2_OFF + HN;

    float *emb2, *eik, *ekj, *part, *part2, *split;
    GETSYM(emb2, g_emb2);
    GETSYM(eik, g_eik); GETSYM(ekj, g_ekj);
    GETSYM(part, g_part); GETSYM(part2, g_part2); GETSYM(split, g_split);

    __nv_bfloat16 *emb2s_h, *emb2s_l, *ths_h, *ths_l, *fps_h, *fps_l;
    __nv_bfloat16 *fhTs_h, *fhTs_l, *Es_h, *Es_l, *ETs_h, *ETs_l;
    __nv_bfloat16 *hTs_h, *hTs_l, *pTs_h, *pTs_l, *xs_h, *xs_l;
    __nv_bfloat16 *Wa1s_h, *Wa1s_l, *Wa2s_h, *Wa2s_l, *Wc1s_h, *Wc1s_l, *Wc2s_h, *Wc2s_l;
    GETSYM(emb2s_h, g_emb2s_h); GETSYM(emb2s_l, g_emb2s_l);
    GETSYM(ths_h, g_ths_h);     GETSYM(ths_l, g_ths_l);
    GETSYM(fps_h, g_fps_h);     GETSYM(fps_l, g_fps_l);
    GETSYM(fhTs_h, g_fhTs_h);   GETSYM(fhTs_l, g_fhTs_l);
    GETSYM(Es_h, g_Es_h);       GETSYM(Es_l, g_Es_l);
    GETSYM(ETs_h, g_ETs_h);     GETSYM(ETs_l, g_ETs_l);
    GETSYM(hTs_h, g_hTs_h);     GETSYM(hTs_l, g_hTs_l);
    GETSYM(pTs_h, g_pTs_h);     GETSYM(pTs_l, g_pTs_l);
    GETSYM(xs_h, g_xs_h);       GETSYM(xs_l, g_xs_l);
    GETSYM(Wa1s_h, g_Wa1s_h);   GETSYM(Wa1s_l, g_Wa1s_l);
    GETSYM(Wa2s_h, g_Wa2s_h);   GETSYM(Wa2s_l, g_Wa2s_l);
    GETSYM(Wc1s_h, g_Wc1s_h);   GETSYM(Wc1s_l, g_Wc1s_l);
    GETSYM(Wc2s_h, g_Wc2s_h);   GETSYM(Wc2s_l, g_Wc2s_l);

    // 0) all weight splits in one launch
    {
        long total = (long)HN * (DP + HN + D2P + HN);
        split_weights_kernel<<<(int)((total + 255) / 256), 256>>>(
            W_a1, W_a2, W_c1, W_c2,
            Wa1s_h, Wa1s_l, Wa2s_h, Wa2s_l, Wc1s_h, Wc1s_l, Wc2s_h, Wc2s_l);
    }

    // 1) fused gather + splits + xs fill
    gather_split_kernel<<<M2, 128>>>(emb, p_idx, h_idx, emb2,
                                     emb2s_h, emb2s_l, xs_h, xs_l);

    // 2) attend1 (batched p+h)
    {
        BArgs a{emb2s_h, emb2s_l, DP, Wa1s_h, Wa1s_l, DP};
        a.bias = b_a1; a.Chi = ths_h; a.Clo = ths_l; a.ldS = HN;
        a.M = M2; a.N = HN; a.K = DP; a.relu = 1;
        launch_bgemm(a);
    }
    // 3) attend2 with fused reshape-transpose: p-tiles -> fps, h-tiles -> fhTs
    {
        BArgs a{ths_h, ths_l, HN, Wa2s_h, Wa2s_l, HN};
        a.bias = b_a2;
        a.Chi = fps_h; a.Clo = fps_l; a.ldS = HN;
        a.Th = fhTs_h; a.Tl = fhTs_l; a.ldT = HN;
        a.reshapeRow = LPN;
        a.M = M2; a.N = HN; a.K = HN; a.relu = 1;
        launch_bgemm(a);
    }

    // 4) E GEMM with fused split + transposed split + row/col partials
    {
        BArgs a{fps_h, fps_l, HN, fhTs_h, fhTs_l, HN};
        a.C = out + E_OFF; a.ldc = LHN;
        a.Chi = Es_h; a.Clo = Es_l; a.ldS = LHN;
        a.Th = ETs_h; a.Tl = ETs_l; a.ldT = LHN;
        a.rowpart = part; a.colpart = part2;
        a.M = LPN; a.N = LHN; a.K = HN;
        launch_bgemm(a);
    }
    {
        dim3 g((LPN + 255) / 256, 2);
        colsum_reduce2_kernel<<<g, 256>>>(part, eik, part2, ekj, LPN, 32);
    }

    // 5) embedding transposes for beta/alpha B-operands (one launch)
    {
        dim3 b(32, 8);
        dim3 g((NROWS_PAD + 31) / 32, (LPN + 31) / 32, 2);
        transpose_split2_kernel<<<g, b>>>(emb2, pTs_h, pTs_l,
                                          emb2 + (long)LPN * DN, hTs_h, hTs_l,
                                          LPN, DN, NROWS_PAD);
    }

    // 6) beta & alpha in ONE launch, split-K x4 each
    {
        BArgs a{Es_h, Es_l, LHN, hTs_h, hTs_l, LHN};
        a.A2h = ETs_h; a.A2l = ETs_l; a.B2h = pTs_h; a.B2l = pTs_l;
        a.C = split; a.ldc = DN; a.sliceStride = (long)LPN * DN;
        a.M = LPN; a.N = DN; a.K = LHN; a.splits = 4; a.zTotal = 8;
        launch_bgemm(a);
    }
    {
        dim3 g((int)(((long)LPN * DN + 255) / 256), 2);
        splitk_concat2_kernel<<<g, 256>>>(split, eik, out + BETA_OFF,
                                          split + 4 * (long)LPN * DN, ekj, out + ALPHA_OFF,
                                          xs_h, xs_l, LPN, DN, 4);
    }

    // 7) comp (batched), colsums fused into comp2
    {
        BArgs a{xs_h, xs_l, D2P, Wc1s_h, Wc1s_l, D2P};
        a.bias = b_c1; a.Chi = ths_h; a.Clo = ths_l; a.ldS = HN;
        a.M = M2; a.N = HN; a.K = D2P; a.relu = 1;
        launch_bgemm(a);
    }
    {
        BArgs a{ths_h, ths_l, HN, Wc2s_h, Wc2s_l, HN};
        a.bias = b_c2; a.colpart = part;
        a.M = M2; a.N = HN; a.K = HN; a.relu = 1;
        launch_bgemm(a);
    }
    {
        dim3 g((HN + 255) / 256, 2);
        colsum_reduce2_kernel<<<g, 256>>>(part, out + V1_OFF, part + 32 * HN, out + V2_OFF, HN, 32);
    }

    // 8) head
    head_kernel<<<1, HN>>>(out + V1_OFF, W_g1, b_g1, W_g2, b_g2, W_g3, b_g3, out + Y_OFF);

    (void)in_sizes; (void)n_in; (void)out_size;
}

// round 10
// speedup vs baseline: 2.1846x; 1.0306x over previous
#include <cuda_runtime.h>
#include <cuda_bf16.h>
#include <cstdint>
#include <cmath>

#define LPN 4096
#define LHN 4096
#define DN  300
#define HN  512
#define DP  320          // DN padded to 32
#define D2P 608          // 2*DN padded to 32
#define NROWS_PAD 384    // DN padded for B-operand rows (>= 5*64)
#define M2  8192         // batched p+h rows

// ---------------- scratch (static device globals) ---------------------------
__device__ float g_emb2[M2 * DN];
__device__ float g_eik [LPN];
__device__ float g_ekj [LHN];
__device__ float g_part [64 * 4096];
__device__ float g_part2[64 * 4096];
__device__ float g_split[8 * LPN * DN];

__device__ __nv_bfloat16 g_emb2s_h[M2 * DP],  g_emb2s_l[M2 * DP];
__device__ __nv_bfloat16 g_ths_h [M2 * HN],   g_ths_l [M2 * HN];
__device__ __nv_bfloat16 g_fps_h [LPN * HN],  g_fps_l [LPN * HN];
__device__ __nv_bfloat16 g_fhTs_h[LHN * HN],  g_fhTs_l[LHN * HN];
__device__ __nv_bfloat16 g_Es_h [(long)LPN * LHN], g_Es_l [(long)LPN * LHN];
__device__ __nv_bfloat16 g_ETs_h[(long)LPN * LHN], g_ETs_l[(long)LPN * LHN];
__device__ __nv_bfloat16 g_hTs_h[NROWS_PAD * LHN], g_hTs_l[NROWS_PAD * LHN];
__device__ __nv_bfloat16 g_pTs_h[NROWS_PAD * LPN], g_pTs_l[NROWS_PAD * LPN];
__device__ __nv_bfloat16 g_xs_h [M2 * D2P],   g_xs_l [M2 * D2P];
__device__ __nv_bfloat16 g_Wa1s_h[HN * DP],   g_Wa1s_l[HN * DP];
__device__ __nv_bfloat16 g_Wa2s_h[HN * HN],   g_Wa2s_l[HN * HN];
__device__ __nv_bfloat16 g_Wc1s_h[HN * D2P],  g_Wc1s_l[HN * D2P];
__device__ __nv_bfloat16 g_Wc2s_h[HN * HN],   g_Wc2s_l[HN * HN];

// ---------------- PTX helpers ------------------------------------------------
__device__ __forceinline__ uint32_t smem_u32(const void* p) {
    uint32_t a;
    asm("{ .reg .u64 t; cvta.to.shared.u64 t, %1; cvt.u32.u64 %0, t; }" : "=r"(a) : "l"(p));
    return a;
}
__device__ __forceinline__ void ldsm4(uint32_t& r0, uint32_t& r1, uint32_t& r2,
                                      uint32_t& r3, uint32_t addr) {
    asm volatile("ldmatrix.sync.aligned.m8n8.x4.shared.b16 {%0,%1,%2,%3}, [%4];"
                 : "=r"(r0), "=r"(r1), "=r"(r2), "=r"(r3) : "r"(addr));
}
__device__ __forceinline__ void mma16816(float* c, const uint32_t* a,
                                         const uint32_t b0, const uint32_t b1) {
    asm volatile(
        "mma.sync.aligned.m16n8k16.row.col.f32.bf16.bf16.f32 "
        "{%0,%1,%2,%3}, {%4,%5,%6,%7}, {%8,%9}, {%0,%1,%2,%3};"
        : "+f"(c[0]), "+f"(c[1]), "+f"(c[2]), "+f"(c[3])
        : "r"(a[0]), "r"(a[1]), "r"(a[2]), "r"(a[3]), "r"(b0), "r"(b1));
}
__device__ __forceinline__ void cvt_split(float x, __nv_bfloat16& hi, __nv_bfloat16& lo) {
    hi = __float2bfloat16(x);
    lo = __float2bfloat16(x - __bfloat162float(hi));
}
__device__ __forceinline__ void cp16(uint32_t dst, const void* src) {
    asm volatile("cp.async.cg.shared.global [%0], [%1], 16;"
                 :: "r"(dst), "l"(__cvta_generic_to_global(src)));
}
__device__ __forceinline__ void cp_commit() {
    asm volatile("cp.async.commit_group;");
}
template <int NN> __device__ __forceinline__ void cp_wait() {
    asm volatile("cp.async.wait_group %0;" :: "n"(NN));
}

// ---------------- bf16x3 mma.sync SGEMM, 128x64 tile, 3 CTAs/SM --------------
// smem/stage: Ah 10240 | Al 10240 | Bh 5120 | Bl 5120 = 30720; 2 stages.
__global__ __launch_bounds__(256, 3)
void bgemm(const __nv_bfloat16* __restrict__ Agh, const __nv_bfloat16* __restrict__ Agl, long ldA,
           const __nv_bfloat16* __restrict__ Bgh, const __nv_bfloat16* __restrict__ Bgl, long ldB,
           const __nv_bfloat16* __restrict__ A2gh, const __nv_bfloat16* __restrict__ A2gl,
           const __nv_bfloat16* __restrict__ B2gh, const __nv_bfloat16* __restrict__ B2gl,
           int zSecond,
           const float* __restrict__ bias,
           float* __restrict__ C, long ldc, long sliceStride,
           __nv_bfloat16* __restrict__ Chi, __nv_bfloat16* __restrict__ Clo, long ldS,
           __nv_bfloat16* __restrict__ Th, __nv_bfloat16* __restrict__ Tl, long ldT,
           float* __restrict__ rowpart, float* __restrict__ colpart,
           int reshapeRow,
           int M, int N, int K, int kPerSlice, int relu) {
    extern __shared__ __align__(16) char smraw[];
    const int tid = threadIdx.x, lane = tid & 31, wid = tid >> 5;
    const int wm = wid >> 1, wn = wid & 1;          // 4 x 2 warps, warp tile 32x32
    const int m0 = blockIdx.y * 128, n0 = blockIdx.x * 64;
    const int zz = blockIdx.z;
    if (A2gh && zz >= zSecond) { Agh = A2gh; Agl = A2gl; Bgh = B2gh; Bgl = B2gl; }
    const int kbeg = (zz % zSecond) * kPerSlice;
    const int kend = min(K, kbeg + kPerSlice);
    const int nch = (kend - kbeg) >> 5;
    C += (long)zz * sliceStride;

    const uint32_t sb = smem_u32(smraw);

    float acc[2][4][4];
    #pragma unroll
    for (int i = 0; i < 2; i++)
        #pragma unroll
        for (int j = 0; j < 4; j++)
            #pragma unroll
            for (int e = 0; e < 4; e++) acc[i][j][e] = 0.f;

    const int lrow = (((lane >> 3) & 1) << 3) + (lane & 7);
    const int lcol = (lane >> 4) << 4;

    auto load_stage = [&](int st, int k0) {
        uint32_t sbase = sb + st * 30720;
        #pragma unroll
        for (int i = 0; i < 2; i++) {
            int c = tid + i * 256;          // 0..511 -> A rows
            int r = c >> 2, kq = c & 3;
            uint32_t dso = (uint32_t)(r * 80 + kq * 16);
            long ao = (long)(m0 + r) * ldA + k0 + kq * 8;
            cp16(sbase + dso,         Agh + ao);
            cp16(sbase + 10240 + dso, Agl + ao);
        }
        {
            int r = tid >> 2, kq = tid & 3; // 0..255 -> B rows (64)
            uint32_t dso = (uint32_t)(r * 80 + kq * 16);
            long bo = (long)(n0 + r) * ldB + k0 + kq * 8;
            cp16(sbase + 20480 + dso, Bgh + bo);
            cp16(sbase + 25600 + dso, Bgl + bo);
        }
    };

    load_stage(0, kbeg);
    cp_commit();

    for (int i = 0; i < nch; i++) {
        if (i + 1 < nch) {
            load_stage((i + 1) & 1, kbeg + (i + 1) * 32);
            cp_commit();
            cp_wait<1>();
        } else {
            cp_wait<0>();
        }
        __syncthreads();

        const uint32_t aAh = sb + (i & 1) * 30720;
        const uint32_t aAl = aAh + 10240;
        const uint32_t aBh = aAh + 20480;
        const uint32_t aBl = aAh + 25600;

        #pragma unroll
        for (int s = 0; s < 2; s++) {
            const int sbyte = s * 32;
            uint32_t ah[2][4], al[2][4], bh[2][4];
            #pragma unroll
            for (int mf = 0; mf < 2; mf++) {
                int row = wm * 32 + mf * 16 + lrow;
                ldsm4(ah[mf][0], ah[mf][1], ah[mf][2], ah[mf][3],
                      aAh + row * 80 + lcol + sbyte);
                ldsm4(al[mf][0], al[mf][1], al[mf][2], al[mf][3],
                      aAl + row * 80 + lcol + sbyte);
            }
            #pragma unroll
            for (int nf = 0; nf < 2; nf++) {
                int row = wn * 32 + nf * 16 + lrow;
                ldsm4(bh[nf][0], bh[nf][1], bh[nf][2], bh[nf][3],
                      aBh + row * 80 + lcol + sbyte);
            }
            #pragma unroll
            for (int nf = 0; nf < 2; nf++)
                #pragma unroll
                for (int j = 0; j < 2; j++)
                    #pragma unroll
                    for (int mf = 0; mf < 2; mf++)
                        mma16816(acc[mf][nf * 2 + j], ah[mf], bh[nf][j], bh[nf][j + 2]);
            #pragma unroll
            for (int nf = 0; nf < 2; nf++)
                #pragma unroll
                for (int j = 0; j < 2; j++)
                    #pragma unroll
                    for (int mf = 0; mf < 2; mf++)
                        mma16816(acc[mf][nf * 2 + j], al[mf], bh[nf][j], bh[nf][j + 2]);
            #pragma unroll
            for (int nf = 0; nf < 2; nf++) {
                int row = wn * 32 + nf * 16 + lrow;
                uint32_t bl[4];
                ldsm4(bl[0], bl[1], bl[2], bl[3], aBl + row * 80 + lcol + sbyte);
                #pragma unroll
                for (int j = 0; j < 2; j++)
                    #pragma unroll
                    for (int mf = 0; mf < 2; mf++)
                        mma16816(acc[mf][nf * 2 + j], ah[mf], bl[j], bl[j + 2]);
            }
        }
        __syncthreads();
    }

    // ---- epilogue: bias/relu in-place ----
    const int tg = lane >> 2;
    const int tn = (lane & 3) << 1;
    if (bias || relu) {
        #pragma unroll
        for (int mf = 0; mf < 2; mf++)
            #pragma unroll
            for (int nfj = 0; nfj < 4; nfj++) {
                int n = n0 + (wn * 32 + nfj * 8 + tn);
                #pragma unroll
                for (int h2 = 0; h2 < 2; h2++) {
                    float vx = acc[mf][nfj][h2 * 2 + 0];
                    float vy = acc[mf][nfj][h2 * 2 + 1];
                    if (bias && n < N) { vx += bias[n]; vy += bias[n + 1]; }
                    if (relu) { vx = fmaxf(vx, 0.f); vy = fmaxf(vy, 0.f); }
                    acc[mf][nfj][h2 * 2 + 0] = vx;
                    acc[mf][nfj][h2 * 2 + 1] = vy;
                }
            }
    }

    const bool rsh = (reshapeRow >= 0);
    const bool isH = rsh && (m0 >= reshapeRow);

    if (C || (Chi && !isH)) {
        #pragma unroll
        for (int mf = 0; mf < 2; mf++) {
            #pragma unroll
            for (int h2 = 0; h2 < 2; h2++) {
                int m = m0 + wm * 32 + mf * 16 + h2 * 8 + tg;
                #pragma unroll
                for (int nfj = 0; nfj < 4; nfj++) {
                    int n = n0 + wn * 32 + nfj * 8 + tn;
                    if (n >= N) continue;
                    float2 v;
                    v.x = acc[mf][nfj][h2 * 2 + 0];
                    v.y = acc[mf][nfj][h2 * 2 + 1];
                    if (C) *(float2*)(C + (long)m * ldc + n) = v;
                    if (Chi && !isH) {
                        __nv_bfloat16 h0, l0, h1, l1;
                        cvt_split(v.x, h0, l0);
                        cvt_split(v.y, h1, l1);
                        long o = (long)m * ldS + n;
                        Chi[o] = h0; Chi[o + 1] = h1;
                        Clo[o] = l0; Clo[o + 1] = l1;
                    }
                }
            }
        }
    }

    const bool doStage = (Th && (!rsh || isH)) || rowpart || colpart;
    if (doStage) {
        __syncthreads();
        float* ts = (float*)smraw;             // [64][129]
        #pragma unroll
        for (int mf = 0; mf < 2; mf++) {
            #pragma unroll
            for (int h2 = 0; h2 < 2; h2++) {
                int ml = wm * 32 + mf * 16 + h2 * 8 + tg;
                #pragma unroll
                for (int nfj = 0; nfj < 4; nfj++) {
                    int nl = wn * 32 + nfj * 8 + tn;
                    ts[(nl + 0) * 129 + ml] = acc[mf][nfj][h2 * 2 + 0];
                    ts[(nl + 1) * 129 + ml] = acc[mf][nfj][h2 * 2 + 1];
                }
            }
        }
        __syncthreads();
        if (tid < 128 && rowpart) {
            float s = 0.f;
            #pragma unroll 8
            for (int n = 0; n < 64; n++) s += ts[n * 129 + tid];
            rowpart[(long)blockIdx.x * M + m0 + tid] = s;
        }
        if (tid < 64 && colpart) {
            float s2 = 0.f;
            #pragma unroll 8
            for (int m = 0; m < 128; m++) s2 += ts[tid * 129 + m];
            colpart[(long)blockIdx.y * N + n0 + tid] = s2;
        }
        if (Th && (!rsh || isH)) {
            if (rsh) {
                // fused reshape([HN,LHN]) transpose: f[m][n] -> fhT[(mm%8)*HN+n][mm/8]
                long kb = (long)(m0 - reshapeRow) >> 3;
                for (int idx = tid; idx < 512; idx += 256) {
                    int r8 = idx >> 6, nl = idx & 63;
                    long j = (long)r8 * HN + n0 + nl;
                    __align__(16) __nv_bfloat16 hb[16], lb[16];
                    #pragma unroll
                    for (int q = 0; q < 16; q++) {
                        __nv_bfloat16 hi, lo;
                        cvt_split(ts[nl * 129 + r8 + 8 * q], hi, lo);
                        hb[q] = hi; lb[q] = lo;
                    }
                    long o = j * ldT + kb;
                    *(uint4*)(Th + o)     = *(uint4*)(hb);
                    *(uint4*)(Th + o + 8) = *(uint4*)(hb + 8);
                    *(uint4*)(Tl + o)     = *(uint4*)(lb);
                    *(uint4*)(Tl + o + 8) = *(uint4*)(lb + 8);
                }
            } else {
                for (int idx = tid; idx < 8192; idx += 256) {
                    int n = idx >> 7, m = idx & 127;
                    __nv_bfloat16 hi, lo;
                    cvt_split(ts[n * 129 + m], hi, lo);
                    long o = (long)(n0 + n) * ldT + m0 + m;
                    Th[o] = hi; Tl[o] = lo;
                }
            }
        }
    }
}

static const int BGEMM_SMEM = 2 * 30720;

// ---------------- all 4 weight splits in ONE kernel ---------------------------
__global__ void split_weights_kernel(const float* __restrict__ Wa1, const float* __restrict__ Wa2,
                                     const float* __restrict__ Wc1, const float* __restrict__ Wc2,
                                     __nv_bfloat16* __restrict__ a1h, __nv_bfloat16* __restrict__ a1l,
                                     __nv_bfloat16* __restrict__ a2h, __nv_bfloat16* __restrict__ a2l,
                                     __nv_bfloat16* __restrict__ c1h, __nv_bfloat16* __restrict__ c1l,
                                     __nv_bfloat16* __restrict__ c2h, __nv_bfloat16* __restrict__ c2l) {
    const long s1 = (long)HN * DP, s2 = (long)HN * HN, s3 = (long)HN * D2P, s4 = (long)HN * HN;
    long i = (long)blockIdx.x * blockDim.x + threadIdx.x;
    const float* src; __nv_bfloat16 *dh, *dl; int K, Kpad; long li;
    if (i < s1)                { src = Wa1; dh = a1h; dl = a1l; K = DN;     Kpad = DP;  li = i; }
    else if (i < s1 + s2)      { src = Wa2; dh = a2h; dl = a2l; K = HN;     Kpad = HN;  li = i - s1; }
    else if (i < s1 + s2 + s3) { src = Wc1; dh = c1h; dl = c1l; K = 2 * DN; Kpad = D2P; li = i - s1 - s2; }
    else if (i < s1 + s2 + s3 + s4) { src = Wc2; dh = c2h; dl = c2l; K = HN; Kpad = HN; li = i - s1 - s2 - s3; }
    else return;
    int m = (int)(li / Kpad), k = (int)(li % Kpad);
    float v = (k < K) ? src[(long)m * K + k] : 0.f;
    __nv_bfloat16 hi, lo;
    cvt_split(v, hi, lo);
    dh[li] = hi; dl[li] = lo;
}

// ---------------- fused gather + fp32 + split-pad + xs fill -------------------
__global__ void gather_split_kernel(const float* __restrict__ emb,
                                    const int* __restrict__ p_idx,
                                    const int* __restrict__ h_idx,
                                    float* __restrict__ emb2,
                                    __nv_bfloat16* __restrict__ e_h,
                                    __nv_bfloat16* __restrict__ e_l,
                                    __nv_bfloat16* __restrict__ x_h,
                                    __nv_bfloat16* __restrict__ x_l) {
    int r = blockIdx.x;
    long src = (r < LPN) ? p_idx[r] : h_idx[r - LPN];
    const float* s = emb + src * (long)DN;
    for (int c = threadIdx.x; c < DP; c += blockDim.x) {
        float v = (c < DN) ? s[c] : 0.f;
        __nv_bfloat16 hi, lo;
        cvt_split(v, hi, lo);
        long eo = (long)r * DP + c;
        e_h[eo] = hi; e_l[eo] = lo;
        if (c < DN) {
            emb2[(long)r * DN + c] = v;
            long xo = (long)r * D2P + c;
            x_h[xo] = hi; x_l[xo] = lo;
        }
    }
    for (int c = 2 * DN + threadIdx.x; c < D2P; c += blockDim.x) {
        long xo = (long)r * D2P + c;
        x_h[xo] = __float2bfloat16(0.f);
        x_l[xo] = __float2bfloat16(0.f);
    }
}

// ---------------- transpose + split (dual-source via blockIdx.z) --------------
__global__ void transpose_split2_kernel(const float* __restrict__ srcA,
                                        __nv_bfloat16* __restrict__ dhA, __nv_bfloat16* __restrict__ dlA,
                                        const float* __restrict__ srcB,
                                        __nv_bfloat16* __restrict__ dhB, __nv_bfloat16* __restrict__ dlB,
                                        int R, int C, int dR) {
    const float* src = blockIdx.z ? srcB : srcA;
    __nv_bfloat16* dh = blockIdx.z ? dhB : dhA;
    __nv_bfloat16* dl = blockIdx.z ? dlB : dlA;
    __shared__ float tile[32][33];
    int c0 = blockIdx.x * 32, r0 = blockIdx.y * 32;
    int x = threadIdx.x, y = threadIdx.y;
    #pragma unroll
    for (int i = y; i < 32; i += 8) {
        int r = r0 + i, c = c0 + x;
        tile[i][x] = (r < R && c < C) ? src[(long)r * C + c] : 0.f;
    }
    __syncthreads();
    #pragma unroll
    for (int i = y; i < 32; i += 8) {
        int dr = c0 + i, dc = r0 + x;
        if (dr < dR && dc < R) {
            __nv_bfloat16 hi, lo;
            cvt_split(tile[x][i], hi, lo);
            dh[(long)dr * R + dc] = hi;
            dl[(long)dr * R + dc] = lo;
        }
    }
}

// ---------------- split-K reduce + rowdiv + fused concat, dual via grid.y -----
__global__ void splitk_concat2_kernel(const float* __restrict__ partA, const float* __restrict__ rdA,
                                      float* __restrict__ CA,
                                      const float* __restrict__ partB, const float* __restrict__ rdB,
                                      float* __restrict__ CB,
                                      __nv_bfloat16* __restrict__ xh, __nv_bfloat16* __restrict__ xl,
                                      int M, int N, int S) {
    const float* part = blockIdx.y ? partB : partA;
    const float* rowdiv = blockIdx.y ? rdB : rdA;
    float* C = blockIdx.y ? CB : CA;
    long xRowOff = blockIdx.y ? (long)M : 0;
    long i = (long)blockIdx.x * blockDim.x + threadIdx.x;
    long total = (long)M * N;
    if (i >= total) return;
    int m = (int)(i / N), n = (int)(i % N);
    float s = 0.f;
    for (int p = 0; p < S; p++) s += part[(long)p * total + i];
    float v = s / rowdiv[m];
    C[(long)m * N + n] = v;
    __nv_bfloat16 hi, lo;
    cvt_split(v, hi, lo);
    long o = (xRowOff + m) * (long)D2P + DN + n;
    xh[o] = hi; xl[o] = lo;
}

// ---------------- dual column reduce (independent P per source) ---------------
__global__ void colsum_reduce2_kernel(const float* __restrict__ partA, float* __restrict__ outA, int PA,
                                      const float* __restrict__ partB, float* __restrict__ outB, int PB,
                                      int C) {
    const float* part = blockIdx.y ? partB : partA;
    float* out = blockIdx.y ? outB : outA;
    int P = blockIdx.y ? PB : PA;
    int c = blockIdx.x * blockDim.x + threadIdx.x;
    if (c >= C) return;
    float s = 0.f;
    for (int p = 0; p < P; p++) s += part[(long)p * C + c];
    out[c] = s;
}

// ---------------- final MLP head + softmax -------------------------------------
__global__ void head_kernel(const float* __restrict__ v,
                            const float* __restrict__ Wg1, const float* __restrict__ bg1,
                            const float* __restrict__ Wg2, const float* __restrict__ bg2,
                            const float* __restrict__ Wg3, const float* __restrict__ bg3,
                            float* __restrict__ y) {
    __shared__ float sv[2 * HN];
    __shared__ float y1[HN];
    __shared__ float y2[HN];
    __shared__ float logit[3];
    int t = threadIdx.x;
    sv[t] = v[t];
    sv[t + HN] = v[t + HN];
    __syncthreads();
    {
        float acc = bg1[t];
        const float* w = Wg1 + (long)t * (2 * HN);
        for (int k = 0; k < 2 * HN; k++) acc += sv[k] * w[k];
        y1[t] = fmaxf(acc, 0.f);
    }
    __syncthreads();
    {
        float acc = bg2[t];
        const float* w = Wg2 + (long)t * HN;
        for (int k = 0; k < HN; k++) acc += y1[k] * w[k];
        y2[t] = fmaxf(acc, 0.f);
    }
    __syncthreads();
    if (t < 3) {
        float a = bg3[t];
        const float* w = Wg3 + (long)t * HN;
        for (int k = 0; k < HN; k++) a += y2[k] * w[k];
        logit[t] = a;
    }
    __syncthreads();
    if (t == 0) {
        float m = fmaxf(logit[0], fmaxf(logit[1], logit[2]));
        float e0 = expf(logit[0] - m), e1 = expf(logit[1] - m), e2 = expf(logit[2] - m);
        float s = e0 + e1 + e2;
        y[0] = e0 / s; y[1] = e1 / s; y[2] = e2 / s;
    }
}

// ---------------- host dispatch -----------------------------------------------
struct BArgs {
    const __nv_bfloat16 *Ah, *Al; long ldA;
    const __nv_bfloat16 *Bh, *Bl; long ldB;
    const __nv_bfloat16 *A2h = nullptr, *A2l = nullptr, *B2h = nullptr, *B2l = nullptr;
    const float* bias = nullptr;
    float* C = nullptr; long ldc = 0; long sliceStride = 0;
    __nv_bfloat16 *Chi = nullptr, *Clo = nullptr; long ldS = 0;
    __nv_bfloat16 *Th = nullptr, *Tl = nullptr; long ldT = 0;
    float *rowpart = nullptr, *colpart = nullptr;
    int reshapeRow = -1;
    int M, N, K, splits = 1, zTotal = 0, relu = 0;
};

static void launch_bgemm(const BArgs& a) {
    cudaFuncSetAttribute(bgemm, cudaFuncAttributeMaxDynamicSharedMemorySize, BGEMM_SMEM);
    int kps = (a.K + a.splits - 1) / a.splits;
    kps = ((kps + 31) / 32) * 32;
    int zt = a.zTotal ? a.zTotal : a.splits;
    dim3 grid((a.N + 63) / 64, a.M / 128, zt);
    bgemm<<<grid, 256, BGEMM_SMEM>>>(a.Ah, a.Al, a.ldA, a.Bh, a.Bl, a.ldB,
                                     a.A2h, a.A2l, a.B2h, a.B2l, a.splits,
                                     a.bias, a.C, a.ldc, a.sliceStride,
                                     a.Chi, a.Clo, a.ldS, a.Th, a.Tl, a.ldT,
                                     a.rowpart, a.colpart, a.reshapeRow,
                                     a.M, a.N, a.K, kps, a.relu);
}

#define GETSYM(var, sym) cudaGetSymbolAddress((void**)&var, sym)

extern "C" void kernel_launch(void* const* d_in, const int* in_sizes, int n_in,
                              void* d_out, int out_size) {
    const int*   p_idx = (const int*)  d_in[0];
    const int*   h_idx = (const int*)  d_in[1];
    const float* emb   = (const float*)d_in[2];
    const float* W_a1  = (const float*)d_in[3];
    const float* b_a1  = (const float*)d_in[4];
    const float* W_a2  = (const float*)d_in[5];
    const float* b_a2  = (const float*)d_in[6];
    const float* W_c1  = (const float*)d_in[7];
    const float* b_c1  = (const float*)d_in[8];
    const float* W_c2  = (const float*)d_in[9];
    const float* b_c2  = (const float*)d_in[10];
    const float* W_g1  = (const float*)d_in[11];
    const float* b_g1  = (const float*)d_in[12];
    const float* W_g2  = (const float*)d_in[13];
    const float* b_g2  = (const float*)d_in[14];
    const float* W_g3  = (const float*)d_in[15];
    const float* b_g3  = (const float*)d_in[16];

    float* out = (float*)d_out;
    const long E_OFF    = 0;
    const long BETA_OFF = (long)LPN * LHN;
    const long ALPHA_OFF= BETA_OFF + (long)LPN * DN;
    const long V1_OFF   = ALPHA_OFF + (long)LHN * DN;
    const long V2_OFF   = V1_OFF + HN;
    const long Y_OFF    = V2_OFF + HN;

    float *emb2, *eik, *ekj, *part, *part2, *split;
    GETSYM(emb2, g_emb2);
    GETSYM(eik, g_eik); GETSYM(ekj, g_ekj);
    GETSYM(part, g_part); GETSYM(part2, g_part2); GETSYM(split, g_split);

    __nv_bfloat16 *emb2s_h, *emb2s_l, *ths_h, *ths_l, *fps_h, *fps_l;
    __nv_bfloat16 *fhTs_h, *fhTs_l, *Es_h, *Es_l, *ETs_h, *ETs_l;
    __nv_bfloat16 *hTs_h, *hTs_l, *pTs_h, *pTs_l, *xs_h, *xs_l;
    __nv_bfloat16 *Wa1s_h, *Wa1s_l, *Wa2s_h, *Wa2s_l, *Wc1s_h, *Wc1s_l, *Wc2s_h, *Wc2s_l;
    GETSYM(emb2s_h, g_emb2s_h); GETSYM(emb2s_l, g_emb2s_l);
    GETSYM(ths_h, g_ths_h);     GETSYM(ths_l, g_ths_l);
    GETSYM(fps_h, g_fps_h);     GETSYM(fps_l, g_fps_l);
    GETSYM(fhTs_h, g_fhTs_h);   GETSYM(fhTs_l, g_fhTs_l);
    GETSYM(Es_h, g_Es_h);       GETSYM(Es_l, g_Es_l);
    GETSYM(ETs_h, g_ETs_h);     GETSYM(ETs_l, g_ETs_l);
    GETSYM(hTs_h, g_hTs_h);     GETSYM(hTs_l, g_hTs_l);
    GETSYM(pTs_h, g_pTs_h);     GETSYM(pTs_l, g_pTs_l);
    GETSYM(xs_h, g_xs_h);       GETSYM(xs_l, g_xs_l);
    GETSYM(Wa1s_h, g_Wa1s_h);   GETSYM(Wa1s_l, g_Wa1s_l);
    GETSYM(Wa2s_h, g_Wa2s_h);   GETSYM(Wa2s_l, g_Wa2s_l);
    GETSYM(Wc1s_h, g_Wc1s_h);   GETSYM(Wc1s_l, g_Wc1s_l);
    GETSYM(Wc2s_h, g_Wc2s_h);   GETSYM(Wc2s_l, g_Wc2s_l);

    // 0) all weight splits
    {
        long total = (long)HN * (DP + HN + D2P + HN);
        split_weights_kernel<<<(int)((total + 255) / 256), 256>>>(
            W_a1, W_a2, W_c1, W_c2,
            Wa1s_h, Wa1s_l, Wa2s_h, Wa2s_l, Wc1s_h, Wc1s_l, Wc2s_h, Wc2s_l);
    }

    // 1) fused gather + splits + xs fill
    gather_split_kernel<<<M2, 128>>>(emb, p_idx, h_idx, emb2,
                                     emb2s_h, emb2s_l, xs_h, xs_l);

    // 2) attend1 (batched p+h)
    {
        BArgs a{emb2s_h, emb2s_l, DP, Wa1s_h, Wa1s_l, DP};
        a.bias = b_a1; a.Chi = ths_h; a.Clo = ths_l; a.ldS = HN;
        a.M = M2; a.N = HN; a.K = DP; a.relu = 1;
        launch_bgemm(a);
    }
    // 3) attend2 with fused reshape-transpose
    {
        BArgs a{ths_h, ths_l, HN, Wa2s_h, Wa2s_l, HN};
        a.bias = b_a2;
        a.Chi = fps_h; a.Clo = fps_l; a.ldS = HN;
        a.Th = fhTs_h; a.Tl = fhTs_l; a.ldT = HN;
        a.reshapeRow = LPN;
        a.M = M2; a.N = HN; a.K = HN; a.relu = 1;
        launch_bgemm(a);
    }

    // 4) E GEMM with fused split + transposed split + row/col partials
    {
        BArgs a{fps_h, fps_l, HN, fhTs_h, fhTs_l, HN};
        a.C = out + E_OFF; a.ldc = LHN;
        a.Chi = Es_h; a.Clo = Es_l; a.ldS = LHN;
        a.Th = ETs_h; a.Tl = ETs_l; a.ldT = LHN;
        a.rowpart = part; a.colpart = part2;
        a.M = LPN; a.N = LHN; a.K = HN;
        launch_bgemm(a);
    }
    {
        dim3 g((LPN + 255) / 256, 2);
        colsum_reduce2_kernel<<<g, 256>>>(part, eik, 64, part2, ekj, 32, LPN);
    }

    // 5) embedding transposes for beta/alpha B-operands
    {
        dim3 b(32, 8);
        dim3 g((NROWS_PAD + 31) / 32, (LPN + 31) / 32, 2);
        transpose_split2_kernel<<<g, b>>>(emb2, pTs_h, pTs_l,
                                          emb2 + (long)LPN * DN, hTs_h, hTs_l,
                                          LPN, DN, NROWS_PAD);
    }

    // 6) beta & alpha in ONE launch, split-K x4 each
    {
        BArgs a{Es_h, Es_l, LHN, hTs_h, hTs_l, LHN};
        a.A2h = ETs_h; a.A2l = ETs_l; a.B2h = pTs_h; a.B2l = pTs_l;
        a.C = split; a.ldc = DN; a.sliceStride = (long)LPN * DN;
        a.M = LPN; a.N = DN; a.K = LHN; a.splits = 4; a.zTotal = 8;
        launch_bgemm(a);
    }
    {
        dim3 g((int)(((long)LPN * DN + 255) / 256), 2);
        splitk_concat2_kernel<<<g, 256>>>(split, eik, out + BETA_OFF,
                                          split + 4 * (long)LPN * DN, ekj, out + ALPHA_OFF,
                                          xs_h, xs_l, LPN, DN, 4);
    }

    // 7) comp (batched), colsums fused into comp2
    {
        BArgs a{xs_h, xs_l, D2P, Wc1s_h, Wc1s_l, D2P};
        a.bias = b_c1; a.Chi = ths_h; a.Clo = ths_l; a.ldS = HN;
        a.M = M2; a.N = HN; a.K = D2P; a.relu = 1;
        launch_bgemm(a);
    }
    {
        BArgs a{ths_h, ths_l, HN, Wc2s_h, Wc2s_l, HN};
        a.bias = b_c2; a.colpart = part;
        a.M = M2; a.N = HN; a.K = HN; a.relu = 1;
        launch_bgemm(a);
    }
    {
        dim3 g((HN + 255) / 256, 2);
        colsum_reduce2_kernel<<<g, 256>>>(part, out + V1_OFF, 32,
                                          part + 32 * HN, out + V2_OFF, 32, HN);
    }

    // 8) head
    head_kernel<<<1, HN>>>(out + V1_OFF, W_g1, b_g1, W_g2, b_g2, W_g3, b_g3, out + Y_OFF);

    (void)in_sizes; (void)n_in; (void)out_size;
}